// round 11
// baseline (speedup 1.0000x reference)
#include <cuda_runtime.h>
#include <math.h>

#define SEQ   2048
#define DIMM  1024
#define QKVW  1280
#define NEGF  (-3.402823466e38f)

// ---------------- scratch (static device globals) ----------------
__device__ __align__(16) float g_xn  [SEQ*DIMM];
__device__ __align__(16) float g_qkv [SEQ*QKVW];
__device__ __align__(16) float g_rq  [SEQ*DIMM];
__device__ __align__(16) float g_rk  [SEQ*128];
__device__ __align__(16) float g_cin [2*64*4096];
__device__ __align__(16) float g_hidp[4*2*64*4096];
__device__ __align__(16) float g_hid [2*64*4096];
__device__ __align__(16) float g_ck  [2*33*64];
__device__ __align__(16) float g_cv  [2*33*64];
__device__ __align__(16) float g_cout[SEQ*DIMM];
__device__ __align__(16) float g_fout[SEQ*DIMM];
__device__ __align__(16) float g_sout[SEQ*DIMM];
__device__ __align__(16) float g_gate[SEQ*48];
__device__ __align__(16) float g_comb[SEQ*DIMM];
__device__            int   g_sel [2*SEQ*9];

__device__ __forceinline__ float wmax(float v){
    #pragma unroll
    for (int o=16;o;o>>=1) v = fmaxf(v, __shfl_xor_sync(0xffffffffu, v, o));
    return v;
}
__device__ __forceinline__ float wsum(float v){
    #pragma unroll
    for (int o=16;o;o>>=1) v += __shfl_xor_sync(0xffffffffu, v, o);
    return v;
}

// ---------------- cp.async helpers ----------------
__device__ __forceinline__ void cp16(unsigned dst, const void* src){
    asm volatile("cp.async.cg.shared.global [%0], [%1], 16;" :: "r"(dst), "l"(src));
}
__device__ __forceinline__ void cp_commit(){ asm volatile("cp.async.commit_group;"); }
template<int N> __device__ __forceinline__ void cp_wait(){
    asm volatile("cp.async.wait_group %0;" :: "n"(N));
}

// ---------------- tf32 helpers ----------------
__device__ __forceinline__ void tf32_split(float f, unsigned& hi, unsigned& lo){
    asm("cvt.rna.tf32.f32 %0, %1;" : "=r"(hi) : "f"(f));
    float rem = f - __uint_as_float(hi);
    asm("cvt.rna.tf32.f32 %0, %1;" : "=r"(lo) : "f"(rem));
}
__device__ __forceinline__ void mma_tf32(float* c, const unsigned* a, const unsigned* b){
    asm volatile(
        "mma.sync.aligned.m16n8k8.row.col.f32.tf32.tf32.f32 "
        "{%0,%1,%2,%3},{%4,%5,%6,%7},{%8,%9},{%0,%1,%2,%3};"
        : "+f"(c[0]), "+f"(c[1]), "+f"(c[2]), "+f"(c[3])
        : "r"(a[0]), "r"(a[1]), "r"(a[2]), "r"(a[3]), "r"(b[0]), "r"(b[1]));
}
__device__ __forceinline__ void ldsm4(unsigned* r, unsigned addr){
    asm volatile("ldmatrix.sync.aligned.m8n8.x4.shared.b16 {%0,%1,%2,%3}, [%4];"
        : "=r"(r[0]), "=r"(r[1]), "=r"(r[2]), "=r"(r[3]) : "r"(addr));
}

// ---------------- RMSNorm ----------------
__global__ void rmsnorm_kernel(const float* __restrict__ x, const float* __restrict__ g){
    int s = blockIdx.x, tid = threadIdx.x;
    const float* xr = x + (size_t)s*DIMM;
    __shared__ float red[256];
    float ss = 0.f;
    for (int i = tid; i < DIMM; i += 256){ float v = xr[i]; ss += v*v; }
    red[tid] = ss; __syncthreads();
    for (int st = 128; st > 0; st >>= 1){ if (tid < st) red[tid] += red[tid+st]; __syncthreads(); }
    float sc = rsqrtf(red[0]*(1.f/DIMM) + 1.1920929e-7f);
    for (int i = tid; i < DIMM; i += 256) g_xn[(size_t)s*DIMM+i] = xr[i]*sc*g[i];
}

// ---------------- tf32x3 GEMM, double-buffered: BM=128,BN=128,BK=16 ----------------
#define GSTG 9344
__global__ __launch_bounds__(256,2) void tf32gemm_kernel(
        const float* __restrict__ A, const float* __restrict__ B,
        float* __restrict__ C, int M, int N, int K){
    extern __shared__ unsigned dsm[];
    int tid = threadIdx.x, lane = tid&31, wid = tid>>5;
    int m0b = blockIdx.y*128, n0b = blockIdx.x*128;
    int mw = (wid>>2)*64, nw = (wid&3)*32;
    int r = lane>>2, c = lane&3;
    float acc[4][4][4] = {};
    int la_m = tid>>2, la_k = (tid&3)*4;
    int lb_r = tid>>5, lb_n = (tid&31)*4;
    int sub = lane>>3, e = lane&7;
    int a_row = mw + ((sub&1)<<3) + e;
    int a_col = (sub>>1)<<2;
    unsigned sm_base = (unsigned)__cvta_generic_to_shared(dsm);

    float4 pa0 = *(const float4*)(A + (size_t)(m0b+la_m)*K + la_k);
    float4 pa1 = *(const float4*)(A + (size_t)(m0b+la_m+64)*K + la_k);
    float4 pb0 = *(const float4*)(B + (size_t)lb_r*N + n0b + lb_n);
    float4 pb1 = *(const float4*)(B + (size_t)(lb_r+8)*N + n0b + lb_n);

    {
        unsigned* Ah = dsm; unsigned* Al = dsm + 2560; unsigned* Bhl = dsm + 5120;
        float fa0[4]={pa0.x,pa0.y,pa0.z,pa0.w}, fa1[4]={pa1.x,pa1.y,pa1.z,pa1.w};
        #pragma unroll
        for (int u = 0; u < 4; u++){
            unsigned hi, lo;
            tf32_split(fa0[u], hi, lo); Ah[la_m*20 + la_k+u] = hi;      Al[la_m*20 + la_k+u] = lo;
            tf32_split(fa1[u], hi, lo); Ah[(la_m+64)*20 + la_k+u] = hi; Al[(la_m+64)*20 + la_k+u] = lo;
        }
        unsigned h0,l0,h1,l1,h2,l2,h3,l3;
        tf32_split(pb0.x,h0,l0); tf32_split(pb0.y,h1,l1);
        tf32_split(pb0.z,h2,l2); tf32_split(pb0.w,h3,l3);
        *(uint4*)&Bhl[lb_r*264 + lb_n*2]     = make_uint4(h0,l0,h1,l1);
        *(uint4*)&Bhl[lb_r*264 + lb_n*2 + 4] = make_uint4(h2,l2,h3,l3);
        tf32_split(pb1.x,h0,l0); tf32_split(pb1.y,h1,l1);
        tf32_split(pb1.z,h2,l2); tf32_split(pb1.w,h3,l3);
        *(uint4*)&Bhl[(lb_r+8)*264 + lb_n*2]     = make_uint4(h0,l0,h1,l1);
        *(uint4*)&Bhl[(lb_r+8)*264 + lb_n*2 + 4] = make_uint4(h2,l2,h3,l3);
    }
    if (16 < K){
        pa0 = *(const float4*)(A + (size_t)(m0b+la_m)*K + 16 + la_k);
        pa1 = *(const float4*)(A + (size_t)(m0b+la_m+64)*K + 16 + la_k);
        pb0 = *(const float4*)(B + (size_t)(16+lb_r)*N + n0b + lb_n);
        pb1 = *(const float4*)(B + (size_t)(16+lb_r+8)*N + n0b + lb_n);
    }
    __syncthreads();

    int cur = 0;
    for (int k0 = 0; k0 < K; k0 += 16){
        {
            unsigned stg = cur*GSTG;
            unsigned* Bhl = dsm + stg + 5120;
            #pragma unroll
            for (int ks = 0; ks < 2; ks++){
                int kk = ks*8;
                unsigned ah[4][4], al[4][4];
                #pragma unroll
                for (int t = 0; t < 4; t++){
                    unsigned offh = sm_base + (stg + (a_row + t*16)*20 + kk + a_col)*4u;
                    ldsm4(ah[t], offh);
                    ldsm4(al[t], offh + 2560*4u);
                }
                #pragma unroll
                for (int j = 0; j < 4; j++){
                    int nc = nw + j*8 + r;
                    uint2 b0 = *(const uint2*)&Bhl[(kk+c)*264 + nc*2];
                    uint2 b1 = *(const uint2*)&Bhl[(kk+c+4)*264 + nc*2];
                    unsigned bh[2] = { b0.x, b1.x };
                    unsigned bl[2] = { b0.y, b1.y };
                    #pragma unroll
                    for (int t = 0; t < 4; t++){
                        mma_tf32(acc[t][j], ah[t], bh);
                        mma_tf32(acc[t][j], ah[t], bl);
                        mma_tf32(acc[t][j], al[t], bh);
                    }
                }
            }
        }
        if (k0 + 16 < K){
            unsigned nstg = (cur^1)*GSTG;
            unsigned* Ah = dsm + nstg; unsigned* Al = dsm + nstg + 2560; unsigned* Bhl = dsm + nstg + 5120;
            float fa0[4]={pa0.x,pa0.y,pa0.z,pa0.w}, fa1[4]={pa1.x,pa1.y,pa1.z,pa1.w};
            #pragma unroll
            for (int u = 0; u < 4; u++){
                unsigned hi, lo;
                tf32_split(fa0[u], hi, lo); Ah[la_m*20 + la_k+u] = hi;      Al[la_m*20 + la_k+u] = lo;
                tf32_split(fa1[u], hi, lo); Ah[(la_m+64)*20 + la_k+u] = hi; Al[(la_m+64)*20 + la_k+u] = lo;
            }
            unsigned h0,l0,h1,l1,h2,l2,h3,l3;
            tf32_split(pb0.x,h0,l0); tf32_split(pb0.y,h1,l1);
            tf32_split(pb0.z,h2,l2); tf32_split(pb0.w,h3,l3);
            *(uint4*)&Bhl[lb_r*264 + lb_n*2]     = make_uint4(h0,l0,h1,l1);
            *(uint4*)&Bhl[lb_r*264 + lb_n*2 + 4] = make_uint4(h2,l2,h3,l3);
            tf32_split(pb1.x,h0,l0); tf32_split(pb1.y,h1,l1);
            tf32_split(pb1.z,h2,l2); tf32_split(pb1.w,h3,l3);
            *(uint4*)&Bhl[(lb_r+8)*264 + lb_n*2]     = make_uint4(h0,l0,h1,l1);
            *(uint4*)&Bhl[(lb_r+8)*264 + lb_n*2 + 4] = make_uint4(h2,l2,h3,l3);
        }
        if (k0 + 32 < K){
            pa0 = *(const float4*)(A + (size_t)(m0b+la_m)*K + k0+32 + la_k);
            pa1 = *(const float4*)(A + (size_t)(m0b+la_m+64)*K + k0+32 + la_k);
            pb0 = *(const float4*)(B + (size_t)(k0+32+lb_r)*N + n0b + lb_n);
            pb1 = *(const float4*)(B + (size_t)(k0+32+lb_r+8)*N + n0b + lb_n);
        }
        __syncthreads();
        cur ^= 1;
    }
    #pragma unroll
    for (int t = 0; t < 4; t++)
        #pragma unroll
        for (int j = 0; j < 4; j++){
            int row = m0b + mw + t*16 + r;
            int col = n0b + nw + j*8 + c*2;
            C[(size_t)row*N + col]       = acc[t][j][0];
            C[(size_t)row*N + col+1]     = acc[t][j][1];
            C[(size_t)(row+8)*N + col]   = acc[t][j][2];
            C[(size_t)(row+8)*N + col+1] = acc[t][j][3];
        }
}

// ---------------- MLP1 tf32x3 split-K, double-buffered: BM=64,BN=128 ----------------
#define MSTG 6784
__global__ __launch_bounds__(256,2) void mlp1_tf32_kernel(
        const float* __restrict__ kW1, const float* __restrict__ vW1){
    extern __shared__ unsigned dsm[];
    int tid = threadIdx.x, lane = tid&31, wid = tid>>5;
    int mat = blockIdx.y, kc = blockIdx.z;
    const float* A = g_cin + (size_t)mat*262144;
    const float* B = (mat ? vW1 : kW1);
    int n0b = blockIdx.x*128, kbase = kc*1024;
    int mw = (wid>>2)*32, nw = (wid&3)*32;
    int r = lane>>2, c = lane&3;
    float acc[2][4][4] = {};
    int fa_k = tid&15, fa_m = tid>>4;
    int fb_n = tid&127, fb_r = tid>>7;
    int sub = lane>>3, e = lane&7;
    int a_row = mw + ((sub&1)<<3) + e;
    int a_col = (sub>>1)<<2;
    unsigned sm_base = (unsigned)__cvta_generic_to_shared(dsm);

    float pa[4], pb[8];
    #pragma unroll
    for (int p = 0; p < 4; p++)
        pa[p] = A[(size_t)(fa_m + 16*p)*4096 + kbase + fa_k];
    #pragma unroll
    for (int p = 0; p < 8; p++)
        pb[p] = B[(size_t)(kbase + fb_r + 2*p)*4096 + n0b + fb_n];

    {
        unsigned* Ah = dsm; unsigned* Al = dsm + 1280; unsigned* Bhl = dsm + 2560;
        #pragma unroll
        for (int p = 0; p < 4; p++){
            unsigned hi, lo;
            tf32_split(pa[p], hi, lo);
            Ah[(fa_m + 16*p)*20 + fa_k] = hi;
            Al[(fa_m + 16*p)*20 + fa_k] = lo;
        }
        #pragma unroll
        for (int p = 0; p < 8; p++){
            unsigned hi, lo;
            tf32_split(pb[p], hi, lo);
            *(uint2*)&Bhl[(fb_r + 2*p)*264 + fb_n*2] = make_uint2(hi, lo);
        }
    }
    {
        #pragma unroll
        for (int p = 0; p < 4; p++)
            pa[p] = A[(size_t)(fa_m + 16*p)*4096 + kbase + 16 + fa_k];
        #pragma unroll
        for (int p = 0; p < 8; p++)
            pb[p] = B[(size_t)(kbase + 16 + fb_r + 2*p)*4096 + n0b + fb_n];
    }
    __syncthreads();

    int cur = 0;
    for (int k0 = 0; k0 < 1024; k0 += 16){
        {
            unsigned stg = cur*MSTG;
            unsigned* Bhl = dsm + stg + 2560;
            #pragma unroll
            for (int ks = 0; ks < 2; ks++){
                int kk = ks*8;
                unsigned ah[2][4], al[2][4];
                #pragma unroll
                for (int t = 0; t < 2; t++){
                    unsigned offh = sm_base + (stg + (a_row + t*16)*20 + kk + a_col)*4u;
                    ldsm4(ah[t], offh);
                    ldsm4(al[t], offh + 1280*4u);
                }
                #pragma unroll
                for (int j = 0; j < 4; j++){
                    int nc = nw + j*8 + r;
                    uint2 b0 = *(const uint2*)&Bhl[(kk+c)*264 + nc*2];
                    uint2 b1 = *(const uint2*)&Bhl[(kk+c+4)*264 + nc*2];
                    unsigned bh[2] = { b0.x, b1.x };
                    unsigned bl[2] = { b0.y, b1.y };
                    #pragma unroll
                    for (int t = 0; t < 2; t++){
                        mma_tf32(acc[t][j], ah[t], bh);
                        mma_tf32(acc[t][j], ah[t], bl);
                        mma_tf32(acc[t][j], al[t], bh);
                    }
                }
            }
        }
        if (k0 + 16 < 1024){
            unsigned nstg = (cur^1)*MSTG;
            unsigned* Ah = dsm + nstg; unsigned* Al = dsm + nstg + 1280; unsigned* Bhl = dsm + nstg + 2560;
            #pragma unroll
            for (int p = 0; p < 4; p++){
                unsigned hi, lo;
                tf32_split(pa[p], hi, lo);
                Ah[(fa_m + 16*p)*20 + fa_k] = hi;
                Al[(fa_m + 16*p)*20 + fa_k] = lo;
            }
            #pragma unroll
            for (int p = 0; p < 8; p++){
                unsigned hi, lo;
                tf32_split(pb[p], hi, lo);
                *(uint2*)&Bhl[(fb_r + 2*p)*264 + fb_n*2] = make_uint2(hi, lo);
            }
        }
        if (k0 + 32 < 1024){
            #pragma unroll
            for (int p = 0; p < 4; p++)
                pa[p] = A[(size_t)(fa_m + 16*p)*4096 + kbase + k0 + 32 + fa_k];
            #pragma unroll
            for (int p = 0; p < 8; p++)
                pb[p] = B[(size_t)(kbase + k0 + 32 + fb_r + 2*p)*4096 + n0b + fb_n];
        }
        __syncthreads();
        cur ^= 1;
    }
    float* O = g_hidp + (size_t)(kc*2+mat)*64*4096;
    #pragma unroll
    for (int t = 0; t < 2; t++)
        #pragma unroll
        for (int j = 0; j < 4; j++){
            int row = mw + t*16 + r;
            int col = n0b + nw + j*8 + c*2;
            O[(size_t)row*4096 + col]       = acc[t][j][0];
            O[(size_t)row*4096 + col+1]     = acc[t][j][1];
            O[(size_t)(row+8)*4096 + col]   = acc[t][j][2];
            O[(size_t)(row+8)*4096 + col+1] = acc[t][j][3];
        }
}

// ---------------- small SGEMM (gates) ----------------
__global__ void sgemm_kernel(const float* __restrict__ A, const float* __restrict__ B,
                             const float* __restrict__ bias, float* __restrict__ C,
                             int M, int N, int K, int epi){
    __shared__ __align__(16) float As[16][72];
    __shared__ __align__(16) float Bs[16][72];
    int tid = threadIdx.x;
    int tr = tid>>4, tc = tid&15;
    int m0 = blockIdx.y*64, n0 = blockIdx.x*64;
    int lm = tid>>2, lk4 = (tid&3)*4;
    int lkb = tid>>4, ln4 = (tid&15)*4;
    float acc[4][4] = {};
    for (int k0 = 0; k0 < K; k0 += 16){
        float4 a4 = *(const float4*)(A + (size_t)(m0+lm)*K + k0 + lk4);
        As[lk4+0][lm]=a4.x; As[lk4+1][lm]=a4.y; As[lk4+2][lm]=a4.z; As[lk4+3][lm]=a4.w;
        if (n0+ln4+3 < N){
            *(float4*)&Bs[lkb][ln4] = *(const float4*)(B + (size_t)(k0+lkb)*N + n0 + ln4);
        } else {
            #pragma unroll
            for (int u=0;u<4;u++)
                Bs[lkb][ln4+u] = (n0+ln4+u < N) ? B[(size_t)(k0+lkb)*N + n0+ln4+u] : 0.f;
        }
        __syncthreads();
        #pragma unroll
        for (int kk=0; kk<16; kk++){
            float4 a = *(const float4*)&As[kk][tr*4];
            float4 b = *(const float4*)&Bs[kk][tc*4];
            float av[4]={a.x,a.y,a.z,a.w}, bv[4]={b.x,b.y,b.z,b.w};
            #pragma unroll
            for (int i=0;i<4;i++)
                #pragma unroll
                for (int j=0;j<4;j++) acc[i][j] += av[i]*bv[j];
        }
        __syncthreads();
    }
    #pragma unroll
    for (int i=0;i<4;i++){
        int row = m0 + tr*4 + i;
        #pragma unroll
        for (int j=0;j<4;j++){
            int col = n0 + tc*4 + j;
            if (col < N){
                float v = acc[i][j];
                if (epi >= 1) v += bias[col];
                if (epi == 3) v = 1.f/(1.f + expf(-v));
                C[(size_t)row*N + col] = v;
            }
        }
    }
}

// ---------------- build compression MLP input [2][64][4096] ----------------
__global__ void build_comp_kernel(const float* __restrict__ k_pos, const float* __restrict__ v_pos){
    int idx = blockIdx.x*256 + threadIdx.x;
    int mat = idx>>18, rem = idx & 262143;
    int r = rem>>12, i = rem & 4095;
    int h = r>>5, w = r&31;
    int c = i>>6, d = i&63;
    int s = w*64 + c;
    const float* pos = mat ? v_pos : k_pos;
    int off = mat ? (DIMM + 128) : DIMM;
    g_cin[idx] = g_qkv[(size_t)s*QKVW + off + h*64 + d] + pos[(h*64+c)*64 + d];
}

__global__ void mlp1red_kernel(const float* __restrict__ kb1, const float* __restrict__ vb1){
    int idx = blockIdx.x*256 + threadIdx.x;
    int mat = idx>>18, n = idx & 4095;
    float s = g_hidp[idx] + g_hidp[idx+524288] + g_hidp[idx+1048576] + g_hidp[idx+1572864];
    s += (mat ? vb1 : kb1)[n];
    g_hid[idx] = fmaxf(s, 0.f);
}

// ---------------- mem token init ----------------
__global__ void init_ck_kernel(const float* __restrict__ mem_kv){
    int t = threadIdx.x;
    int mat = t>>7, h = (t>>6)&1, d = t&63;
    float* out = mat ? g_cv : g_ck;
    out[h*33*64 + d] = mem_kv[(mat*2+h)*64 + d];
}

// ---------------- MLP layer2 ----------------
__global__ void mlp2_kernel(const float* __restrict__ kW2, const float* __restrict__ kb2,
                            const float* __restrict__ vW2, const float* __restrict__ vb2){
    int r = blockIdx.x, mat = blockIdx.y, tid = threadIdx.x;
    int d = tid&63, kq = tid>>6;
    const float* H = g_hid + (size_t)(mat*64+r)*4096;
    const float* W = mat ? vW2 : kW2;
    const float* b = mat ? vb2 : kb2;
    float acc = 0.f;
    int kend = kq*1024 + 1024;
    for (int k = kq*1024; k < kend; k++) acc += H[k]*W[(size_t)k*64 + d];
    __shared__ float red[4][64];
    red[kq][d] = acc; __syncthreads();
    if (kq == 0){
        float s = red[0][d]+red[1][d]+red[2][d]+red[3][d] + b[d];
        int h = r>>5, w = r&31;
        float* out = mat ? g_cv : g_ck;
        out[(h*33 + 1 + w)*64 + d] = s;
    }
}

// ---------------- compressed attention + selection ----------------
__global__ void comp_attn_kernel(){
    int i = blockIdx.x, h = blockIdx.y, tid = threadIdx.x;
    __shared__ float sq[512];
    __shared__ float sk[33*65];
    __shared__ float sv[33*65];
    __shared__ float L[264], P[264], Zr[8];
    for (int o = tid; o < 512; o += 256) sq[o] = g_qkv[(size_t)i*QKVW + h*512 + o];
    for (int o = tid; o < 33*64; o += 256){
        int j = o>>6, d = o&63;
        sk[j*65+d] = g_ck[h*2112 + o];
        sv[j*65+d] = g_cv[h*2112 + o];
    }
    __syncthreads();
    for (int o = tid; o < 264; o += 256){
        int g = o/33, j = o - g*33;
        bool vis = (j == 0) || (j*64 - 1 < i);
        float a = NEGF;
        if (vis){
            float s = 0.f;
            #pragma unroll 8
            for (int d = 0; d < 64; d++) s += sq[g*64+d]*sk[j*65+d];
            a = s*0.125f;
        }
        L[o] = a;
    }
    __syncthreads();
    if (tid < 8){
        int g = tid;
        float m = NEGF;
        for (int j = 0; j < 33; j++) m = fmaxf(m, L[g*33+j]);
        float z = 0.f;
        for (int j = 0; j < 33; j++){
            float l = L[g*33+j];
            float p = (l < -1e30f) ? 0.f : expf(l - m);
            P[g*33+j] = p; z += p;
        }
        Zr[g] = z;
    }
    if (tid == 32){
        float pr[32], im[32]; float M = -1000.f;
        for (int j = 0; j < 32; j++){
            float s = 0.f;
            for (int g = 0; g < 8; g++) s += L[g*33 + j + 1];
            im[j] = s*0.125f;
            M = fmaxf(M, im[j]);
        }
        float Zs = expf(-1000.f - M);
        for (int j = 0; j < 32; j++){
            float p = (im[j] < -1e30f) ? 0.f : expf(im[j] - M);
            pr[j] = p; Zs += p;
        }
        bool taken[32];
        for (int j = 0; j < 32; j++) taken[j] = false;
        int base = (h*SEQ + i)*9;
        for (int t = 0; t < 8; t++){
            int best = -1; float bv = -1.f;
            for (int j = 0; j < 32; j++)
                if (!taken[j] && pr[j] > bv){ bv = pr[j]; best = j; }
            if (best >= 0 && bv/Zs > 1e-10f){ taken[best] = true; g_sel[base+t] = best; }
            else g_sel[base+t] = -1;
        }
        g_sel[base+8] = i>>6;
    }
    __syncthreads();
    for (int o = tid; o < 512; o += 256){
        int g = o>>6, d = o&63;
        float a = 0.f;
        for (int j = 0; j < 33; j++) a += P[g*33+j]*sv[j*65+d];
        g_cout[(size_t)i*DIMM + h*512 + o] = a/Zr[g];
    }
}

// ---------------- RoPE on q and k ----------------
__global__ void rope_kernel(){
    int idx = blockIdx.x*256 + threadIdx.x;
    if (idx >= SEQ*576) return;
    int s = idx/576, e = idx - s*576;
    float pos = (float)s;
    if (e < 512){
        int p = e & 31;
        float ang = pos*exp2f(-(float)p*0.41524101186092033f);
        float c = cosf(ang), si = sinf(ang);
        const float* b = g_qkv + (size_t)s*QKVW + e*2;
        float u0 = b[0], u1 = b[1];
        g_rq[(size_t)s*DIMM + e*2]   = u0*c - u1*si;
        g_rq[(size_t)s*DIMM + e*2+1] = u1*c + u0*si;
    } else {
        int e2 = e - 512, p = e2 & 31;
        float ang = pos*exp2f(-(float)p*0.41524101186092033f);
        float c = cosf(ang), si = sinf(ang);
        const float* b = g_qkv + (size_t)s*QKVW + DIMM + e2*2;
        float u0 = b[0], u1 = b[1];
        g_rk[(size_t)s*128 + e2*2]   = u0*c - u1*si;
        g_rk[(size_t)s*128 + e2*2+1] = u1*c + u0*si;
    }
}

// ---------------- fine attention: cp.async double-buffered tiles ----------------
__global__ void fine_attn_kernel(){
    extern __shared__ float fsm[];
    float* Kb = fsm;
    float* Vb = fsm + 8704;
    float* SQ = fsm + 16896;
    float* SP = fsm + 17408;
    int i = blockIdx.x, h = blockIdx.y, tid = threadIdx.x;
    int w = tid>>5, l = tid&31;
    int base = (h*SEQ + i)*9;
    int blks[9]; bool dg[9]; int nb = 0;
    #pragma unroll
    for (int slot = 0; slot < 9; slot++){
        int blk = (slot < 8) ? g_sel[base+slot] : (i>>6);
        if (blk >= 0){ blks[nb] = blk; dg[nb] = (slot == 8); nb++; }
    }
    for (int o = tid; o < 512; o += 128) SQ[o] = g_rq[(size_t)i*DIMM + h*512 + o];

    auto issue = [&](int t, int stg){
        int blk = blks[t];
        float* Kd = Kb + stg*4352;
        float* Vd = Vb + stg*4096;
        #pragma unroll
        for (int o = tid; o < 1024; o += 128){
            int c = o>>4, d4 = (o&15)*4;
            cp16((unsigned)__cvta_generic_to_shared(&Kd[c*68+d4]),
                 g_rk + (size_t)(blk*64+c)*128 + h*64 + d4);
            cp16((unsigned)__cvta_generic_to_shared(&Vd[c*64+d4]),
                 g_qkv + (size_t)(blk*64+c)*QKVW + 1152 + h*64 + d4);
        }
        cp_commit();
    };

    int g0 = w*2, g1 = w*2+1;
    float m0=NEGF, m1=NEGF, Z0=0.f, Z1=0.f;
    float2 a0 = make_float2(0.f,0.f), a1 = make_float2(0.f,0.f);
    int lim = i & 63;

    issue(0, 0);
    for (int t = 0; t < nb; t++){
        if (t + 1 < nb) issue(t+1, (t+1)&1);
        if (t + 1 < nb) cp_wait<1>(); else cp_wait<0>();
        __syncthreads();
        float* Kd = Kb + (t&1)*4352;
        float* Vd = Vb + (t&1)*4096;
        bool isdg = dg[t];

        float2 s0 = make_float2(0.f,0.f), s1 = make_float2(0.f,0.f);
        #pragma unroll
        for (int d4 = 0; d4 < 64; d4 += 4){
            float4 k0 = *(const float4*)&Kd[l*68+d4];
            float4 k1 = *(const float4*)&Kd[(l+32)*68+d4];
            float4 q0 = *(const float4*)&SQ[g0*64+d4];
            float4 q1 = *(const float4*)&SQ[g1*64+d4];
            s0.x += q0.x*k0.x + q0.y*k0.y + q0.z*k0.z + q0.w*k0.w;
            s0.y += q0.x*k1.x + q0.y*k1.y + q0.z*k1.z + q0.w*k1.w;
            s1.x += q1.x*k0.x + q1.y*k0.y + q1.z*k0.z + q1.w*k0.w;
            s1.y += q1.x*k1.x + q1.y*k1.y + q1.z*k1.z + q1.w*k1.w;
        }
        bool v0 = (!isdg) || (l <= lim);
        bool v1 = (!isdg) || (l+32 <= lim);
        float sa = v0 ? s0.x*0.125f : NEGF;
        float sb = v1 ? s0.y*0.125f : NEGF;
        float sc_ = v0 ? s1.x*0.125f : NEGF;
        float sd = v1 ? s1.y*0.125f : NEGF;
        float mn0 = fmaxf(m0, wmax(fmaxf(sa, sb)));
        float e0 = expf(m0 - mn0);
        float p00 = v0 ? expf(sa - mn0) : 0.f;
        float p01 = v1 ? expf(sb - mn0) : 0.f;
        SP[g0*64+l] = p00; SP[g0*64+l+32] = p01;
        Z0 = Z0*e0 + wsum(p00 + p01);
        a0.x *= e0; a0.y *= e0;
        float mn1 = fmaxf(m1, wmax(fmaxf(sc_, sd)));
        float e1 = expf(m1 - mn1);
        float p10 = v0 ? expf(sc_ - mn1) : 0.f;
        float p11 = v1 ? expf(sd - mn1) : 0.f;
        SP[g1*64+l] = p10; SP[g1*64+l+32] = p11;
        Z1 = Z1*e1 + wsum(p10 + p11);
        a1.x *= e1; a1.y *= e1;
        m0 = mn0; m1 = mn1;
        __syncwarp();
        int dl = 2*l;
        #pragma unroll
        for (int c4 = 0; c4 < 64; c4 += 4){
            float4 pg0 = *(const float4*)&SP[g0*64+c4];
            float4 pg1 = *(const float4*)&SP[g1*64+c4];
            float2 vv0 = *(const float2*)&Vd[(c4+0)*64+dl];
            float2 vv1 = *(const float2*)&Vd[(c4+1)*64+dl];
            float2 vv2 = *(const float2*)&Vd[(c4+2)*64+dl];
            float2 vv3 = *(const float2*)&Vd[(c4+3)*64+dl];
            a0.x += pg0.x*vv0.x + pg0.y*vv1.x + pg0.z*vv2.x + pg0.w*vv3.x;
            a0.y += pg0.x*vv0.y + pg0.y*vv1.y + pg0.z*vv2.y + pg0.w*vv3.y;
            a1.x += pg1.x*vv0.x + pg1.y*vv1.x + pg1.z*vv2.x + pg1.w*vv3.x;
            a1.y += pg1.x*vv0.y + pg1.y*vv1.y + pg1.z*vv2.y + pg1.w*vv3.y;
        }
        __syncthreads();
    }
    size_t ob = (size_t)i*DIMM + h*512;
    *(float2*)&g_fout[ob + g0*64 + 2*l] = make_float2(a0.x/Z0, a0.y/Z0);
    *(float2*)&g_fout[ob + g1*64 + 2*l] = make_float2(a1.x/Z1, a1.y/Z1);
}

// ---------------- sliding window: cp.async double-buffered tiles ----------------
__global__ void slide_kernel(){
    extern __shared__ float ssm[];
    float* Kb = ssm;
    float* Vb = ssm + 8704;
    float* SQ = ssm + 16896;
    float* SP = ssm + 17920;
    int tid = threadIdx.x;
    int w = tid>>5, l = tid&31;
    int hq = blockIdx.y, hk = hq>>3;
    int i0 = blockIdx.x*16;
    for (int o = tid; o < 1024; o += 128){
        int qq = o>>6, d = o&63;
        SQ[o] = g_rq[(size_t)(i0+qq)*DIMM + hq*64 + d];
    }
    int cbtop = i0>>6;
    int cb0 = cbtop - 8; if (cb0 < 0) cb0 = 0;
    int nb = cbtop - cb0 + 1;

    auto issue = [&](int t, int stg){
        int cb = cb0 + t;
        float* Kd = Kb + stg*4352;
        float* Vd = Vb + stg*4096;
        #pragma unroll
        for (int o = tid; o < 1024; o += 128){
            int c = o>>4, d4 = (o&15)*4;
            cp16((unsigned)__cvta_generic_to_shared(&Kd[c*68+d4]),
                 g_rk + (size_t)(cb*64+c)*128 + hk*64 + d4);
            cp16((unsigned)__cvta_generic_to_shared(&Vd[c*64+d4]),
                 g_qkv + (size_t)(cb*64+c)*QKVW + 1152 + hk*64 + d4);
        }
        cp_commit();
    };

    float m[4], Z[4]; float2 a[4];
    #pragma unroll
    for (int q = 0; q < 4; q++){ m[q]=NEGF; Z[q]=0.f; a[q]=make_float2(0.f,0.f); }
    int q0 = w*4;

    issue(0, 0);
    for (int t = 0; t < nb; t++){
        if (t + 1 < nb) issue(t+1, (t+1)&1);
        if (t + 1 < nb) cp_wait<1>(); else cp_wait<0>();
        __syncthreads();
        int cb = cb0 + t;
        float* Kd = Kb + (t&1)*4352;
        float* Vd = Vb + (t&1)*4096;

        float2 s[4];
        #pragma unroll
        for (int q = 0; q < 4; q++) s[q] = make_float2(0.f,0.f);
        #pragma unroll
        for (int d4 = 0; d4 < 64; d4 += 4){
            float4 k0 = *(const float4*)&Kd[l*68+d4];
            float4 k1 = *(const float4*)&Kd[(l+32)*68+d4];
            #pragma unroll
            for (int q = 0; q < 4; q++){
                float4 qv = *(const float4*)&SQ[(q0+q)*64+d4];
                s[q].x += qv.x*k0.x + qv.y*k0.y + qv.z*k0.z + qv.w*k0.w;
                s[q].y += qv.x*k1.x + qv.y*k1.y + qv.z*k1.z + qv.w*k1.w;
            }
        }
        int k0p = cb*64 + l, k1p = k0p + 32;
        #pragma unroll
        for (int q = 0; q < 4; q++){
            int i = i0 + q0 + q;
            bool v0 = (k0p <= i) && (i - k0p <= 512);
            bool v1 = (k1p <= i) && (i - k1p <= 512);
            float sx = v0 ? s[q].x*0.125f : NEGF;
            float sy = v1 ? s[q].y*0.125f : NEGF;
            float mn = fmaxf(m[q], wmax(fmaxf(sx, sy)));
            float e = expf(m[q] - mn);
            float p0 = v0 ? expf(sx - mn) : 0.f;
            float p1 = v1 ? expf(sy - mn) : 0.f;
            SP[(q0+q)*64+l] = p0; SP[(q0+q)*64+l+32] = p1;
            Z[q] = Z[q]*e + wsum(p0 + p1);
            a[q].x *= e; a[q].y *= e;
            m[q] = mn;
        }
        __syncwarp();
        int dl = 2*l;
        #pragma unroll
        for (int c4 = 0; c4 < 64; c4 += 4){
            float2 vv0 = *(const float2*)&Vd[(c4+0)*64+dl];
            float2 vv1 = *(const float2*)&Vd[(c4+1)*64+dl];
            float2 vv2 = *(const float2*)&Vd[(c4+2)*64+dl];
            float2 vv3 = *(const float2*)&Vd[(c4+3)*64+dl];
            #pragma unroll
            for (int q = 0; q < 4; q++){
                float4 pg = *(const float4*)&SP[(q0+q)*64+c4];
                a[q].x += pg.x*vv0.x + pg.y*vv1.x + pg.z*vv2.x + pg.w*vv3.x;
                a[q].y += pg.x*vv0.y + pg.y*vv1.y + pg.z*vv2.y + pg.w*vv3.y;
            }
        }
        __syncthreads();
    }
    #pragma unroll
    for (int q = 0; q < 4; q++){
        int i = i0 + q0 + q;
        *(float2*)&g_sout[(size_t)i*DIMM + hq*64 + 2*l] = make_float2(a[q].x/Z[q], a[q].y/Z[q]);
    }
}

// ---------------- gated combination ----------------
__global__ void combine_kernel(){
    int idx = blockIdx.x*256 + threadIdx.x;
    int i = idx>>10, e = idx & 1023;
    int hh = e>>6;
    const float* gt = g_gate + i*48 + hh*3;
    g_comb[idx] = gt[0]*g_cout[idx] + gt[1]*g_fout[idx] + gt[2]*g_sout[idx];
}

extern "C" void kernel_launch(void* const* d_in, const int* in_sizes, int n_in,
                              void* d_out, int out_size){
    const float* x      = (const float*)d_in[0];
    const float* rms_g  = (const float*)d_in[1];
    const float* W_qkv  = (const float*)d_in[2];
    const float* k_pos  = (const float*)d_in[3];
    const float* v_pos  = (const float*)d_in[4];
    const float* mem_kv = (const float*)d_in[5];
    const float* kW1    = (const float*)d_in[6];
    const float* kb1    = (const float*)d_in[7];
    const float* kW2    = (const float*)d_in[8];
    const float* kb2    = (const float*)d_in[9];
    const float* vW1    = (const float*)d_in[10];
    const float* vb1    = (const float*)d_in[11];
    const float* vW2    = (const float*)d_in[12];
    const float* vb2    = (const float*)d_in[13];
    const float* W_comb = (const float*)d_in[14];
    const float* b_comb = (const float*)d_in[15];
    const float* W_out  = (const float*)d_in[16];
    float* out = (float*)d_out;

    float *p_xn, *p_qkv, *p_gate, *p_comb;
    cudaGetSymbolAddress((void**)&p_xn,   g_xn);
    cudaGetSymbolAddress((void**)&p_qkv,  g_qkv);
    cudaGetSymbolAddress((void**)&p_gate, g_gate);
    cudaGetSymbolAddress((void**)&p_comb, g_comb);

    const int GEMM_SMEM  = 2*GSTG*4;
    const int MLP1_SMEM  = 2*MSTG*4;
    const int FINE_SMEM  = 17920*4;
    const int SLIDE_SMEM = 18944*4;
    cudaFuncSetAttribute(tf32gemm_kernel,  cudaFuncAttributeMaxDynamicSharedMemorySize, GEMM_SMEM);
    cudaFuncSetAttribute(mlp1_tf32_kernel, cudaFuncAttributeMaxDynamicSharedMemorySize, MLP1_SMEM);
    cudaFuncSetAttribute(fine_attn_kernel, cudaFuncAttributeMaxDynamicSharedMemorySize, FINE_SMEM);
    cudaFuncSetAttribute(slide_kernel,     cudaFuncAttributeMaxDynamicSharedMemorySize, SLIDE_SMEM);

    // side stream + events (created once on first, uncaptured call; no device allocs)
    static cudaStream_t sB = nullptr;
    static cudaEvent_t e0 = nullptr, e1 = nullptr, eR = nullptr, eS = nullptr;
    if (!sB){
        cudaStreamCreateWithFlags(&sB, cudaStreamNonBlocking);
        cudaEventCreateWithFlags(&e0, cudaEventDisableTiming);
        cudaEventCreateWithFlags(&e1, cudaEventDisableTiming);
        cudaEventCreateWithFlags(&eR, cudaEventDisableTiming);
        cudaEventCreateWithFlags(&eS, cudaEventDisableTiming);
    }

    // main stream (legacy default)
    rmsnorm_kernel<<<SEQ, 256>>>(x, rms_g);
    cudaEventRecord(e0, 0);
    tf32gemm_kernel<<<dim3(10, 16), 256, GEMM_SMEM>>>(p_xn, W_qkv, p_qkv, SEQ, QKVW, DIMM);
    cudaEventRecord(e1, 0);

    // side stream: gates (needs xn) ; rope+slide (need qkv)
    cudaStreamWaitEvent(sB, e0, 0);
    sgemm_kernel<<<dim3(1, 32), 256, 0, sB>>>(p_xn, W_comb, b_comb, p_gate, SEQ, 48, DIMM, 3);
    cudaStreamWaitEvent(sB, e1, 0);
    rope_kernel<<<(SEQ*576 + 255)/256, 256, 0, sB>>>();
    cudaEventRecord(eR, sB);
    slide_kernel<<<dim3(128, 16), 128, SLIDE_SMEM, sB>>>();
    cudaEventRecord(eS, sB);

    // main stream: MLP chain + compressed attention
    build_comp_kernel<<<2048, 256>>>(k_pos, v_pos);
    mlp1_tf32_kernel<<<dim3(32, 2, 4), 256, MLP1_SMEM>>>(kW1, vW1);
    mlp1red_kernel<<<2048, 256>>>(kb1, vb1);
    init_ck_kernel<<<1, 256>>>(mem_kv);
    mlp2_kernel<<<dim3(64, 2), 256>>>(kW2, kb2, vW2, vb2);
    comp_attn_kernel<<<dim3(SEQ, 2), 256>>>();

    // fine needs rope (sB) + comp_attn (main)
    cudaStreamWaitEvent(0, eR, 0);
    fine_attn_kernel<<<dim3(SEQ, 2), 128, FINE_SMEM>>>();

    // combine needs slide + gates (both sB) + cout/fout
    cudaStreamWaitEvent(0, eS, 0);
    combine_kernel<<<8192, 256>>>();
    tf32gemm_kernel<<<dim3(8, 16), 256, GEMM_SMEM>>>(p_comb, W_out, out, SEQ, DIMM, DIMM);
}

// round 12
// speedup vs baseline: 1.4315x; 1.4315x over previous
#include <cuda_runtime.h>
#include <math.h>

#define SEQ   2048
#define DIMM  1024
#define QKVW  1280
#define NEGF  (-3.402823466e38f)

// ---------------- scratch (static device globals) ----------------
__device__ __align__(16) float g_xn  [SEQ*DIMM];
__device__ __align__(16) float g_qkv [SEQ*QKVW];
__device__ __align__(16) float g_rq  [SEQ*DIMM];
__device__ __align__(16) float g_rk  [SEQ*128];
__device__ __align__(16) float g_cin [2*64*4096];
__device__ __align__(16) float g_hidp[4*2*64*4096];
__device__ __align__(16) float g_hid [2*64*4096];
__device__ __align__(16) float g_gp  [2*SEQ*QKVW];
__device__ __align__(16) float g_ck  [2*33*64];
__device__ __align__(16) float g_cv  [2*33*64];
__device__ __align__(16) float g_cout[SEQ*DIMM];
__device__ __align__(16) float g_fout[SEQ*DIMM];
__device__ __align__(16) float g_sout[SEQ*DIMM];
__device__ __align__(16) float g_gate[SEQ*48];
__device__ __align__(16) float g_comb[SEQ*DIMM];
__device__            int   g_sel [2*SEQ*9];

__device__ __forceinline__ float wmax(float v){
    #pragma unroll
    for (int o=16;o;o>>=1) v = fmaxf(v, __shfl_xor_sync(0xffffffffu, v, o));
    return v;
}
__device__ __forceinline__ float wsum(float v){
    #pragma unroll
    for (int o=16;o;o>>=1) v += __shfl_xor_sync(0xffffffffu, v, o);
    return v;
}

// ---------------- cp.async helpers ----------------
__device__ __forceinline__ void cp16(unsigned dst, const void* src){
    asm volatile("cp.async.cg.shared.global [%0], [%1], 16;" :: "r"(dst), "l"(src));
}
__device__ __forceinline__ void cp_commit(){ asm volatile("cp.async.commit_group;"); }
template<int N> __device__ __forceinline__ void cp_wait(){
    asm volatile("cp.async.wait_group %0;" :: "n"(N));
}

// ---------------- tf32 helpers ----------------
__device__ __forceinline__ void tf32_split(float f, unsigned& hi, unsigned& lo){
    asm("cvt.rna.tf32.f32 %0, %1;" : "=r"(hi) : "f"(f));
    float rem = f - __uint_as_float(hi);
    asm("cvt.rna.tf32.f32 %0, %1;" : "=r"(lo) : "f"(rem));
}
__device__ __forceinline__ void mma_tf32(float* c, const unsigned* a, const unsigned* b){
    asm volatile(
        "mma.sync.aligned.m16n8k8.row.col.f32.tf32.tf32.f32 "
        "{%0,%1,%2,%3},{%4,%5,%6,%7},{%8,%9},{%0,%1,%2,%3};"
        : "+f"(c[0]), "+f"(c[1]), "+f"(c[2]), "+f"(c[3])
        : "r"(a[0]), "r"(a[1]), "r"(a[2]), "r"(a[3]), "r"(b[0]), "r"(b[1]));
}
__device__ __forceinline__ void ldsm4(unsigned* r, unsigned addr){
    asm volatile("ldmatrix.sync.aligned.m8n8.x4.shared.b16 {%0,%1,%2,%3}, [%4];"
        : "=r"(r[0]), "=r"(r[1]), "=r"(r[2]), "=r"(r[3]) : "r"(addr));
}

// ---------------- RMSNorm ----------------
__global__ void rmsnorm_kernel(const float* __restrict__ x, const float* __restrict__ g){
    int s = blockIdx.x, tid = threadIdx.x;
    const float* xr = x + (size_t)s*DIMM;
    __shared__ float red[256];
    float ss = 0.f;
    for (int i = tid; i < DIMM; i += 256){ float v = xr[i]; ss += v*v; }
    red[tid] = ss; __syncthreads();
    for (int st = 128; st > 0; st >>= 1){ if (tid < st) red[tid] += red[tid+st]; __syncthreads(); }
    float sc = rsqrtf(red[0]*(1.f/DIMM) + 1.1920929e-7f);
    for (int i = tid; i < DIMM; i += 256) g_xn[(size_t)s*DIMM+i] = xr[i]*sc*g[i];
}

// ---------------- tf32x3 GEMM, double-buffered + split-K: BM=128,BN=128,BK=16 ----------------
// grid.z = K/Kc chunks; each chunk writes partials to Cp + z*M*N.
#define GSTG 9344
__global__ __launch_bounds__(256,2) void tf32gemm_kernel(
        const float* __restrict__ A, const float* __restrict__ B,
        float* __restrict__ Cp, int M, int N, int K, int Kc){
    extern __shared__ unsigned dsm[];
    int tid = threadIdx.x, lane = tid&31, wid = tid>>5;
    int m0b = blockIdx.y*128, n0b = blockIdx.x*128;
    int kbase = blockIdx.z*Kc;
    int mw = (wid>>2)*64, nw = (wid&3)*32;
    int r = lane>>2, c = lane&3;
    float acc[4][4][4] = {};
    int la_m = tid>>2, la_k = (tid&3)*4;
    int lb_r = tid>>5, lb_n = (tid&31)*4;
    int sub = lane>>3, e = lane&7;
    int a_row = mw + ((sub&1)<<3) + e;
    int a_col = (sub>>1)<<2;
    unsigned sm_base = (unsigned)__cvta_generic_to_shared(dsm);

    float4 pa0 = *(const float4*)(A + (size_t)(m0b+la_m)*K + kbase + la_k);
    float4 pa1 = *(const float4*)(A + (size_t)(m0b+la_m+64)*K + kbase + la_k);
    float4 pb0 = *(const float4*)(B + (size_t)(kbase+lb_r)*N + n0b + lb_n);
    float4 pb1 = *(const float4*)(B + (size_t)(kbase+lb_r+8)*N + n0b + lb_n);

    {
        unsigned* Ah = dsm; unsigned* Al = dsm + 2560; unsigned* Bhl = dsm + 5120;
        float fa0[4]={pa0.x,pa0.y,pa0.z,pa0.w}, fa1[4]={pa1.x,pa1.y,pa1.z,pa1.w};
        #pragma unroll
        for (int u = 0; u < 4; u++){
            unsigned hi, lo;
            tf32_split(fa0[u], hi, lo); Ah[la_m*20 + la_k+u] = hi;      Al[la_m*20 + la_k+u] = lo;
            tf32_split(fa1[u], hi, lo); Ah[(la_m+64)*20 + la_k+u] = hi; Al[(la_m+64)*20 + la_k+u] = lo;
        }
        unsigned h0,l0,h1,l1,h2,l2,h3,l3;
        tf32_split(pb0.x,h0,l0); tf32_split(pb0.y,h1,l1);
        tf32_split(pb0.z,h2,l2); tf32_split(pb0.w,h3,l3);
        *(uint4*)&Bhl[lb_r*264 + lb_n*2]     = make_uint4(h0,l0,h1,l1);
        *(uint4*)&Bhl[lb_r*264 + lb_n*2 + 4] = make_uint4(h2,l2,h3,l3);
        tf32_split(pb1.x,h0,l0); tf32_split(pb1.y,h1,l1);
        tf32_split(pb1.z,h2,l2); tf32_split(pb1.w,h3,l3);
        *(uint4*)&Bhl[(lb_r+8)*264 + lb_n*2]     = make_uint4(h0,l0,h1,l1);
        *(uint4*)&Bhl[(lb_r+8)*264 + lb_n*2 + 4] = make_uint4(h2,l2,h3,l3);
    }
    if (16 < Kc){
        pa0 = *(const float4*)(A + (size_t)(m0b+la_m)*K + kbase + 16 + la_k);
        pa1 = *(const float4*)(A + (size_t)(m0b+la_m+64)*K + kbase + 16 + la_k);
        pb0 = *(const float4*)(B + (size_t)(kbase+16+lb_r)*N + n0b + lb_n);
        pb1 = *(const float4*)(B + (size_t)(kbase+16+lb_r+8)*N + n0b + lb_n);
    }
    __syncthreads();

    int cur = 0;
    for (int k0 = 0; k0 < Kc; k0 += 16){
        {
            unsigned stg = cur*GSTG;
            unsigned* Bhl = dsm + stg + 5120;
            #pragma unroll
            for (int ks = 0; ks < 2; ks++){
                int kk = ks*8;
                unsigned ah[4][4], al[4][4];
                #pragma unroll
                for (int t = 0; t < 4; t++){
                    unsigned offh = sm_base + (stg + (a_row + t*16)*20 + kk + a_col)*4u;
                    ldsm4(ah[t], offh);
                    ldsm4(al[t], offh + 2560*4u);
                }
                #pragma unroll
                for (int j = 0; j < 4; j++){
                    int nc = nw + j*8 + r;
                    uint2 b0 = *(const uint2*)&Bhl[(kk+c)*264 + nc*2];
                    uint2 b1 = *(const uint2*)&Bhl[(kk+c+4)*264 + nc*2];
                    unsigned bh[2] = { b0.x, b1.x };
                    unsigned bl[2] = { b0.y, b1.y };
                    #pragma unroll
                    for (int t = 0; t < 4; t++){
                        mma_tf32(acc[t][j], ah[t], bh);
                        mma_tf32(acc[t][j], ah[t], bl);
                        mma_tf32(acc[t][j], al[t], bh);
                    }
                }
            }
        }
        if (k0 + 16 < Kc){
            unsigned nstg = (cur^1)*GSTG;
            unsigned* Ah = dsm + nstg; unsigned* Al = dsm + nstg + 2560; unsigned* Bhl = dsm + nstg + 5120;
            float fa0[4]={pa0.x,pa0.y,pa0.z,pa0.w}, fa1[4]={pa1.x,pa1.y,pa1.z,pa1.w};
            #pragma unroll
            for (int u = 0; u < 4; u++){
                unsigned hi, lo;
                tf32_split(fa0[u], hi, lo); Ah[la_m*20 + la_k+u] = hi;      Al[la_m*20 + la_k+u] = lo;
                tf32_split(fa1[u], hi, lo); Ah[(la_m+64)*20 + la_k+u] = hi; Al[(la_m+64)*20 + la_k+u] = lo;
            }
            unsigned h0,l0,h1,l1,h2,l2,h3,l3;
            tf32_split(pb0.x,h0,l0); tf32_split(pb0.y,h1,l1);
            tf32_split(pb0.z,h2,l2); tf32_split(pb0.w,h3,l3);
            *(uint4*)&Bhl[lb_r*264 + lb_n*2]     = make_uint4(h0,l0,h1,l1);
            *(uint4*)&Bhl[lb_r*264 + lb_n*2 + 4] = make_uint4(h2,l2,h3,l3);
            tf32_split(pb1.x,h0,l0); tf32_split(pb1.y,h1,l1);
            tf32_split(pb1.z,h2,l2); tf32_split(pb1.w,h3,l3);
            *(uint4*)&Bhl[(lb_r+8)*264 + lb_n*2]     = make_uint4(h0,l0,h1,l1);
            *(uint4*)&Bhl[(lb_r+8)*264 + lb_n*2 + 4] = make_uint4(h2,l2,h3,l3);
        }
        if (k0 + 32 < Kc){
            pa0 = *(const float4*)(A + (size_t)(m0b+la_m)*K + kbase + k0+32 + la_k);
            pa1 = *(const float4*)(A + (size_t)(m0b+la_m+64)*K + kbase + k0+32 + la_k);
            pb0 = *(const float4*)(B + (size_t)(kbase+k0+32+lb_r)*N + n0b + lb_n);
            pb1 = *(const float4*)(B + (size_t)(kbase+k0+32+lb_r+8)*N + n0b + lb_n);
        }
        __syncthreads();
        cur ^= 1;
    }
    float* O = Cp + (size_t)blockIdx.z*M*N;
    #pragma unroll
    for (int t = 0; t < 4; t++)
        #pragma unroll
        for (int j = 0; j < 4; j++){
            int row = m0b + mw + t*16 + r;
            int col = n0b + nw + j*8 + c*2;
            O[(size_t)row*N + col]       = acc[t][j][0];
            O[(size_t)row*N + col+1]     = acc[t][j][1];
            O[(size_t)(row+8)*N + col]   = acc[t][j][2];
            O[(size_t)(row+8)*N + col+1] = acc[t][j][3];
        }
}

// partial sum: out[i] = p[i] + p[i+n]
__global__ void add2_kernel(const float* __restrict__ p, float* __restrict__ out, int n){
    int idx = blockIdx.x*256 + threadIdx.x;
    if (idx < n) out[idx] = p[idx] + p[idx + n];
}

// ---------------- MLP1 tf32x3 split-K, double-buffered: BM=64,BN=128 ----------------
#define MSTG 6784
__global__ __launch_bounds__(256,2) void mlp1_tf32_kernel(
        const float* __restrict__ kW1, const float* __restrict__ vW1){
    extern __shared__ unsigned dsm[];
    int tid = threadIdx.x, lane = tid&31, wid = tid>>5;
    int mat = blockIdx.y, kc = blockIdx.z;
    const float* A = g_cin + (size_t)mat*262144;
    const float* B = (mat ? vW1 : kW1);
    int n0b = blockIdx.x*128, kbase = kc*1024;
    int mw = (wid>>2)*32, nw = (wid&3)*32;
    int r = lane>>2, c = lane&3;
    float acc[2][4][4] = {};
    int fa_k = tid&15, fa_m = tid>>4;
    int fb_n = tid&127, fb_r = tid>>7;
    int sub = lane>>3, e = lane&7;
    int a_row = mw + ((sub&1)<<3) + e;
    int a_col = (sub>>1)<<2;
    unsigned sm_base = (unsigned)__cvta_generic_to_shared(dsm);

    float pa[4], pb[8];
    #pragma unroll
    for (int p = 0; p < 4; p++)
        pa[p] = A[(size_t)(fa_m + 16*p)*4096 + kbase + fa_k];
    #pragma unroll
    for (int p = 0; p < 8; p++)
        pb[p] = B[(size_t)(kbase + fb_r + 2*p)*4096 + n0b + fb_n];

    {
        unsigned* Ah = dsm; unsigned* Al = dsm + 1280; unsigned* Bhl = dsm + 2560;
        #pragma unroll
        for (int p = 0; p < 4; p++){
            unsigned hi, lo;
            tf32_split(pa[p], hi, lo);
            Ah[(fa_m + 16*p)*20 + fa_k] = hi;
            Al[(fa_m + 16*p)*20 + fa_k] = lo;
        }
        #pragma unroll
        for (int p = 0; p < 8; p++){
            unsigned hi, lo;
            tf32_split(pb[p], hi, lo);
            *(uint2*)&Bhl[(fb_r + 2*p)*264 + fb_n*2] = make_uint2(hi, lo);
        }
    }
    {
        #pragma unroll
        for (int p = 0; p < 4; p++)
            pa[p] = A[(size_t)(fa_m + 16*p)*4096 + kbase + 16 + fa_k];
        #pragma unroll
        for (int p = 0; p < 8; p++)
            pb[p] = B[(size_t)(kbase + 16 + fb_r + 2*p)*4096 + n0b + fb_n];
    }
    __syncthreads();

    int cur = 0;
    for (int k0 = 0; k0 < 1024; k0 += 16){
        {
            unsigned stg = cur*MSTG;
            unsigned* Bhl = dsm + stg + 2560;
            #pragma unroll
            for (int ks = 0; ks < 2; ks++){
                int kk = ks*8;
                unsigned ah[2][4], al[2][4];
                #pragma unroll
                for (int t = 0; t < 2; t++){
                    unsigned offh = sm_base + (stg + (a_row + t*16)*20 + kk + a_col)*4u;
                    ldsm4(ah[t], offh);
                    ldsm4(al[t], offh + 1280*4u);
                }
                #pragma unroll
                for (int j = 0; j < 4; j++){
                    int nc = nw + j*8 + r;
                    uint2 b0 = *(const uint2*)&Bhl[(kk+c)*264 + nc*2];
                    uint2 b1 = *(const uint2*)&Bhl[(kk+c+4)*264 + nc*2];
                    unsigned bh[2] = { b0.x, b1.x };
                    unsigned bl[2] = { b0.y, b1.y };
                    #pragma unroll
                    for (int t = 0; t < 2; t++){
                        mma_tf32(acc[t][j], ah[t], bh);
                        mma_tf32(acc[t][j], ah[t], bl);
                        mma_tf32(acc[t][j], al[t], bh);
                    }
                }
            }
        }
        if (k0 + 16 < 1024){
            unsigned nstg = (cur^1)*MSTG;
            unsigned* Ah = dsm + nstg; unsigned* Al = dsm + nstg + 1280; unsigned* Bhl = dsm + nstg + 2560;
            #pragma unroll
            for (int p = 0; p < 4; p++){
                unsigned hi, lo;
                tf32_split(pa[p], hi, lo);
                Ah[(fa_m + 16*p)*20 + fa_k] = hi;
                Al[(fa_m + 16*p)*20 + fa_k] = lo;
            }
            #pragma unroll
            for (int p = 0; p < 8; p++){
                unsigned hi, lo;
                tf32_split(pb[p], hi, lo);
                *(uint2*)&Bhl[(fb_r + 2*p)*264 + fb_n*2] = make_uint2(hi, lo);
            }
        }
        if (k0 + 32 < 1024){
            #pragma unroll
            for (int p = 0; p < 4; p++)
                pa[p] = A[(size_t)(fa_m + 16*p)*4096 + kbase + k0 + 32 + fa_k];
            #pragma unroll
            for (int p = 0; p < 8; p++)
                pb[p] = B[(size_t)(kbase + k0 + 32 + fb_r + 2*p)*4096 + n0b + fb_n];
        }
        __syncthreads();
        cur ^= 1;
    }
    float* O = g_hidp + (size_t)(kc*2+mat)*64*4096;
    #pragma unroll
    for (int t = 0; t < 2; t++)
        #pragma unroll
        for (int j = 0; j < 4; j++){
            int row = mw + t*16 + r;
            int col = n0b + nw + j*8 + c*2;
            O[(size_t)row*4096 + col]       = acc[t][j][0];
            O[(size_t)row*4096 + col+1]     = acc[t][j][1];
            O[(size_t)(row+8)*4096 + col]   = acc[t][j][2];
            O[(size_t)(row+8)*4096 + col+1] = acc[t][j][3];
        }
}

// ---------------- small SGEMM (gates) ----------------
__global__ void sgemm_kernel(const float* __restrict__ A, const float* __restrict__ B,
                             const float* __restrict__ bias, float* __restrict__ C,
                             int M, int N, int K, int epi){
    __shared__ __align__(16) float As[16][72];
    __shared__ __align__(16) float Bs[16][72];
    int tid = threadIdx.x;
    int tr = tid>>4, tc = tid&15;
    int m0 = blockIdx.y*64, n0 = blockIdx.x*64;
    int lm = tid>>2, lk4 = (tid&3)*4;
    int lkb = tid>>4, ln4 = (tid&15)*4;
    float acc[4][4] = {};
    for (int k0 = 0; k0 < K; k0 += 16){
        float4 a4 = *(const float4*)(A + (size_t)(m0+lm)*K + k0 + lk4);
        As[lk4+0][lm]=a4.x; As[lk4+1][lm]=a4.y; As[lk4+2][lm]=a4.z; As[lk4+3][lm]=a4.w;
        if (n0+ln4+3 < N){
            *(float4*)&Bs[lkb][ln4] = *(const float4*)(B + (size_t)(k0+lkb)*N + n0 + ln4);
        } else {
            #pragma unroll
            for (int u=0;u<4;u++)
                Bs[lkb][ln4+u] = (n0+ln4+u < N) ? B[(size_t)(k0+lkb)*N + n0+ln4+u] : 0.f;
        }
        __syncthreads();
        #pragma unroll
        for (int kk=0; kk<16; kk++){
            float4 a = *(const float4*)&As[kk][tr*4];
            float4 b = *(const float4*)&Bs[kk][tc*4];
            float av[4]={a.x,a.y,a.z,a.w}, bv[4]={b.x,b.y,b.z,b.w};
            #pragma unroll
            for (int i=0;i<4;i++)
                #pragma unroll
                for (int j=0;j<4;j++) acc[i][j] += av[i]*bv[j];
        }
        __syncthreads();
    }
    #pragma unroll
    for (int i=0;i<4;i++){
        int row = m0 + tr*4 + i;
        #pragma unroll
        for (int j=0;j<4;j++){
            int col = n0 + tc*4 + j;
            if (col < N){
                float v = acc[i][j];
                if (epi >= 1) v += bias[col];
                if (epi == 3) v = 1.f/(1.f + expf(-v));
                C[(size_t)row*N + col] = v;
            }
        }
    }
}

// ---------------- build compression MLP input [2][64][4096] ----------------
__global__ void build_comp_kernel(const float* __restrict__ k_pos, const float* __restrict__ v_pos){
    int idx = blockIdx.x*256 + threadIdx.x;
    int mat = idx>>18, rem = idx & 262143;
    int r = rem>>12, i = rem & 4095;
    int h = r>>5, w = r&31;
    int c = i>>6, d = i&63;
    int s = w*64 + c;
    const float* pos = mat ? v_pos : k_pos;
    int off = mat ? (DIMM + 128) : DIMM;
    g_cin[idx] = g_qkv[(size_t)s*QKVW + off + h*64 + d] + pos[(h*64+c)*64 + d];
}

__global__ void mlp1red_kernel(const float* __restrict__ kb1, const float* __restrict__ vb1){
    int idx = blockIdx.x*256 + threadIdx.x;
    int mat = idx>>18, n = idx & 4095;
    float s = g_hidp[idx] + g_hidp[idx+524288] + g_hidp[idx+1048576] + g_hidp[idx+1572864];
    s += (mat ? vb1 : kb1)[n];
    g_hid[idx] = fmaxf(s, 0.f);
}

// ---------------- mem token init ----------------
__global__ void init_ck_kernel(const float* __restrict__ mem_kv){
    int t = threadIdx.x;
    int mat = t>>7, h = (t>>6)&1, d = t&63;
    float* out = mat ? g_cv : g_ck;
    out[h*33*64 + d] = mem_kv[(mat*2+h)*64 + d];
}

// ---------------- MLP layer2 ----------------
__global__ void mlp2_kernel(const float* __restrict__ kW2, const float* __restrict__ kb2,
                            const float* __restrict__ vW2, const float* __restrict__ vb2){
    int r = blockIdx.x, mat = blockIdx.y, tid = threadIdx.x;
    int d = tid&63, kq = tid>>6;
    const float* H = g_hid + (size_t)(mat*64+r)*4096;
    const float* W = mat ? vW2 : kW2;
    const float* b = mat ? vb2 : kb2;
    float acc = 0.f;
    int kend = kq*1024 + 1024;
    for (int k = kq*1024; k < kend; k++) acc += H[k]*W[(size_t)k*64 + d];
    __shared__ float red[4][64];
    red[kq][d] = acc; __syncthreads();
    if (kq == 0){
        float s = red[0][d]+red[1][d]+red[2][d]+red[3][d] + b[d];
        int h = r>>5, w = r&31;
        float* out = mat ? g_cv : g_ck;
        out[(h*33 + 1 + w)*64 + d] = s;
    }
}

// ---------------- compressed attention + selection ----------------
__global__ void comp_attn_kernel(){
    int i = blockIdx.x, h = blockIdx.y, tid = threadIdx.x;
    __shared__ float sq[512];
    __shared__ float sk[33*65];
    __shared__ float sv[33*65];
    __shared__ float L[264], P[264], Zr[8];
    for (int o = tid; o < 512; o += 256) sq[o] = g_qkv[(size_t)i*QKVW + h*512 + o];
    for (int o = tid; o < 33*64; o += 256){
        int j = o>>6, d = o&63;
        sk[j*65+d] = g_ck[h*2112 + o];
        sv[j*65+d] = g_cv[h*2112 + o];
    }
    __syncthreads();
    for (int o = tid; o < 264; o += 256){
        int g = o/33, j = o - g*33;
        bool vis = (j == 0) || (j*64 - 1 < i);
        float a = NEGF;
        if (vis){
            float s = 0.f;
            #pragma unroll 8
            for (int d = 0; d < 64; d++) s += sq[g*64+d]*sk[j*65+d];
            a = s*0.125f;
        }
        L[o] = a;
    }
    __syncthreads();
    if (tid < 8){
        int g = tid;
        float m = NEGF;
        for (int j = 0; j < 33; j++) m = fmaxf(m, L[g*33+j]);
        float z = 0.f;
        for (int j = 0; j < 33; j++){
            float l = L[g*33+j];
            float p = (l < -1e30f) ? 0.f : expf(l - m);
            P[g*33+j] = p; z += p;
        }
        Zr[g] = z;
    }
    if (tid == 32){
        float pr[32], im[32]; float M = -1000.f;
        for (int j = 0; j < 32; j++){
            float s = 0.f;
            for (int g = 0; g < 8; g++) s += L[g*33 + j + 1];
            im[j] = s*0.125f;
            M = fmaxf(M, im[j]);
        }
        float Zs = expf(-1000.f - M);
        for (int j = 0; j < 32; j++){
            float p = (im[j] < -1e30f) ? 0.f : expf(im[j] - M);
            pr[j] = p; Zs += p;
        }
        bool taken[32];
        for (int j = 0; j < 32; j++) taken[j] = false;
        int base = (h*SEQ + i)*9;
        for (int t = 0; t < 8; t++){
            int best = -1; float bv = -1.f;
            for (int j = 0; j < 32; j++)
                if (!taken[j] && pr[j] > bv){ bv = pr[j]; best = j; }
            if (best >= 0 && bv/Zs > 1e-10f){ taken[best] = true; g_sel[base+t] = best; }
            else g_sel[base+t] = -1;
        }
        g_sel[base+8] = i>>6;
    }
    __syncthreads();
    for (int o = tid; o < 512; o += 256){
        int g = o>>6, d = o&63;
        float a = 0.f;
        for (int j = 0; j < 33; j++) a += P[g*33+j]*sv[j*65+d];
        g_cout[(size_t)i*DIMM + h*512 + o] = a/Zr[g];
    }
}

// ---------------- RoPE on q and k ----------------
__global__ void rope_kernel(){
    int idx = blockIdx.x*256 + threadIdx.x;
    if (idx >= SEQ*576) return;
    int s = idx/576, e = idx - s*576;
    float pos = (float)s;
    if (e < 512){
        int p = e & 31;
        float ang = pos*exp2f(-(float)p*0.41524101186092033f);
        float c = cosf(ang), si = sinf(ang);
        const float* b = g_qkv + (size_t)s*QKVW + e*2;
        float u0 = b[0], u1 = b[1];
        g_rq[(size_t)s*DIMM + e*2]   = u0*c - u1*si;
        g_rq[(size_t)s*DIMM + e*2+1] = u1*c + u0*si;
    } else {
        int e2 = e - 512, p = e2 & 31;
        float ang = pos*exp2f(-(float)p*0.41524101186092033f);
        float c = cosf(ang), si = sinf(ang);
        const float* b = g_qkv + (size_t)s*QKVW + DIMM + e2*2;
        float u0 = b[0], u1 = b[1];
        g_rk[(size_t)s*128 + e2*2]   = u0*c - u1*si;
        g_rk[(size_t)s*128 + e2*2+1] = u1*c + u0*si;
    }
}

// ---------------- fine attention: cp.async double-buffered tiles ----------------
__global__ void fine_attn_kernel(){
    extern __shared__ float fsm[];
    float* Kb = fsm;
    float* Vb = fsm + 8704;
    float* SQ = fsm + 16896;
    float* SP = fsm + 17408;
    int i = blockIdx.x, h = blockIdx.y, tid = threadIdx.x;
    int w = tid>>5, l = tid&31;
    int base = (h*SEQ + i)*9;
    int blks[9]; bool dg[9]; int nb = 0;
    #pragma unroll
    for (int slot = 0; slot < 9; slot++){
        int blk = (slot < 8) ? g_sel[base+slot] : (i>>6);
        if (blk >= 0){ blks[nb] = blk; dg[nb] = (slot == 8); nb++; }
    }
    for (int o = tid; o < 512; o += 128) SQ[o] = g_rq[(size_t)i*DIMM + h*512 + o];

    auto issue = [&](int t, int stg){
        int blk = blks[t];
        float* Kd = Kb + stg*4352;
        float* Vd = Vb + stg*4096;
        #pragma unroll
        for (int o = tid; o < 1024; o += 128){
            int c = o>>4, d4 = (o&15)*4;
            cp16((unsigned)__cvta_generic_to_shared(&Kd[c*68+d4]),
                 g_rk + (size_t)(blk*64+c)*128 + h*64 + d4);
            cp16((unsigned)__cvta_generic_to_shared(&Vd[c*64+d4]),
                 g_qkv + (size_t)(blk*64+c)*QKVW + 1152 + h*64 + d4);
        }
        cp_commit();
    };

    int g0 = w*2, g1 = w*2+1;
    float m0=NEGF, m1=NEGF, Z0=0.f, Z1=0.f;
    float2 a0 = make_float2(0.f,0.f), a1 = make_float2(0.f,0.f);
    int lim = i & 63;

    issue(0, 0);
    for (int t = 0; t < nb; t++){
        if (t + 1 < nb) issue(t+1, (t+1)&1);
        if (t + 1 < nb) cp_wait<1>(); else cp_wait<0>();
        __syncthreads();
        float* Kd = Kb + (t&1)*4352;
        float* Vd = Vb + (t&1)*4096;
        bool isdg = dg[t];

        float2 s0 = make_float2(0.f,0.f), s1 = make_float2(0.f,0.f);
        #pragma unroll
        for (int d4 = 0; d4 < 64; d4 += 4){
            float4 k0 = *(const float4*)&Kd[l*68+d4];
            float4 k1 = *(const float4*)&Kd[(l+32)*68+d4];
            float4 q0 = *(const float4*)&SQ[g0*64+d4];
            float4 q1 = *(const float4*)&SQ[g1*64+d4];
            s0.x += q0.x*k0.x + q0.y*k0.y + q0.z*k0.z + q0.w*k0.w;
            s0.y += q0.x*k1.x + q0.y*k1.y + q0.z*k1.z + q0.w*k1.w;
            s1.x += q1.x*k0.x + q1.y*k0.y + q1.z*k0.z + q1.w*k0.w;
            s1.y += q1.x*k1.x + q1.y*k1.y + q1.z*k1.z + q1.w*k1.w;
        }
        bool v0 = (!isdg) || (l <= lim);
        bool v1 = (!isdg) || (l+32 <= lim);
        float sa = v0 ? s0.x*0.125f : NEGF;
        float sb = v1 ? s0.y*0.125f : NEGF;
        float sc_ = v0 ? s1.x*0.125f : NEGF;
        float sd = v1 ? s1.y*0.125f : NEGF;
        float mn0 = fmaxf(m0, wmax(fmaxf(sa, sb)));
        float e0 = expf(m0 - mn0);
        float p00 = v0 ? expf(sa - mn0) : 0.f;
        float p01 = v1 ? expf(sb - mn0) : 0.f;
        SP[g0*64+l] = p00; SP[g0*64+l+32] = p01;
        Z0 = Z0*e0 + wsum(p00 + p01);
        a0.x *= e0; a0.y *= e0;
        float mn1 = fmaxf(m1, wmax(fmaxf(sc_, sd)));
        float e1 = expf(m1 - mn1);
        float p10 = v0 ? expf(sc_ - mn1) : 0.f;
        float p11 = v1 ? expf(sd - mn1) : 0.f;
        SP[g1*64+l] = p10; SP[g1*64+l+32] = p11;
        Z1 = Z1*e1 + wsum(p10 + p11);
        a1.x *= e1; a1.y *= e1;
        m0 = mn0; m1 = mn1;
        __syncwarp();
        int dl = 2*l;
        #pragma unroll
        for (int c4 = 0; c4 < 64; c4 += 4){
            float4 pg0 = *(const float4*)&SP[g0*64+c4];
            float4 pg1 = *(const float4*)&SP[g1*64+c4];
            float2 vv0 = *(const float2*)&Vd[(c4+0)*64+dl];
            float2 vv1 = *(const float2*)&Vd[(c4+1)*64+dl];
            float2 vv2 = *(const float2*)&Vd[(c4+2)*64+dl];
            float2 vv3 = *(const float2*)&Vd[(c4+3)*64+dl];
            a0.x += pg0.x*vv0.x + pg0.y*vv1.x + pg0.z*vv2.x + pg0.w*vv3.x;
            a0.y += pg0.x*vv0.y + pg0.y*vv1.y + pg0.z*vv2.y + pg0.w*vv3.y;
            a1.x += pg1.x*vv0.x + pg1.y*vv1.x + pg1.z*vv2.x + pg1.w*vv3.x;
            a1.y += pg1.x*vv0.y + pg1.y*vv1.y + pg1.z*vv2.y + pg1.w*vv3.y;
        }
        __syncthreads();
    }
    size_t ob = (size_t)i*DIMM + h*512;
    *(float2*)&g_fout[ob + g0*64 + 2*l] = make_float2(a0.x/Z0, a0.y/Z0);
    *(float2*)&g_fout[ob + g1*64 + 2*l] = make_float2(a1.x/Z1, a1.y/Z1);
}

// ---------------- sliding window: cp.async double-buffered tiles ----------------
__global__ void slide_kernel(){
    extern __shared__ float ssm[];
    float* Kb = ssm;
    float* Vb = ssm + 8704;
    float* SQ = ssm + 16896;
    float* SP = ssm + 17920;
    int tid = threadIdx.x;
    int w = tid>>5, l = tid&31;
    int hq = blockIdx.y, hk = hq>>3;
    int i0 = blockIdx.x*16;
    for (int o = tid; o < 1024; o += 128){
        int qq = o>>6, d = o&63;
        SQ[o] = g_rq[(size_t)(i0+qq)*DIMM + hq*64 + d];
    }
    int cbtop = i0>>6;
    int cb0 = cbtop - 8; if (cb0 < 0) cb0 = 0;
    int nb = cbtop - cb0 + 1;

    auto issue = [&](int t, int stg){
        int cb = cb0 + t;
        float* Kd = Kb + stg*4352;
        float* Vd = Vb + stg*4096;
        #pragma unroll
        for (int o = tid; o < 1024; o += 128){
            int c = o>>4, d4 = (o&15)*4;
            cp16((unsigned)__cvta_generic_to_shared(&Kd[c*68+d4]),
                 g_rk + (size_t)(cb*64+c)*128 + hk*64 + d4);
            cp16((unsigned)__cvta_generic_to_shared(&Vd[c*64+d4]),
                 g_qkv + (size_t)(cb*64+c)*QKVW + 1152 + hk*64 + d4);
        }
        cp_commit();
    };

    float m[4], Z[4]; float2 a[4];
    #pragma unroll
    for (int q = 0; q < 4; q++){ m[q]=NEGF; Z[q]=0.f; a[q]=make_float2(0.f,0.f); }
    int q0 = w*4;

    issue(0, 0);
    for (int t = 0; t < nb; t++){
        if (t + 1 < nb) issue(t+1, (t+1)&1);
        if (t + 1 < nb) cp_wait<1>(); else cp_wait<0>();
        __syncthreads();
        int cb = cb0 + t;
        float* Kd = Kb + (t&1)*4352;
        float* Vd = Vb + (t&1)*4096;

        float2 s[4];
        #pragma unroll
        for (int q = 0; q < 4; q++) s[q] = make_float2(0.f,0.f);
        #pragma unroll
        for (int d4 = 0; d4 < 64; d4 += 4){
            float4 k0 = *(const float4*)&Kd[l*68+d4];
            float4 k1 = *(const float4*)&Kd[(l+32)*68+d4];
            #pragma unroll
            for (int q = 0; q < 4; q++){
                float4 qv = *(const float4*)&SQ[(q0+q)*64+d4];
                s[q].x += qv.x*k0.x + qv.y*k0.y + qv.z*k0.z + qv.w*k0.w;
                s[q].y += qv.x*k1.x + qv.y*k1.y + qv.z*k1.z + qv.w*k1.w;
            }
        }
        int k0p = cb*64 + l, k1p = k0p + 32;
        #pragma unroll
        for (int q = 0; q < 4; q++){
            int i = i0 + q0 + q;
            bool v0 = (k0p <= i) && (i - k0p <= 512);
            bool v1 = (k1p <= i) && (i - k1p <= 512);
            float sx = v0 ? s[q].x*0.125f : NEGF;
            float sy = v1 ? s[q].y*0.125f : NEGF;
            float mn = fmaxf(m[q], wmax(fmaxf(sx, sy)));
            float e = expf(m[q] - mn);
            float p0 = v0 ? expf(sx - mn) : 0.f;
            float p1 = v1 ? expf(sy - mn) : 0.f;
            SP[(q0+q)*64+l] = p0; SP[(q0+q)*64+l+32] = p1;
            Z[q] = Z[q]*e + wsum(p0 + p1);
            a[q].x *= e; a[q].y *= e;
            m[q] = mn;
        }
        __syncwarp();
        int dl = 2*l;
        #pragma unroll
        for (int c4 = 0; c4 < 64; c4 += 4){
            float2 vv0 = *(const float2*)&Vd[(c4+0)*64+dl];
            float2 vv1 = *(const float2*)&Vd[(c4+1)*64+dl];
            float2 vv2 = *(const float2*)&Vd[(c4+2)*64+dl];
            float2 vv3 = *(const float2*)&Vd[(c4+3)*64+dl];
            #pragma unroll
            for (int q = 0; q < 4; q++){
                float4 pg = *(const float4*)&SP[(q0+q)*64+c4];
                a[q].x += pg.x*vv0.x + pg.y*vv1.x + pg.z*vv2.x + pg.w*vv3.x;
                a[q].y += pg.x*vv0.y + pg.y*vv1.y + pg.z*vv2.y + pg.w*vv3.y;
            }
        }
        __syncthreads();
    }
    #pragma unroll
    for (int q = 0; q < 4; q++){
        int i = i0 + q0 + q;
        *(float2*)&g_sout[(size_t)i*DIMM + hq*64 + 2*l] = make_float2(a[q].x/Z[q], a[q].y/Z[q]);
    }
}

// ---------------- gated combination ----------------
__global__ void combine_kernel(){
    int idx = blockIdx.x*256 + threadIdx.x;
    int i = idx>>10, e = idx & 1023;
    int hh = e>>6;
    const float* gt = g_gate + i*48 + hh*3;
    g_comb[idx] = gt[0]*g_cout[idx] + gt[1]*g_fout[idx] + gt[2]*g_sout[idx];
}

extern "C" void kernel_launch(void* const* d_in, const int* in_sizes, int n_in,
                              void* d_out, int out_size){
    const float* x      = (const float*)d_in[0];
    const float* rms_g  = (const float*)d_in[1];
    const float* W_qkv  = (const float*)d_in[2];
    const float* k_pos  = (const float*)d_in[3];
    const float* v_pos  = (const float*)d_in[4];
    const float* mem_kv = (const float*)d_in[5];
    const float* kW1    = (const float*)d_in[6];
    const float* kb1    = (const float*)d_in[7];
    const float* kW2    = (const float*)d_in[8];
    const float* kb2    = (const float*)d_in[9];
    const float* vW1    = (const float*)d_in[10];
    const float* vb1    = (const float*)d_in[11];
    const float* vW2    = (const float*)d_in[12];
    const float* vb2    = (const float*)d_in[13];
    const float* W_comb = (const float*)d_in[14];
    const float* b_comb = (const float*)d_in[15];
    const float* W_out  = (const float*)d_in[16];
    float* out = (float*)d_out;

    float *p_xn, *p_qkv, *p_gate, *p_comb, *p_gp;
    cudaGetSymbolAddress((void**)&p_xn,   g_xn);
    cudaGetSymbolAddress((void**)&p_qkv,  g_qkv);
    cudaGetSymbolAddress((void**)&p_gate, g_gate);
    cudaGetSymbolAddress((void**)&p_comb, g_comb);
    cudaGetSymbolAddress((void**)&p_gp,   g_gp);

    const int GEMM_SMEM  = 2*GSTG*4;
    const int MLP1_SMEM  = 2*MSTG*4;
    const int FINE_SMEM  = 17920*4;
    const int SLIDE_SMEM = 18944*4;
    cudaFuncSetAttribute(tf32gemm_kernel,  cudaFuncAttributeMaxDynamicSharedMemorySize, GEMM_SMEM);
    cudaFuncSetAttribute(mlp1_tf32_kernel, cudaFuncAttributeMaxDynamicSharedMemorySize, MLP1_SMEM);
    cudaFuncSetAttribute(fine_attn_kernel, cudaFuncAttributeMaxDynamicSharedMemorySize, FINE_SMEM);
    cudaFuncSetAttribute(slide_kernel,     cudaFuncAttributeMaxDynamicSharedMemorySize, SLIDE_SMEM);

    rmsnorm_kernel<<<SEQ, 256>>>(x, rms_g);
    tf32gemm_kernel<<<dim3(10, 16, 2), 256, GEMM_SMEM>>>(p_xn, W_qkv, p_gp, SEQ, QKVW, DIMM, 512);
    add2_kernel<<<(SEQ*QKVW + 255)/256, 256>>>(p_gp, p_qkv, SEQ*QKVW);
    build_comp_kernel<<<2048, 256>>>(k_pos, v_pos);
    mlp1_tf32_kernel<<<dim3(32, 2, 4), 256, MLP1_SMEM>>>(kW1, vW1);
    mlp1red_kernel<<<2048, 256>>>(kb1, vb1);
    init_ck_kernel<<<1, 256>>>(mem_kv);
    mlp2_kernel<<<dim3(64, 2), 256>>>(kW2, kb2, vW2, vb2);
    comp_attn_kernel<<<dim3(SEQ, 2), 256>>>();
    rope_kernel<<<(SEQ*576 + 255)/256, 256>>>();
    fine_attn_kernel<<<dim3(SEQ, 2), 128, FINE_SMEM>>>();
    slide_kernel<<<dim3(128, 16), 128, SLIDE_SMEM>>>();
    sgemm_kernel<<<dim3(1, 32), 256>>>(p_xn, W_comb, b_comb, p_gate, SEQ, 48, DIMM, 3);
    combine_kernel<<<8192, 256>>>();
    tf32gemm_kernel<<<dim3(8, 16, 2), 256, GEMM_SMEM>>>(p_comb, W_out, p_gp, SEQ, DIMM, DIMM, 512);
    add2_kernel<<<(SEQ*DIMM + 255)/256, 256>>>(p_gp, out, SEQ*DIMM);
}

// round 13
// speedup vs baseline: 1.4373x; 1.0041x over previous
#include <cuda_runtime.h>
#include <math.h>

#define SEQ   2048
#define DIMM  1024
#define QKVW  1280
#define NEGF  (-3.402823466e38f)

// ---------------- scratch (static device globals) ----------------
__device__ __align__(16) float g_xn  [SEQ*DIMM];
__device__ __align__(16) float g_qkv [SEQ*QKVW];
__device__ __align__(16) float g_rq  [SEQ*DIMM];
__device__ __align__(16) float g_rk  [SEQ*128];
__device__ __align__(16) float g_cin [2*64*4096];
__device__ __align__(16) float g_hidp[4*2*64*4096];
__device__ __align__(16) float g_hid [2*64*4096];
__device__ __align__(16) float g_gp  [2*SEQ*QKVW];
__device__ __align__(16) float g_ck  [2*33*64];
__device__ __align__(16) float g_cv  [2*33*64];
__device__ __align__(16) float g_cout[SEQ*DIMM];
__device__ __align__(16) float g_fout[SEQ*DIMM];
__device__ __align__(16) float g_sout[SEQ*DIMM];
__device__ __align__(16) float g_gate[SEQ*48];
__device__ __align__(16) float g_comb[SEQ*DIMM];
__device__            int   g_sel [2*SEQ*9];

__device__ __forceinline__ float wmax(float v){
    #pragma unroll
    for (int o=16;o;o>>=1) v = fmaxf(v, __shfl_xor_sync(0xffffffffu, v, o));
    return v;
}
__device__ __forceinline__ float wsum(float v){
    #pragma unroll
    for (int o=16;o;o>>=1) v += __shfl_xor_sync(0xffffffffu, v, o);
    return v;
}

// ---------------- cp.async helpers ----------------
__device__ __forceinline__ void cp16(unsigned dst, const void* src){
    asm volatile("cp.async.cg.shared.global [%0], [%1], 16;" :: "r"(dst), "l"(src));
}
__device__ __forceinline__ void cp_commit(){ asm volatile("cp.async.commit_group;"); }
template<int N> __device__ __forceinline__ void cp_wait(){
    asm volatile("cp.async.wait_group %0;" :: "n"(N));
}

// ---------------- tf32 helpers ----------------
__device__ __forceinline__ void tf32_split(float f, unsigned& hi, unsigned& lo){
    asm("cvt.rna.tf32.f32 %0, %1;" : "=r"(hi) : "f"(f));
    float rem = f - __uint_as_float(hi);
    asm("cvt.rna.tf32.f32 %0, %1;" : "=r"(lo) : "f"(rem));
}
__device__ __forceinline__ void mma_tf32(float* c, const unsigned* a, const unsigned* b){
    asm volatile(
        "mma.sync.aligned.m16n8k8.row.col.f32.tf32.tf32.f32 "
        "{%0,%1,%2,%3},{%4,%5,%6,%7},{%8,%9},{%0,%1,%2,%3};"
        : "+f"(c[0]), "+f"(c[1]), "+f"(c[2]), "+f"(c[3])
        : "r"(a[0]), "r"(a[1]), "r"(a[2]), "r"(a[3]), "r"(b[0]), "r"(b[1]));
}
__device__ __forceinline__ void ldsm4(unsigned* r, unsigned addr){
    asm volatile("ldmatrix.sync.aligned.m8n8.x4.shared.b16 {%0,%1,%2,%3}, [%4];"
        : "=r"(r[0]), "=r"(r[1]), "=r"(r[2]), "=r"(r[3]) : "r"(addr));
}

// ---------------- RMSNorm ----------------
__global__ void rmsnorm_kernel(const float* __restrict__ x, const float* __restrict__ g){
    int s = blockIdx.x, tid = threadIdx.x;
    const float* xr = x + (size_t)s*DIMM;
    __shared__ float red[256];
    float ss = 0.f;
    for (int i = tid; i < DIMM; i += 256){ float v = xr[i]; ss += v*v; }
    red[tid] = ss; __syncthreads();
    for (int st = 128; st > 0; st >>= 1){ if (tid < st) red[tid] += red[tid+st]; __syncthreads(); }
    float sc = rsqrtf(red[0]*(1.f/DIMM) + 1.1920929e-7f);
    for (int i = tid; i < DIMM; i += 256) g_xn[(size_t)s*DIMM+i] = xr[i]*sc*g[i];
}

// ---------------- tf32x3 GEMM, double-buffered + split-K: BM=128,BN=128,BK=16 ----------------
#define GSTG 9344
__global__ __launch_bounds__(256,2) void tf32gemm_kernel(
        const float* __restrict__ A, const float* __restrict__ B,
        float* __restrict__ Cp, int M, int N, int K, int Kc){
    extern __shared__ unsigned dsm[];
    int tid = threadIdx.x, lane = tid&31, wid = tid>>5;
    int m0b = blockIdx.y*128, n0b = blockIdx.x*128;
    int kbase = blockIdx.z*Kc;
    int mw = (wid>>2)*64, nw = (wid&3)*32;
    int r = lane>>2, c = lane&3;
    float acc[4][4][4] = {};
    int la_m = tid>>2, la_k = (tid&3)*4;
    int lb_r = tid>>5, lb_n = (tid&31)*4;
    int sub = lane>>3, e = lane&7;
    int a_row = mw + ((sub&1)<<3) + e;
    int a_col = (sub>>1)<<2;
    unsigned sm_base = (unsigned)__cvta_generic_to_shared(dsm);

    float4 pa0 = *(const float4*)(A + (size_t)(m0b+la_m)*K + kbase + la_k);
    float4 pa1 = *(const float4*)(A + (size_t)(m0b+la_m+64)*K + kbase + la_k);
    float4 pb0 = *(const float4*)(B + (size_t)(kbase+lb_r)*N + n0b + lb_n);
    float4 pb1 = *(const float4*)(B + (size_t)(kbase+lb_r+8)*N + n0b + lb_n);

    {
        unsigned* Ah = dsm; unsigned* Al = dsm + 2560; unsigned* Bhl = dsm + 5120;
        float fa0[4]={pa0.x,pa0.y,pa0.z,pa0.w}, fa1[4]={pa1.x,pa1.y,pa1.z,pa1.w};
        #pragma unroll
        for (int u = 0; u < 4; u++){
            unsigned hi, lo;
            tf32_split(fa0[u], hi, lo); Ah[la_m*20 + la_k+u] = hi;      Al[la_m*20 + la_k+u] = lo;
            tf32_split(fa1[u], hi, lo); Ah[(la_m+64)*20 + la_k+u] = hi; Al[(la_m+64)*20 + la_k+u] = lo;
        }
        unsigned h0,l0,h1,l1,h2,l2,h3,l3;
        tf32_split(pb0.x,h0,l0); tf32_split(pb0.y,h1,l1);
        tf32_split(pb0.z,h2,l2); tf32_split(pb0.w,h3,l3);
        *(uint4*)&Bhl[lb_r*264 + lb_n*2]     = make_uint4(h0,l0,h1,l1);
        *(uint4*)&Bhl[lb_r*264 + lb_n*2 + 4] = make_uint4(h2,l2,h3,l3);
        tf32_split(pb1.x,h0,l0); tf32_split(pb1.y,h1,l1);
        tf32_split(pb1.z,h2,l2); tf32_split(pb1.w,h3,l3);
        *(uint4*)&Bhl[(lb_r+8)*264 + lb_n*2]     = make_uint4(h0,l0,h1,l1);
        *(uint4*)&Bhl[(lb_r+8)*264 + lb_n*2 + 4] = make_uint4(h2,l2,h3,l3);
    }
    if (16 < Kc){
        pa0 = *(const float4*)(A + (size_t)(m0b+la_m)*K + kbase + 16 + la_k);
        pa1 = *(const float4*)(A + (size_t)(m0b+la_m+64)*K + kbase + 16 + la_k);
        pb0 = *(const float4*)(B + (size_t)(kbase+16+lb_r)*N + n0b + lb_n);
        pb1 = *(const float4*)(B + (size_t)(kbase+16+lb_r+8)*N + n0b + lb_n);
    }
    __syncthreads();

    int cur = 0;
    for (int k0 = 0; k0 < Kc; k0 += 16){
        {
            unsigned stg = cur*GSTG;
            unsigned* Bhl = dsm + stg + 5120;
            #pragma unroll
            for (int ks = 0; ks < 2; ks++){
                int kk = ks*8;
                unsigned ah[4][4], al[4][4];
                #pragma unroll
                for (int t = 0; t < 4; t++){
                    unsigned offh = sm_base + (stg + (a_row + t*16)*20 + kk + a_col)*4u;
                    ldsm4(ah[t], offh);
                    ldsm4(al[t], offh + 2560*4u);
                }
                #pragma unroll
                for (int j = 0; j < 4; j++){
                    int nc = nw + j*8 + r;
                    uint2 b0 = *(const uint2*)&Bhl[(kk+c)*264 + nc*2];
                    uint2 b1 = *(const uint2*)&Bhl[(kk+c+4)*264 + nc*2];
                    unsigned bh[2] = { b0.x, b1.x };
                    unsigned bl[2] = { b0.y, b1.y };
                    #pragma unroll
                    for (int t = 0; t < 4; t++){
                        mma_tf32(acc[t][j], ah[t], bh);
                        mma_tf32(acc[t][j], ah[t], bl);
                        mma_tf32(acc[t][j], al[t], bh);
                    }
                }
            }
        }
        if (k0 + 16 < Kc){
            unsigned nstg = (cur^1)*GSTG;
            unsigned* Ah = dsm + nstg; unsigned* Al = dsm + nstg + 2560; unsigned* Bhl = dsm + nstg + 5120;
            float fa0[4]={pa0.x,pa0.y,pa0.z,pa0.w}, fa1[4]={pa1.x,pa1.y,pa1.z,pa1.w};
            #pragma unroll
            for (int u = 0; u < 4; u++){
                unsigned hi, lo;
                tf32_split(fa0[u], hi, lo); Ah[la_m*20 + la_k+u] = hi;      Al[la_m*20 + la_k+u] = lo;
                tf32_split(fa1[u], hi, lo); Ah[(la_m+64)*20 + la_k+u] = hi; Al[(la_m+64)*20 + la_k+u] = lo;
            }
            unsigned h0,l0,h1,l1,h2,l2,h3,l3;
            tf32_split(pb0.x,h0,l0); tf32_split(pb0.y,h1,l1);
            tf32_split(pb0.z,h2,l2); tf32_split(pb0.w,h3,l3);
            *(uint4*)&Bhl[lb_r*264 + lb_n*2]     = make_uint4(h0,l0,h1,l1);
            *(uint4*)&Bhl[lb_r*264 + lb_n*2 + 4] = make_uint4(h2,l2,h3,l3);
            tf32_split(pb1.x,h0,l0); tf32_split(pb1.y,h1,l1);
            tf32_split(pb1.z,h2,l2); tf32_split(pb1.w,h3,l3);
            *(uint4*)&Bhl[(lb_r+8)*264 + lb_n*2]     = make_uint4(h0,l0,h1,l1);
            *(uint4*)&Bhl[(lb_r+8)*264 + lb_n*2 + 4] = make_uint4(h2,l2,h3,l3);
        }
        if (k0 + 32 < Kc){
            pa0 = *(const float4*)(A + (size_t)(m0b+la_m)*K + kbase + k0+32 + la_k);
            pa1 = *(const float4*)(A + (size_t)(m0b+la_m+64)*K + kbase + k0+32 + la_k);
            pb0 = *(const float4*)(B + (size_t)(kbase+k0+32+lb_r)*N + n0b + lb_n);
            pb1 = *(const float4*)(B + (size_t)(kbase+k0+32+lb_r+8)*N + n0b + lb_n);
        }
        __syncthreads();
        cur ^= 1;
    }
    float* O = Cp + (size_t)blockIdx.z*M*N;
    #pragma unroll
    for (int t = 0; t < 4; t++)
        #pragma unroll
        for (int j = 0; j < 4; j++){
            int row = m0b + mw + t*16 + r;
            int col = n0b + nw + j*8 + c*2;
            O[(size_t)row*N + col]       = acc[t][j][0];
            O[(size_t)row*N + col+1]     = acc[t][j][1];
            O[(size_t)(row+8)*N + col]   = acc[t][j][2];
            O[(size_t)(row+8)*N + col+1] = acc[t][j][3];
        }
}

// partial sum: out[i] = p[i] + p[i+n]
__global__ void add2_kernel(const float* __restrict__ p, float* __restrict__ out, int n){
    int idx = blockIdx.x*256 + threadIdx.x;
    if (idx < n) out[idx] = p[idx] + p[idx + n];
}

// ---------------- MLP1 tf32x3 split-K, double-buffered: BM=64,BN=128 ----------------
#define MSTG 6784
__global__ __launch_bounds__(256,2) void mlp1_tf32_kernel(
        const float* __restrict__ kW1, const float* __restrict__ vW1){
    extern __shared__ unsigned dsm[];
    int tid = threadIdx.x, lane = tid&31, wid = tid>>5;
    int mat = blockIdx.y, kc = blockIdx.z;
    const float* A = g_cin + (size_t)mat*262144;
    const float* B = (mat ? vW1 : kW1);
    int n0b = blockIdx.x*128, kbase = kc*1024;
    int mw = (wid>>2)*32, nw = (wid&3)*32;
    int r = lane>>2, c = lane&3;
    float acc[2][4][4] = {};
    int fa_k = tid&15, fa_m = tid>>4;
    int fb_n = tid&127, fb_r = tid>>7;
    int sub = lane>>3, e = lane&7;
    int a_row = mw + ((sub&1)<<3) + e;
    int a_col = (sub>>1)<<2;
    unsigned sm_base = (unsigned)__cvta_generic_to_shared(dsm);

    float pa[4], pb[8];
    #pragma unroll
    for (int p = 0; p < 4; p++)
        pa[p] = A[(size_t)(fa_m + 16*p)*4096 + kbase + fa_k];
    #pragma unroll
    for (int p = 0; p < 8; p++)
        pb[p] = B[(size_t)(kbase + fb_r + 2*p)*4096 + n0b + fb_n];

    {
        unsigned* Ah = dsm; unsigned* Al = dsm + 1280; unsigned* Bhl = dsm + 2560;
        #pragma unroll
        for (int p = 0; p < 4; p++){
            unsigned hi, lo;
            tf32_split(pa[p], hi, lo);
            Ah[(fa_m + 16*p)*20 + fa_k] = hi;
            Al[(fa_m + 16*p)*20 + fa_k] = lo;
        }
        #pragma unroll
        for (int p = 0; p < 8; p++){
            unsigned hi, lo;
            tf32_split(pb[p], hi, lo);
            *(uint2*)&Bhl[(fb_r + 2*p)*264 + fb_n*2] = make_uint2(hi, lo);
        }
    }
    {
        #pragma unroll
        for (int p = 0; p < 4; p++)
            pa[p] = A[(size_t)(fa_m + 16*p)*4096 + kbase + 16 + fa_k];
        #pragma unroll
        for (int p = 0; p < 8; p++)
            pb[p] = B[(size_t)(kbase + 16 + fb_r + 2*p)*4096 + n0b + fb_n];
    }
    __syncthreads();

    int cur = 0;
    for (int k0 = 0; k0 < 1024; k0 += 16){
        {
            unsigned stg = cur*MSTG;
            unsigned* Bhl = dsm + stg + 2560;
            #pragma unroll
            for (int ks = 0; ks < 2; ks++){
                int kk = ks*8;
                unsigned ah[2][4], al[2][4];
                #pragma unroll
                for (int t = 0; t < 2; t++){
                    unsigned offh = sm_base + (stg + (a_row + t*16)*20 + kk + a_col)*4u;
                    ldsm4(ah[t], offh);
                    ldsm4(al[t], offh + 1280*4u);
                }
                #pragma unroll
                for (int j = 0; j < 4; j++){
                    int nc = nw + j*8 + r;
                    uint2 b0 = *(const uint2*)&Bhl[(kk+c)*264 + nc*2];
                    uint2 b1 = *(const uint2*)&Bhl[(kk+c+4)*264 + nc*2];
                    unsigned bh[2] = { b0.x, b1.x };
                    unsigned bl[2] = { b0.y, b1.y };
                    #pragma unroll
                    for (int t = 0; t < 2; t++){
                        mma_tf32(acc[t][j], ah[t], bh);
                        mma_tf32(acc[t][j], ah[t], bl);
                        mma_tf32(acc[t][j], al[t], bh);
                    }
                }
            }
        }
        if (k0 + 16 < 1024){
            unsigned nstg = (cur^1)*MSTG;
            unsigned* Ah = dsm + nstg; unsigned* Al = dsm + nstg + 1280; unsigned* Bhl = dsm + nstg + 2560;
            #pragma unroll
            for (int p = 0; p < 4; p++){
                unsigned hi, lo;
                tf32_split(pa[p], hi, lo);
                Ah[(fa_m + 16*p)*20 + fa_k] = hi;
                Al[(fa_m + 16*p)*20 + fa_k] = lo;
            }
            #pragma unroll
            for (int p = 0; p < 8; p++){
                unsigned hi, lo;
                tf32_split(pb[p], hi, lo);
                *(uint2*)&Bhl[(fb_r + 2*p)*264 + fb_n*2] = make_uint2(hi, lo);
            }
        }
        if (k0 + 32 < 1024){
            #pragma unroll
            for (int p = 0; p < 4; p++)
                pa[p] = A[(size_t)(fa_m + 16*p)*4096 + kbase + k0 + 32 + fa_k];
            #pragma unroll
            for (int p = 0; p < 8; p++)
                pb[p] = B[(size_t)(kbase + k0 + 32 + fb_r + 2*p)*4096 + n0b + fb_n];
        }
        __syncthreads();
        cur ^= 1;
    }
    float* O = g_hidp + (size_t)(kc*2+mat)*64*4096;
    #pragma unroll
    for (int t = 0; t < 2; t++)
        #pragma unroll
        for (int j = 0; j < 4; j++){
            int row = mw + t*16 + r;
            int col = n0b + nw + j*8 + c*2;
            O[(size_t)row*4096 + col]       = acc[t][j][0];
            O[(size_t)row*4096 + col+1]     = acc[t][j][1];
            O[(size_t)(row+8)*4096 + col]   = acc[t][j][2];
            O[(size_t)(row+8)*4096 + col+1] = acc[t][j][3];
        }
}

// ---------------- small SGEMM (gates) ----------------
__global__ void sgemm_kernel(const float* __restrict__ A, const float* __restrict__ B,
                             const float* __restrict__ bias, float* __restrict__ C,
                             int M, int N, int K, int epi){
    __shared__ __align__(16) float As[16][72];
    __shared__ __align__(16) float Bs[16][72];
    int tid = threadIdx.x;
    int tr = tid>>4, tc = tid&15;
    int m0 = blockIdx.y*64, n0 = blockIdx.x*64;
    int lm = tid>>2, lk4 = (tid&3)*4;
    int lkb = tid>>4, ln4 = (tid&15)*4;
    float acc[4][4] = {};
    for (int k0 = 0; k0 < K; k0 += 16){
        float4 a4 = *(const float4*)(A + (size_t)(m0+lm)*K + k0 + lk4);
        As[lk4+0][lm]=a4.x; As[lk4+1][lm]=a4.y; As[lk4+2][lm]=a4.z; As[lk4+3][lm]=a4.w;
        if (n0+ln4+3 < N){
            *(float4*)&Bs[lkb][ln4] = *(const float4*)(B + (size_t)(k0+lkb)*N + n0 + ln4);
        } else {
            #pragma unroll
            for (int u=0;u<4;u++)
                Bs[lkb][ln4+u] = (n0+ln4+u < N) ? B[(size_t)(k0+lkb)*N + n0+ln4+u] : 0.f;
        }
        __syncthreads();
        #pragma unroll
        for (int kk=0; kk<16; kk++){
            float4 a = *(const float4*)&As[kk][tr*4];
            float4 b = *(const float4*)&Bs[kk][tc*4];
            float av[4]={a.x,a.y,a.z,a.w}, bv[4]={b.x,b.y,b.z,b.w};
            #pragma unroll
            for (int i=0;i<4;i++)
                #pragma unroll
                for (int j=0;j<4;j++) acc[i][j] += av[i]*bv[j];
        }
        __syncthreads();
    }
    #pragma unroll
    for (int i=0;i<4;i++){
        int row = m0 + tr*4 + i;
        #pragma unroll
        for (int j=0;j<4;j++){
            int col = n0 + tc*4 + j;
            if (col < N){
                float v = acc[i][j];
                if (epi >= 1) v += bias[col];
                if (epi == 3) v = 1.f/(1.f + expf(-v));
                C[(size_t)row*N + col] = v;
            }
        }
    }
}

// ---------------- build compression MLP input [2][64][4096] ----------------
__global__ void build_comp_kernel(const float* __restrict__ k_pos, const float* __restrict__ v_pos){
    int idx = blockIdx.x*256 + threadIdx.x;
    int mat = idx>>18, rem = idx & 262143;
    int r = rem>>12, i = rem & 4095;
    int h = r>>5, w = r&31;
    int c = i>>6, d = i&63;
    int s = w*64 + c;
    const float* pos = mat ? v_pos : k_pos;
    int off = mat ? (DIMM + 128) : DIMM;
    g_cin[idx] = g_qkv[(size_t)s*QKVW + off + h*64 + d] + pos[(h*64+c)*64 + d];
}

__global__ void mlp1red_kernel(const float* __restrict__ kb1, const float* __restrict__ vb1){
    int idx = blockIdx.x*256 + threadIdx.x;
    int mat = idx>>18, n = idx & 4095;
    float s = g_hidp[idx] + g_hidp[idx+524288] + g_hidp[idx+1048576] + g_hidp[idx+1572864];
    s += (mat ? vb1 : kb1)[n];
    g_hid[idx] = fmaxf(s, 0.f);
}

// ---------------- mem token init ----------------
__global__ void init_ck_kernel(const float* __restrict__ mem_kv){
    int t = threadIdx.x;
    int mat = t>>7, h = (t>>6)&1, d = t&63;
    float* out = mat ? g_cv : g_ck;
    out[h*33*64 + d] = mem_kv[(mat*2+h)*64 + d];
}

// ---------------- MLP layer2 ----------------
__global__ void mlp2_kernel(const float* __restrict__ kW2, const float* __restrict__ kb2,
                            const float* __restrict__ vW2, const float* __restrict__ vb2){
    int r = blockIdx.x, mat = blockIdx.y, tid = threadIdx.x;
    int d = tid&63, kq = tid>>6;
    const float* H = g_hid + (size_t)(mat*64+r)*4096;
    const float* W = mat ? vW2 : kW2;
    const float* b = mat ? vb2 : kb2;
    float acc = 0.f;
    int kend = kq*1024 + 1024;
    for (int k = kq*1024; k < kend; k++) acc += H[k]*W[(size_t)k*64 + d];
    __shared__ float red[4][64];
    red[kq][d] = acc; __syncthreads();
    if (kq == 0){
        float s = red[0][d]+red[1][d]+red[2][d]+red[3][d] + b[d];
        int h = r>>5, w = r&31;
        float* out = mat ? g_cv : g_ck;
        out[(h*33 + 1 + w)*64 + d] = s;
    }
}

// ---------------- compressed attention + selection ----------------
__global__ void comp_attn_kernel(){
    int i = blockIdx.x, h = blockIdx.y, tid = threadIdx.x;
    __shared__ float sq[512];
    __shared__ float sk[33*65];
    __shared__ float sv[33*65];
    __shared__ float L[264], P[264], Zr[8];
    for (int o = tid; o < 512; o += 256) sq[o] = g_qkv[(size_t)i*QKVW + h*512 + o];
    for (int o = tid; o < 33*64; o += 256){
        int j = o>>6, d = o&63;
        sk[j*65+d] = g_ck[h*2112 + o];
        sv[j*65+d] = g_cv[h*2112 + o];
    }
    __syncthreads();
    for (int o = tid; o < 264; o += 256){
        int g = o/33, j = o - g*33;
        bool vis = (j == 0) || (j*64 - 1 < i);
        float a = NEGF;
        if (vis){
            float s = 0.f;
            #pragma unroll 8
            for (int d = 0; d < 64; d++) s += sq[g*64+d]*sk[j*65+d];
            a = s*0.125f;
        }
        L[o] = a;
    }
    __syncthreads();
    if (tid < 8){
        int g = tid;
        float m = NEGF;
        for (int j = 0; j < 33; j++) m = fmaxf(m, L[g*33+j]);
        float z = 0.f;
        for (int j = 0; j < 33; j++){
            float l = L[g*33+j];
            float p = (l < -1e30f) ? 0.f : expf(l - m);
            P[g*33+j] = p; z += p;
        }
        Zr[g] = z;
    }
    if (tid == 32){
        float pr[32], im[32]; float M = -1000.f;
        for (int j = 0; j < 32; j++){
            float s = 0.f;
            for (int g = 0; g < 8; g++) s += L[g*33 + j + 1];
            im[j] = s*0.125f;
            M = fmaxf(M, im[j]);
        }
        float Zs = expf(-1000.f - M);
        for (int j = 0; j < 32; j++){
            float p = (im[j] < -1e30f) ? 0.f : expf(im[j] - M);
            pr[j] = p; Zs += p;
        }
        bool taken[32];
        for (int j = 0; j < 32; j++) taken[j] = false;
        int base = (h*SEQ + i)*9;
        for (int t = 0; t < 8; t++){
            int best = -1; float bv = -1.f;
            for (int j = 0; j < 32; j++)
                if (!taken[j] && pr[j] > bv){ bv = pr[j]; best = j; }
            if (best >= 0 && bv/Zs > 1e-10f){ taken[best] = true; g_sel[base+t] = best; }
            else g_sel[base+t] = -1;
        }
        g_sel[base+8] = i>>6;
    }
    __syncthreads();
    for (int o = tid; o < 512; o += 256){
        int g = o>>6, d = o&63;
        float a = 0.f;
        for (int j = 0; j < 33; j++) a += P[g*33+j]*sv[j*65+d];
        g_cout[(size_t)i*DIMM + h*512 + o] = a/Zr[g];
    }
}

// ---------------- RoPE on q and k ----------------
__global__ void rope_kernel(){
    int idx = blockIdx.x*256 + threadIdx.x;
    if (idx >= SEQ*576) return;
    int s = idx/576, e = idx - s*576;
    float pos = (float)s;
    if (e < 512){
        int p = e & 31;
        float ang = pos*exp2f(-(float)p*0.41524101186092033f);
        float c = cosf(ang), si = sinf(ang);
        const float* b = g_qkv + (size_t)s*QKVW + e*2;
        float u0 = b[0], u1 = b[1];
        g_rq[(size_t)s*DIMM + e*2]   = u0*c - u1*si;
        g_rq[(size_t)s*DIMM + e*2+1] = u1*c + u0*si;
    } else {
        int e2 = e - 512, p = e2 & 31;
        float ang = pos*exp2f(-(float)p*0.41524101186092033f);
        float c = cosf(ang), si = sinf(ang);
        const float* b = g_qkv + (size_t)s*QKVW + DIMM + e2*2;
        float u0 = b[0], u1 = b[1];
        g_rk[(size_t)s*128 + e2*2]   = u0*c - u1*si;
        g_rk[(size_t)s*128 + e2*2+1] = u1*c + u0*si;
    }
}

// ---------------- fine attention: cp.async double-buffered tiles ----------------
__global__ void fine_attn_kernel(){
    extern __shared__ float fsm[];
    float* Kb = fsm;
    float* Vb = fsm + 8704;
    float* SQ = fsm + 16896;
    float* SP = fsm + 17408;
    int i = blockIdx.x, h = blockIdx.y, tid = threadIdx.x;
    int w = tid>>5, l = tid&31;
    int base = (h*SEQ + i)*9;
    int blks[9]; bool dg[9]; int nb = 0;
    #pragma unroll
    for (int slot = 0; slot < 9; slot++){
        int blk = (slot < 8) ? g_sel[base+slot] : (i>>6);
        if (blk >= 0){ blks[nb] = blk; dg[nb] = (slot == 8); nb++; }
    }
    for (int o = tid; o < 512; o += 128) SQ[o] = g_rq[(size_t)i*DIMM + h*512 + o];

    auto issue = [&](int t, int stg){
        int blk = blks[t];
        float* Kd = Kb + stg*4352;
        float* Vd = Vb + stg*4096;
        #pragma unroll
        for (int o = tid; o < 1024; o += 128){
            int c = o>>4, d4 = (o&15)*4;
            cp16((unsigned)__cvta_generic_to_shared(&Kd[c*68+d4]),
                 g_rk + (size_t)(blk*64+c)*128 + h*64 + d4);
            cp16((unsigned)__cvta_generic_to_shared(&Vd[c*64+d4]),
                 g_qkv + (size_t)(blk*64+c)*QKVW + 1152 + h*64 + d4);
        }
        cp_commit();
    };

    int g0 = w*2, g1 = w*2+1;
    float m0=NEGF, m1=NEGF, Z0=0.f, Z1=0.f;
    float2 a0 = make_float2(0.f,0.f), a1 = make_float2(0.f,0.f);
    int lim = i & 63;

    issue(0, 0);
    for (int t = 0; t < nb; t++){
        if (t + 1 < nb) issue(t+1, (t+1)&1);
        if (t + 1 < nb) cp_wait<1>(); else cp_wait<0>();
        __syncthreads();
        float* Kd = Kb + (t&1)*4352;
        float* Vd = Vb + (t&1)*4096;
        bool isdg = dg[t];

        float2 s0 = make_float2(0.f,0.f), s1 = make_float2(0.f,0.f);
        #pragma unroll
        for (int d4 = 0; d4 < 64; d4 += 4){
            float4 k0 = *(const float4*)&Kd[l*68+d4];
            float4 k1 = *(const float4*)&Kd[(l+32)*68+d4];
            float4 q0 = *(const float4*)&SQ[g0*64+d4];
            float4 q1 = *(const float4*)&SQ[g1*64+d4];
            s0.x += q0.x*k0.x + q0.y*k0.y + q0.z*k0.z + q0.w*k0.w;
            s0.y += q0.x*k1.x + q0.y*k1.y + q0.z*k1.z + q0.w*k1.w;
            s1.x += q1.x*k0.x + q1.y*k0.y + q1.z*k0.z + q1.w*k0.w;
            s1.y += q1.x*k1.x + q1.y*k1.y + q1.z*k1.z + q1.w*k1.w;
        }
        bool v0 = (!isdg) || (l <= lim);
        bool v1 = (!isdg) || (l+32 <= lim);
        float sa = v0 ? s0.x*0.125f : NEGF;
        float sb = v1 ? s0.y*0.125f : NEGF;
        float sc_ = v0 ? s1.x*0.125f : NEGF;
        float sd = v1 ? s1.y*0.125f : NEGF;
        float mn0 = fmaxf(m0, wmax(fmaxf(sa, sb)));
        float e0 = expf(m0 - mn0);
        float p00 = v0 ? expf(sa - mn0) : 0.f;
        float p01 = v1 ? expf(sb - mn0) : 0.f;
        SP[g0*64+l] = p00; SP[g0*64+l+32] = p01;
        Z0 = Z0*e0 + wsum(p00 + p01);
        a0.x *= e0; a0.y *= e0;
        float mn1 = fmaxf(m1, wmax(fmaxf(sc_, sd)));
        float e1 = expf(m1 - mn1);
        float p10 = v0 ? expf(sc_ - mn1) : 0.f;
        float p11 = v1 ? expf(sd - mn1) : 0.f;
        SP[g1*64+l] = p10; SP[g1*64+l+32] = p11;
        Z1 = Z1*e1 + wsum(p10 + p11);
        a1.x *= e1; a1.y *= e1;
        m0 = mn0; m1 = mn1;
        __syncwarp();
        int dl = 2*l;
        #pragma unroll
        for (int c4 = 0; c4 < 64; c4 += 4){
            float4 pg0 = *(const float4*)&SP[g0*64+c4];
            float4 pg1 = *(const float4*)&SP[g1*64+c4];
            float2 vv0 = *(const float2*)&Vd[(c4+0)*64+dl];
            float2 vv1 = *(const float2*)&Vd[(c4+1)*64+dl];
            float2 vv2 = *(const float2*)&Vd[(c4+2)*64+dl];
            float2 vv3 = *(const float2*)&Vd[(c4+3)*64+dl];
            a0.x += pg0.x*vv0.x + pg0.y*vv1.x + pg0.z*vv2.x + pg0.w*vv3.x;
            a0.y += pg0.x*vv0.y + pg0.y*vv1.y + pg0.z*vv2.y + pg0.w*vv3.y;
            a1.x += pg1.x*vv0.x + pg1.y*vv1.x + pg1.z*vv2.x + pg1.w*vv3.x;
            a1.y += pg1.x*vv0.y + pg1.y*vv1.y + pg1.z*vv2.y + pg1.w*vv3.y;
        }
        __syncthreads();
    }
    size_t ob = (size_t)i*DIMM + h*512;
    *(float2*)&g_fout[ob + g0*64 + 2*l] = make_float2(a0.x/Z0, a0.y/Z0);
    *(float2*)&g_fout[ob + g1*64 + 2*l] = make_float2(a1.x/Z1, a1.y/Z1);
}

// ---------------- sliding window: 256 thr, 8 warps x 4 q = 32 queries/block ----------------
// dyn smem (floats): K 2*64*68 @0, V 2*64*64 @8704, SQ 2048 @16896, SP 2048 @18944; total 20992
__global__ void slide_kernel(){
    extern __shared__ float ssm[];
    float* Kb = ssm;
    float* Vb = ssm + 8704;
    float* SQ = ssm + 16896;
    float* SP = ssm + 18944;
    int tid = threadIdx.x;
    int w = tid>>5, l = tid&31;
    int hq = blockIdx.y, hk = hq>>3;
    int i0 = blockIdx.x*32;
    for (int o = tid; o < 2048; o += 256){
        int qq = o>>6, d = o&63;
        SQ[o] = g_rq[(size_t)(i0+qq)*DIMM + hq*64 + d];
    }
    int cbtop = i0>>6;
    int cb0 = cbtop - 8; if (cb0 < 0) cb0 = 0;
    int nb = cbtop - cb0 + 1;

    auto issue = [&](int t, int stg){
        int cb = cb0 + t;
        float* Kd = Kb + stg*4352;
        float* Vd = Vb + stg*4096;
        #pragma unroll
        for (int o = tid; o < 1024; o += 256){
            int c = o>>4, d4 = (o&15)*4;
            cp16((unsigned)__cvta_generic_to_shared(&Kd[c*68+d4]),
                 g_rk + (size_t)(cb*64+c)*128 + hk*64 + d4);
            cp16((unsigned)__cvta_generic_to_shared(&Vd[c*64+d4]),
                 g_qkv + (size_t)(cb*64+c)*QKVW + 1152 + hk*64 + d4);
        }
        cp_commit();
    };

    float m[4], Z[4]; float2 a[4];
    #pragma unroll
    for (int q = 0; q < 4; q++){ m[q]=NEGF; Z[q]=0.f; a[q]=make_float2(0.f,0.f); }
    int q0 = w*4;

    issue(0, 0);
    for (int t = 0; t < nb; t++){
        if (t + 1 < nb) issue(t+1, (t+1)&1);
        if (t + 1 < nb) cp_wait<1>(); else cp_wait<0>();
        __syncthreads();
        int cb = cb0 + t;
        float* Kd = Kb + (t&1)*4352;
        float* Vd = Vb + (t&1)*4096;

        float2 s[4];
        #pragma unroll
        for (int q = 0; q < 4; q++) s[q] = make_float2(0.f,0.f);
        #pragma unroll
        for (int d4 = 0; d4 < 64; d4 += 4){
            float4 k0 = *(const float4*)&Kd[l*68+d4];
            float4 k1 = *(const float4*)&Kd[(l+32)*68+d4];
            #pragma unroll
            for (int q = 0; q < 4; q++){
                float4 qv = *(const float4*)&SQ[(q0+q)*64+d4];
                s[q].x += qv.x*k0.x + qv.y*k0.y + qv.z*k0.z + qv.w*k0.w;
                s[q].y += qv.x*k1.x + qv.y*k1.y + qv.z*k1.z + qv.w*k1.w;
            }
        }
        int k0p = cb*64 + l, k1p = k0p + 32;
        #pragma unroll
        for (int q = 0; q < 4; q++){
            int i = i0 + q0 + q;
            bool v0 = (k0p <= i) && (i - k0p <= 512);
            bool v1 = (k1p <= i) && (i - k1p <= 512);
            float sx = v0 ? s[q].x*0.125f : NEGF;
            float sy = v1 ? s[q].y*0.125f : NEGF;
            float mn = fmaxf(m[q], wmax(fmaxf(sx, sy)));
            float e = expf(m[q] - mn);
            float p0 = v0 ? expf(sx - mn) : 0.f;
            float p1 = v1 ? expf(sy - mn) : 0.f;
            SP[(q0+q)*64+l] = p0; SP[(q0+q)*64+l+32] = p1;
            Z[q] = Z[q]*e + wsum(p0 + p1);
            a[q].x *= e; a[q].y *= e;
            m[q] = mn;
        }
        __syncwarp();
        int dl = 2*l;
        #pragma unroll
        for (int c4 = 0; c4 < 64; c4 += 4){
            float2 vv0 = *(const float2*)&Vd[(c4+0)*64+dl];
            float2 vv1 = *(const float2*)&Vd[(c4+1)*64+dl];
            float2 vv2 = *(const float2*)&Vd[(c4+2)*64+dl];
            float2 vv3 = *(const float2*)&Vd[(c4+3)*64+dl];
            #pragma unroll
            for (int q = 0; q < 4; q++){
                float4 pg = *(const float4*)&SP[(q0+q)*64+c4];
                a[q].x += pg.x*vv0.x + pg.y*vv1.x + pg.z*vv2.x + pg.w*vv3.x;
                a[q].y += pg.x*vv0.y + pg.y*vv1.y + pg.z*vv2.y + pg.w*vv3.y;
            }
        }
        __syncthreads();
    }
    #pragma unroll
    for (int q = 0; q < 4; q++){
        int i = i0 + q0 + q;
        *(float2*)&g_sout[(size_t)i*DIMM + hq*64 + 2*l] = make_float2(a[q].x/Z[q], a[q].y/Z[q]);
    }
}

// ---------------- gated combination ----------------
__global__ void combine_kernel(){
    int idx = blockIdx.x*256 + threadIdx.x;
    int i = idx>>10, e = idx & 1023;
    int hh = e>>6;
    const float* gt = g_gate + i*48 + hh*3;
    g_comb[idx] = gt[0]*g_cout[idx] + gt[1]*g_fout[idx] + gt[2]*g_sout[idx];
}

extern "C" void kernel_launch(void* const* d_in, const int* in_sizes, int n_in,
                              void* d_out, int out_size){
    const float* x      = (const float*)d_in[0];
    const float* rms_g  = (const float*)d_in[1];
    const float* W_qkv  = (const float*)d_in[2];
    const float* k_pos  = (const float*)d_in[3];
    const float* v_pos  = (const float*)d_in[4];
    const float* mem_kv = (const float*)d_in[5];
    const float* kW1    = (const float*)d_in[6];
    const float* kb1    = (const float*)d_in[7];
    const float* kW2    = (const float*)d_in[8];
    const float* kb2    = (const float*)d_in[9];
    const float* vW1    = (const float*)d_in[10];
    const float* vb1    = (const float*)d_in[11];
    const float* vW2    = (const float*)d_in[12];
    const float* vb2    = (const float*)d_in[13];
    const float* W_comb = (const float*)d_in[14];
    const float* b_comb = (const float*)d_in[15];
    const float* W_out  = (const float*)d_in[16];
    float* out = (float*)d_out;

    float *p_xn, *p_qkv, *p_gate, *p_comb, *p_gp;
    cudaGetSymbolAddress((void**)&p_xn,   g_xn);
    cudaGetSymbolAddress((void**)&p_qkv,  g_qkv);
    cudaGetSymbolAddress((void**)&p_gate, g_gate);
    cudaGetSymbolAddress((void**)&p_comb, g_comb);
    cudaGetSymbolAddress((void**)&p_gp,   g_gp);

    const int GEMM_SMEM  = 2*GSTG*4;
    const int MLP1_SMEM  = 2*MSTG*4;
    const int FINE_SMEM  = 17920*4;
    const int SLIDE_SMEM = 20992*4;
    cudaFuncSetAttribute(tf32gemm_kernel,  cudaFuncAttributeMaxDynamicSharedMemorySize, GEMM_SMEM);
    cudaFuncSetAttribute(mlp1_tf32_kernel, cudaFuncAttributeMaxDynamicSharedMemorySize, MLP1_SMEM);
    cudaFuncSetAttribute(fine_attn_kernel, cudaFuncAttributeMaxDynamicSharedMemorySize, FINE_SMEM);
    cudaFuncSetAttribute(slide_kernel,     cudaFuncAttributeMaxDynamicSharedMemorySize, SLIDE_SMEM);

    rmsnorm_kernel<<<SEQ, 256>>>(x, rms_g);
    tf32gemm_kernel<<<dim3(10, 16, 2), 256, GEMM_SMEM>>>(p_xn, W_qkv, p_gp, SEQ, QKVW, DIMM, 512);
    add2_kernel<<<(SEQ*QKVW + 255)/256, 256>>>(p_gp, p_qkv, SEQ*QKVW);
    build_comp_kernel<<<2048, 256>>>(k_pos, v_pos);
    mlp1_tf32_kernel<<<dim3(32, 2, 4), 256, MLP1_SMEM>>>(kW1, vW1);
    mlp1red_kernel<<<2048, 256>>>(kb1, vb1);
    init_ck_kernel<<<1, 256>>>(mem_kv);
    mlp2_kernel<<<dim3(64, 2), 256>>>(kW2, kb2, vW2, vb2);
    comp_attn_kernel<<<dim3(SEQ, 2), 256>>>();
    rope_kernel<<<(SEQ*576 + 255)/256, 256>>>();
    fine_attn_kernel<<<dim3(SEQ, 2), 128, FINE_SMEM>>>();
    slide_kernel<<<dim3(64, 16), 256, SLIDE_SMEM>>>();
    sgemm_kernel<<<dim3(1, 32), 256>>>(p_xn, W_comb, b_comb, p_gate, SEQ, 48, DIMM, 3);
    combine_kernel<<<8192, 256>>>();
    tf32gemm_kernel<<<dim3(8, 16, 2), 256, GEMM_SMEM>>>(p_comb, W_out, p_gp, SEQ, DIMM, DIMM, 512);
    add2_kernel<<<(SEQ*DIMM + 255)/256, 256>>>(p_gp, out, SEQ*DIMM);
}

// round 16
// speedup vs baseline: 1.4608x; 1.0164x over previous
#include <cuda_runtime.h>
#include <math.h>

#define SEQ   2048
#define DIMM  1024
#define QKVW  1280
#define NEGF  (-3.402823466e38f)

// ---------------- scratch (static device globals) ----------------
__device__ __align__(16) float g_xn  [SEQ*DIMM];
__device__ __align__(16) float g_qkv [SEQ*QKVW];
__device__ __align__(16) float g_rq  [SEQ*DIMM];
__device__ __align__(16) float g_rk  [SEQ*128];
__device__ __align__(16) float g_cin [2*64*4096];
__device__ __align__(16) float g_hidp[4*2*64*4096];
__device__ __align__(16) float g_hid [2*64*4096];
__device__ __align__(16) float g_gp  [2*SEQ*QKVW];
__device__ __align__(16) float g_ck  [2*33*64];
__device__ __align__(16) float g_cv  [2*33*64];
__device__ __align__(16) float g_cout[SEQ*DIMM];
__device__ __align__(16) float g_fout[SEQ*DIMM];
__device__ __align__(16) float g_sout[SEQ*DIMM];
__device__ __align__(16) float g_gate[SEQ*48];
__device__ __align__(16) float g_comb[SEQ*DIMM];
__device__            int   g_sel [2*SEQ*9];

__device__ __forceinline__ float wmax(float v){
    #pragma unroll
    for (int o=16;o;o>>=1) v = fmaxf(v, __shfl_xor_sync(0xffffffffu, v, o));
    return v;
}
__device__ __forceinline__ float wsum(float v){
    #pragma unroll
    for (int o=16;o;o>>=1) v += __shfl_xor_sync(0xffffffffu, v, o);
    return v;
}

// ---------------- cp.async helpers ----------------
__device__ __forceinline__ void cp16(unsigned dst, const void* src){
    asm volatile("cp.async.cg.shared.global [%0], [%1], 16;" :: "r"(dst), "l"(src));
}
__device__ __forceinline__ void cp_commit(){ asm volatile("cp.async.commit_group;"); }
template<int N> __device__ __forceinline__ void cp_wait(){
    asm volatile("cp.async.wait_group %0;" :: "n"(N));
}

// ---------------- tf32 helpers ----------------
__device__ __forceinline__ void tf32_split(float f, unsigned& hi, unsigned& lo){
    asm("cvt.rna.tf32.f32 %0, %1;" : "=r"(hi) : "f"(f));
    float rem = f - __uint_as_float(hi);
    asm("cvt.rna.tf32.f32 %0, %1;" : "=r"(lo) : "f"(rem));
}
__device__ __forceinline__ void mma_tf32(float* c, const unsigned* a, const unsigned* b){
    asm volatile(
        "mma.sync.aligned.m16n8k8.row.col.f32.tf32.tf32.f32 "
        "{%0,%1,%2,%3},{%4,%5,%6,%7},{%8,%9},{%0,%1,%2,%3};"
        : "+f"(c[0]), "+f"(c[1]), "+f"(c[2]), "+f"(c[3])
        : "r"(a[0]), "r"(a[1]), "r"(a[2]), "r"(a[3]), "r"(b[0]), "r"(b[1]));
}
__device__ __forceinline__ void ldsm4(unsigned* r, unsigned addr){
    asm volatile("ldmatrix.sync.aligned.m8n8.x4.shared.b16 {%0,%1,%2,%3}, [%4];"
        : "=r"(r[0]), "=r"(r[1]), "=r"(r[2]), "=r"(r[3]) : "r"(addr));
}

// ---------------- RMSNorm ----------------
__global__ void rmsnorm_kernel(const float* __restrict__ x, const float* __restrict__ g){
    int s = blockIdx.x, tid = threadIdx.x;
    const float* xr = x + (size_t)s*DIMM;
    __shared__ float red[256];
    float ss = 0.f;
    for (int i = tid; i < DIMM; i += 256){ float v = xr[i]; ss += v*v; }
    red[tid] = ss; __syncthreads();
    for (int st = 128; st > 0; st >>= 1){ if (tid < st) red[tid] += red[tid+st]; __syncthreads(); }
    float sc = rsqrtf(red[0]*(1.f/DIMM) + 1.1920929e-7f);
    for (int i = tid; i < DIMM; i += 256) g_xn[(size_t)s*DIMM+i] = xr[i]*sc*g[i];
}

// ---------------- tf32 GEMM, double-buffered + split-K: BM=128,BN=128,BK=16 ----------------
// interleaved Bhl layout (stride 264, hi/lo pairs). x3!=0: 3 MMAs (fp32-equiv);
// x3==0: 2 MMAs (drop ah*bl term).
#define GSTG 9344
__global__ __launch_bounds__(256,2) void tf32gemm_kernel(
        const float* __restrict__ A, const float* __restrict__ B,
        float* __restrict__ Cp, int M, int N, int K, int Kc, int x3){
    extern __shared__ unsigned dsm[];
    int tid = threadIdx.x, lane = tid&31, wid = tid>>5;
    int m0b = blockIdx.y*128, n0b = blockIdx.x*128;
    int kbase = blockIdx.z*Kc;
    int mw = (wid>>2)*64, nw = (wid&3)*32;
    int r = lane>>2, c = lane&3;
    float acc[4][4][4] = {};
    int la_m = tid>>2, la_k = (tid&3)*4;
    int lb_r = tid>>5, lb_n = (tid&31)*4;
    int sub = lane>>3, e = lane&7;
    int a_row = mw + ((sub&1)<<3) + e;
    int a_col = (sub>>1)<<2;
    unsigned sm_base = (unsigned)__cvta_generic_to_shared(dsm);

    float4 pa0 = *(const float4*)(A + (size_t)(m0b+la_m)*K + kbase + la_k);
    float4 pa1 = *(const float4*)(A + (size_t)(m0b+la_m+64)*K + kbase + la_k);
    float4 pb0 = *(const float4*)(B + (size_t)(kbase+lb_r)*N + n0b + lb_n);
    float4 pb1 = *(const float4*)(B + (size_t)(kbase+lb_r+8)*N + n0b + lb_n);

    {
        unsigned* Ah = dsm; unsigned* Al = dsm + 2560; unsigned* Bhl = dsm + 5120;
        float fa0[4]={pa0.x,pa0.y,pa0.z,pa0.w}, fa1[4]={pa1.x,pa1.y,pa1.z,pa1.w};
        #pragma unroll
        for (int u = 0; u < 4; u++){
            unsigned hi, lo;
            tf32_split(fa0[u], hi, lo); Ah[la_m*20 + la_k+u] = hi;      Al[la_m*20 + la_k+u] = lo;
            tf32_split(fa1[u], hi, lo); Ah[(la_m+64)*20 + la_k+u] = hi; Al[(la_m+64)*20 + la_k+u] = lo;
        }
        unsigned h0,l0,h1,l1,h2,l2,h3,l3;
        tf32_split(pb0.x,h0,l0); tf32_split(pb0.y,h1,l1);
        tf32_split(pb0.z,h2,l2); tf32_split(pb0.w,h3,l3);
        *(uint4*)&Bhl[lb_r*264 + lb_n*2]     = make_uint4(h0,l0,h1,l1);
        *(uint4*)&Bhl[lb_r*264 + lb_n*2 + 4] = make_uint4(h2,l2,h3,l3);
        tf32_split(pb1.x,h0,l0); tf32_split(pb1.y,h1,l1);
        tf32_split(pb1.z,h2,l2); tf32_split(pb1.w,h3,l3);
        *(uint4*)&Bhl[(lb_r+8)*264 + lb_n*2]     = make_uint4(h0,l0,h1,l1);
        *(uint4*)&Bhl[(lb_r+8)*264 + lb_n*2 + 4] = make_uint4(h2,l2,h3,l3);
    }
    if (16 < Kc){
        pa0 = *(const float4*)(A + (size_t)(m0b+la_m)*K + kbase + 16 + la_k);
        pa1 = *(const float4*)(A + (size_t)(m0b+la_m+64)*K + kbase + 16 + la_k);
        pb0 = *(const float4*)(B + (size_t)(kbase+16+lb_r)*N + n0b + lb_n);
        pb1 = *(const float4*)(B + (size_t)(kbase+16+lb_r+8)*N + n0b + lb_n);
    }
    __syncthreads();

    int cur = 0;
    for (int k0 = 0; k0 < Kc; k0 += 16){
        {
            unsigned stg = cur*GSTG;
            unsigned* Bhl = dsm + stg + 5120;
            #pragma unroll
            for (int ks = 0; ks < 2; ks++){
                int kk = ks*8;
                unsigned ah[4][4], al[4][4];
                #pragma unroll
                for (int t = 0; t < 4; t++){
                    unsigned offh = sm_base + (stg + (a_row + t*16)*20 + kk + a_col)*4u;
                    ldsm4(ah[t], offh);
                    ldsm4(al[t], offh + 2560*4u);
                }
                #pragma unroll
                for (int j = 0; j < 4; j++){
                    int nc = nw + j*8 + r;
                    uint2 b0 = *(const uint2*)&Bhl[(kk+c)*264 + nc*2];
                    uint2 b1 = *(const uint2*)&Bhl[(kk+c+4)*264 + nc*2];
                    unsigned bh[2] = { b0.x, b1.x };
                    unsigned bl[2] = { b0.y, b1.y };
                    #pragma unroll
                    for (int t = 0; t < 4; t++){
                        mma_tf32(acc[t][j], ah[t], bh);
                        mma_tf32(acc[t][j], al[t], bh);
                        if (x3) mma_tf32(acc[t][j], ah[t], bl);
                    }
                }
            }
        }
        if (k0 + 16 < Kc){
            unsigned nstg = (cur^1)*GSTG;
            unsigned* Ah = dsm + nstg; unsigned* Al = dsm + nstg + 2560; unsigned* Bhl = dsm + nstg + 5120;
            float fa0[4]={pa0.x,pa0.y,pa0.z,pa0.w}, fa1[4]={pa1.x,pa1.y,pa1.z,pa1.w};
            #pragma unroll
            for (int u = 0; u < 4; u++){
                unsigned hi, lo;
                tf32_split(fa0[u], hi, lo); Ah[la_m*20 + la_k+u] = hi;      Al[la_m*20 + la_k+u] = lo;
                tf32_split(fa1[u], hi, lo); Ah[(la_m+64)*20 + la_k+u] = hi; Al[(la_m+64)*20 + la_k+u] = lo;
            }
            unsigned h0,l0,h1,l1,h2,l2,h3,l3;
            tf32_split(pb0.x,h0,l0); tf32_split(pb0.y,h1,l1);
            tf32_split(pb0.z,h2,l2); tf32_split(pb0.w,h3,l3);
            *(uint4*)&Bhl[lb_r*264 + lb_n*2]     = make_uint4(h0,l0,h1,l1);
            *(uint4*)&Bhl[lb_r*264 + lb_n*2 + 4] = make_uint4(h2,l2,h3,l3);
            tf32_split(pb1.x,h0,l0); tf32_split(pb1.y,h1,l1);
            tf32_split(pb1.z,h2,l2); tf32_split(pb1.w,h3,l3);
            *(uint4*)&Bhl[(lb_r+8)*264 + lb_n*2]     = make_uint4(h0,l0,h1,l1);
            *(uint4*)&Bhl[(lb_r+8)*264 + lb_n*2 + 4] = make_uint4(h2,l2,h3,l3);
        }
        if (k0 + 32 < Kc){
            pa0 = *(const float4*)(A + (size_t)(m0b+la_m)*K + kbase + k0+32 + la_k);
            pa1 = *(const float4*)(A + (size_t)(m0b+la_m+64)*K + kbase + k0+32 + la_k);
            pb0 = *(const float4*)(B + (size_t)(kbase+k0+32+lb_r)*N + n0b + lb_n);
            pb1 = *(const float4*)(B + (size_t)(kbase+k0+32+lb_r+8)*N + n0b + lb_n);
        }
        __syncthreads();
        cur ^= 1;
    }
    float* O = Cp + (size_t)blockIdx.z*M*N;
    #pragma unroll
    for (int t = 0; t < 4; t++)
        #pragma unroll
        for (int j = 0; j < 4; j++){
            int row = m0b + mw + t*16 + r;
            int col = n0b + nw + j*8 + c*2;
            O[(size_t)row*N + col]       = acc[t][j][0];
            O[(size_t)row*N + col+1]     = acc[t][j][1];
            O[(size_t)(row+8)*N + col]   = acc[t][j][2];
            O[(size_t)(row+8)*N + col+1] = acc[t][j][3];
        }
}

// partial sum: out[i] = p[i] + p[i+n]
__global__ void add2_kernel(const float* __restrict__ p, float* __restrict__ out, int n){
    int idx = blockIdx.x*256 + threadIdx.x;
    if (idx < n) out[idx] = p[idx] + p[idx + n];
}

// ---------------- MLP1 tf32x3 split-K, double-buffered: BM=64,BN=128 ----------------
#define MSTG 6784
__global__ __launch_bounds__(256,2) void mlp1_tf32_kernel(
        const float* __restrict__ kW1, const float* __restrict__ vW1){
    extern __shared__ unsigned dsm[];
    int tid = threadIdx.x, lane = tid&31, wid = tid>>5;
    int mat = blockIdx.y, kc = blockIdx.z;
    const float* A = g_cin + (size_t)mat*262144;
    const float* B = (mat ? vW1 : kW1);
    int n0b = blockIdx.x*128, kbase = kc*1024;
    int mw = (wid>>2)*32, nw = (wid&3)*32;
    int r = lane>>2, c = lane&3;
    float acc[2][4][4] = {};
    int fa_k = tid&15, fa_m = tid>>4;
    int fb_n = tid&127, fb_r = tid>>7;
    int sub = lane>>3, e = lane&7;
    int a_row = mw + ((sub&1)<<3) + e;
    int a_col = (sub>>1)<<2;
    unsigned sm_base = (unsigned)__cvta_generic_to_shared(dsm);

    float pa[4], pb[8];
    #pragma unroll
    for (int p = 0; p < 4; p++)
        pa[p] = A[(size_t)(fa_m + 16*p)*4096 + kbase + fa_k];
    #pragma unroll
    for (int p = 0; p < 8; p++)
        pb[p] = B[(size_t)(kbase + fb_r + 2*p)*4096 + n0b + fb_n];

    {
        unsigned* Ah = dsm; unsigned* Al = dsm + 1280; unsigned* Bhl = dsm + 2560;
        #pragma unroll
        for (int p = 0; p < 4; p++){
            unsigned hi, lo;
            tf32_split(pa[p], hi, lo);
            Ah[(fa_m + 16*p)*20 + fa_k] = hi;
            Al[(fa_m + 16*p)*20 + fa_k] = lo;
        }
        #pragma unroll
        for (int p = 0; p < 8; p++){
            unsigned hi, lo;
            tf32_split(pb[p], hi, lo);
            *(uint2*)&Bhl[(fb_r + 2*p)*264 + fb_n*2] = make_uint2(hi, lo);
        }
    }
    {
        #pragma unroll
        for (int p = 0; p < 4; p++)
            pa[p] = A[(size_t)(fa_m + 16*p)*4096 + kbase + 16 + fa_k];
        #pragma unroll
        for (int p = 0; p < 8; p++)
            pb[p] = B[(size_t)(kbase + 16 + fb_r + 2*p)*4096 + n0b + fb_n];
    }
    __syncthreads();

    int cur = 0;
    for (int k0 = 0; k0 < 1024; k0 += 16){
        {
            unsigned stg = cur*MSTG;
            unsigned* Bhl = dsm + stg + 2560;
            #pragma unroll
            for (int ks = 0; ks < 2; ks++){
                int kk = ks*8;
                unsigned ah[2][4], al[2][4];
                #pragma unroll
                for (int t = 0; t < 2; t++){
                    unsigned offh = sm_base + (stg + (a_row + t*16)*20 + kk + a_col)*4u;
                    ldsm4(ah[t], offh);
                    ldsm4(al[t], offh + 1280*4u);
                }
                #pragma unroll
                for (int j = 0; j < 4; j++){
                    int nc = nw + j*8 + r;
                    uint2 b0 = *(const uint2*)&Bhl[(kk+c)*264 + nc*2];
                    uint2 b1 = *(const uint2*)&Bhl[(kk+c+4)*264 + nc*2];
                    unsigned bh[2] = { b0.x, b1.x };
                    unsigned bl[2] = { b0.y, b1.y };
                    #pragma unroll
                    for (int t = 0; t < 2; t++){
                        mma_tf32(acc[t][j], ah[t], bh);
                        mma_tf32(acc[t][j], ah[t], bl);
                        mma_tf32(acc[t][j], al[t], bh);
                    }
                }
            }
        }
        if (k0 + 16 < 1024){
            unsigned nstg = (cur^1)*MSTG;
            unsigned* Ah = dsm + nstg; unsigned* Al = dsm + nstg + 1280; unsigned* Bhl = dsm + nstg + 2560;
            #pragma unroll
            for (int p = 0; p < 4; p++){
                unsigned hi, lo;
                tf32_split(pa[p], hi, lo);
                Ah[(fa_m + 16*p)*20 + fa_k] = hi;
                Al[(fa_m + 16*p)*20 + fa_k] = lo;
            }
            #pragma unroll
            for (int p = 0; p < 8; p++){
                unsigned hi, lo;
                tf32_split(pb[p], hi, lo);
                *(uint2*)&Bhl[(fb_r + 2*p)*264 + fb_n*2] = make_uint2(hi, lo);
            }
        }
        if (k0 + 32 < 1024){
            #pragma unroll
            for (int p = 0; p < 4; p++)
                pa[p] = A[(size_t)(fa_m + 16*p)*4096 + kbase + k0 + 32 + fa_k];
            #pragma unroll
            for (int p = 0; p < 8; p++)
                pb[p] = B[(size_t)(kbase + k0 + 32 + fb_r + 2*p)*4096 + n0b + fb_n];
        }
        __syncthreads();
        cur ^= 1;
    }
    float* O = g_hidp + (size_t)(kc*2+mat)*64*4096;
    #pragma unroll
    for (int t = 0; t < 2; t++)
        #pragma unroll
        for (int j = 0; j < 4; j++){
            int row = mw + t*16 + r;
            int col = n0b + nw + j*8 + c*2;
            O[(size_t)row*4096 + col]       = acc[t][j][0];
            O[(size_t)row*4096 + col+1]     = acc[t][j][1];
            O[(size_t)(row+8)*4096 + col]   = acc[t][j][2];
            O[(size_t)(row+8)*4096 + col+1] = acc[t][j][3];
        }
}

// ---------------- small SGEMM (gates) ----------------
__global__ void sgemm_kernel(const float* __restrict__ A, const float* __restrict__ B,
                             const float* __restrict__ bias, float* __restrict__ C,
                             int M, int N, int K, int epi){
    __shared__ __align__(16) float As[16][72];
    __shared__ __align__(16) float Bs[16][72];
    int tid = threadIdx.x;
    int tr = tid>>4, tc = tid&15;
    int m0 = blockIdx.y*64, n0 = blockIdx.x*64;
    int lm = tid>>2, lk4 = (tid&3)*4;
    int lkb = tid>>4, ln4 = (tid&15)*4;
    float acc[4][4] = {};
    for (int k0 = 0; k0 < K; k0 += 16){
        float4 a4 = *(const float4*)(A + (size_t)(m0+lm)*K + k0 + lk4);
        As[lk4+0][lm]=a4.x; As[lk4+1][lm]=a4.y; As[lk4+2][lm]=a4.z; As[lk4+3][lm]=a4.w;
        if (n0+ln4+3 < N){
            *(float4*)&Bs[lkb][ln4] = *(const float4*)(B + (size_t)(k0+lkb)*N + n0 + ln4);
        } else {
            #pragma unroll
            for (int u=0;u<4;u++)
                Bs[lkb][ln4+u] = (n0+ln4+u < N) ? B[(size_t)(k0+lkb)*N + n0+ln4+u] : 0.f;
        }
        __syncthreads();
        #pragma unroll
        for (int kk=0; kk<16; kk++){
            float4 a = *(const float4*)&As[kk][tr*4];
            float4 b = *(const float4*)&Bs[kk][tc*4];
            float av[4]={a.x,a.y,a.z,a.w}, bv[4]={b.x,b.y,b.z,b.w};
            #pragma unroll
            for (int i=0;i<4;i++)
                #pragma unroll
                for (int j=0;j<4;j++) acc[i][j] += av[i]*bv[j];
        }
        __syncthreads();
    }
    #pragma unroll
    for (int i=0;i<4;i++){
        int row = m0 + tr*4 + i;
        #pragma unroll
        for (int j=0;j<4;j++){
            int col = n0 + tc*4 + j;
            if (col < N){
                float v = acc[i][j];
                if (epi >= 1) v += bias[col];
                if (epi == 3) v = 1.f/(1.f + expf(-v));
                C[(size_t)row*N + col] = v;
            }
        }
    }
}

// ---------------- build compression MLP input [2][64][4096] ----------------
__global__ void build_comp_kernel(const float* __restrict__ k_pos, const float* __restrict__ v_pos){
    int idx = blockIdx.x*256 + threadIdx.x;
    int mat = idx>>18, rem = idx & 262143;
    int r = rem>>12, i = rem & 4095;
    int h = r>>5, w = r&31;
    int c = i>>6, d = i&63;
    int s = w*64 + c;
    const float* pos = mat ? v_pos : k_pos;
    int off = mat ? (DIMM + 128) : DIMM;
    g_cin[idx] = g_qkv[(size_t)s*QKVW + off + h*64 + d] + pos[(h*64+c)*64 + d];
}

__global__ void mlp1red_kernel(const float* __restrict__ kb1, const float* __restrict__ vb1){
    int idx = blockIdx.x*256 + threadIdx.x;
    int mat = idx>>18, n = idx & 4095;
    float s = g_hidp[idx] + g_hidp[idx+524288] + g_hidp[idx+1048576] + g_hidp[idx+1572864];
    s += (mat ? vb1 : kb1)[n];
    g_hid[idx] = fmaxf(s, 0.f);
}

// ---------------- mem token init ----------------
__global__ void init_ck_kernel(const float* __restrict__ mem_kv){
    int t = threadIdx.x;
    int mat = t>>7, h = (t>>6)&1, d = t&63;
    float* out = mat ? g_cv : g_ck;
    out[h*33*64 + d] = mem_kv[(mat*2+h)*64 + d];
}

// ---------------- MLP layer2 ----------------
__global__ void mlp2_kernel(const float* __restrict__ kW2, const float* __restrict__ kb2,
                            const float* __restrict__ vW2, const float* __restrict__ vb2){
    int r = blockIdx.x, mat = blockIdx.y, tid = threadIdx.x;
    int d = tid&63, kq = tid>>6;
    const float* H = g_hid + (size_t)(mat*64+r)*4096;
    const float* W = mat ? vW2 : kW2;
    const float* b = mat ? vb2 : kb2;
    float acc = 0.f;
    int kend = kq*1024 + 1024;
    for (int k = kq*1024; k < kend; k++) acc += H[k]*W[(size_t)k*64 + d];
    __shared__ float red[4][64];
    red[kq][d] = acc; __syncthreads();
    if (kq == 0){
        float s = red[0][d]+red[1][d]+red[2][d]+red[3][d] + b[d];
        int h = r>>5, w = r&31;
        float* out = mat ? g_cv : g_ck;
        out[(h*33 + 1 + w)*64 + d] = s;
    }
}

// ---------------- compressed attention + selection ----------------
__global__ void comp_attn_kernel(){
    int i = blockIdx.x, h = blockIdx.y, tid = threadIdx.x;
    __shared__ float sq[512];
    __shared__ float sk[33*65];
    __shared__ float sv[33*65];
    __shared__ float L[264], P[264], Zr[8];
    for (int o = tid; o < 512; o += 256) sq[o] = g_qkv[(size_t)i*QKVW + h*512 + o];
    for (int o = tid; o < 33*64; o += 256){
        int j = o>>6, d = o&63;
        sk[j*65+d] = g_ck[h*2112 + o];
        sv[j*65+d] = g_cv[h*2112 + o];
    }
    __syncthreads();
    for (int o = tid; o < 264; o += 256){
        int g = o/33, j = o - g*33;
        bool vis = (j == 0) || (j*64 - 1 < i);
        float a = NEGF;
        if (vis){
            float s = 0.f;
            #pragma unroll 8
            for (int d = 0; d < 64; d++) s += sq[g*64+d]*sk[j*65+d];
            a = s*0.125f;
        }
        L[o] = a;
    }
    __syncthreads();
    if (tid < 8){
        int g = tid;
        float m = NEGF;
        for (int j = 0; j < 33; j++) m = fmaxf(m, L[g*33+j]);
        float z = 0.f;
        for (int j = 0; j < 33; j++){
            float l = L[g*33+j];
            float p = (l < -1e30f) ? 0.f : expf(l - m);
            P[g*33+j] = p; z += p;
        }
        Zr[g] = z;
    }
    if (tid == 32){
        float pr[32], im[32]; float M = -1000.f;
        for (int j = 0; j < 32; j++){
            float s = 0.f;
            for (int g = 0; g < 8; g++) s += L[g*33 + j + 1];
            im[j] = s*0.125f;
            M = fmaxf(M, im[j]);
        }
        float Zs = expf(-1000.f - M);
        for (int j = 0; j < 32; j++){
            float p = (im[j] < -1e30f) ? 0.f : expf(im[j] - M);
            pr[j] = p; Zs += p;
        }
        bool taken[32];
        for (int j = 0; j < 32; j++) taken[j] = false;
        int base = (h*SEQ + i)*9;
        for (int t = 0; t < 8; t++){
            int best = -1; float bv = -1.f;
            for (int j = 0; j < 32; j++)
                if (!taken[j] && pr[j] > bv){ bv = pr[j]; best = j; }
            if (best >= 0 && bv/Zs > 1e-10f){ taken[best] = true; g_sel[base+t] = best; }
            else g_sel[base+t] = -1;
        }
        g_sel[base+8] = i>>6;
    }
    __syncthreads();
    for (int o = tid; o < 512; o += 256){
        int g = o>>6, d = o&63;
        float a = 0.f;
        for (int j = 0; j < 33; j++) a += P[g*33+j]*sv[j*65+d];
        g_cout[(size_t)i*DIMM + h*512 + o] = a/Zr[g];
    }
}

// ---------------- RoPE on q and k ----------------
__global__ void rope_kernel(){
    int idx = blockIdx.x*256 + threadIdx.x;
    if (idx >= SEQ*576) return;
    int s = idx/576, e = idx - s*576;
    float pos = (float)s;
    if (e < 512){
        int p = e & 31;
        float ang = pos*exp2f(-(float)p*0.41524101186092033f);
        float c = cosf(ang), si = sinf(ang);
        const float* b = g_qkv + (size_t)s*QKVW + e*2;
        float u0 = b[0], u1 = b[1];
        g_rq[(size_t)s*DIMM + e*2]   = u0*c - u1*si;
        g_rq[(size_t)s*DIMM + e*2+1] = u1*c + u0*si;
    } else {
        int e2 = e - 512, p = e2 & 31;
        float ang = pos*exp2f(-(float)p*0.41524101186092033f);
        float c = cosf(ang), si = sinf(ang);
        const float* b = g_qkv + (size_t)s*QKVW + DIMM + e2*2;
        float u0 = b[0], u1 = b[1];
        g_rk[(size_t)s*128 + e2*2]   = u0*c - u1*si;
        g_rk[(size_t)s*128 + e2*2+1] = u1*c + u0*si;
    }
}

// ---------------- fine attention: cp.async double-buffered tiles ----------------
__global__ void fine_attn_kernel(){
    extern __shared__ float fsm[];
    float* Kb = fsm;
    float* Vb = fsm + 8704;
    float* SQ = fsm + 16896;
    float* SP = fsm + 17408;
    int i = blockIdx.x, h = blockIdx.y, tid = threadIdx.x;
    int w = tid>>5, l = tid&31;
    int base = (h*SEQ + i)*9;
    int blks[9]; bool dg[9]; int nb = 0;
    #pragma unroll
    for (int slot = 0; slot < 9; slot++){
        int blk = (slot < 8) ? g_sel[base+slot] : (i>>6);
        if (blk >= 0){ blks[nb] = blk; dg[nb] = (slot == 8); nb++; }
    }
    for (int o = tid; o < 512; o += 128) SQ[o] = g_rq[(size_t)i*DIMM + h*512 + o];

    auto issue = [&](int t, int stg){
        int blk = blks[t];
        float* Kd = Kb + stg*4352;
        float* Vd = Vb + stg*4096;
        #pragma unroll
        for (int o = tid; o < 1024; o += 128){
            int c = o>>4, d4 = (o&15)*4;
            cp16((unsigned)__cvta_generic_to_shared(&Kd[c*68+d4]),
                 g_rk + (size_t)(blk*64+c)*128 + h*64 + d4);
            cp16((unsigned)__cvta_generic_to_shared(&Vd[c*64+d4]),
                 g_qkv + (size_t)(blk*64+c)*QKVW + 1152 + h*64 + d4);
        }
        cp_commit();
    };

    int g0 = w*2, g1 = w*2+1;
    float m0=NEGF, m1=NEGF, Z0=0.f, Z1=0.f;
    float2 a0 = make_float2(0.f,0.f), a1 = make_float2(0.f,0.f);
    int lim = i & 63;

    issue(0, 0);
    for (int t = 0; t < nb; t++){
        if (t + 1 < nb) issue(t+1, (t+1)&1);
        if (t + 1 < nb) cp_wait<1>(); else cp_wait<0>();
        __syncthreads();
        float* Kd = Kb + (t&1)*4352;
        float* Vd = Vb + (t&1)*4096;
        bool isdg = dg[t];

        float2 s0 = make_float2(0.f,0.f), s1 = make_float2(0.f,0.f);
        #pragma unroll
        for (int d4 = 0; d4 < 64; d4 += 4){
            float4 k0 = *(const float4*)&Kd[l*68+d4];
            float4 k1 = *(const float4*)&Kd[(l+32)*68+d4];
            float4 q0 = *(const float4*)&SQ[g0*64+d4];
            float4 q1 = *(const float4*)&SQ[g1*64+d4];
            s0.x += q0.x*k0.x + q0.y*k0.y + q0.z*k0.z + q0.w*k0.w;
            s0.y += q0.x*k1.x + q0.y*k1.y + q0.z*k1.z + q0.w*k1.w;
            s1.x += q1.x*k0.x + q1.y*k0.y + q1.z*k0.z + q1.w*k0.w;
            s1.y += q1.x*k1.x + q1.y*k1.y + q1.z*k1.z + q1.w*k1.w;
        }
        bool v0 = (!isdg) || (l <= lim);
        bool v1 = (!isdg) || (l+32 <= lim);
        float sa = v0 ? s0.x*0.125f : NEGF;
        float sb = v1 ? s0.y*0.125f : NEGF;
        float sc_ = v0 ? s1.x*0.125f : NEGF;
        float sd = v1 ? s1.y*0.125f : NEGF;
        float mn0 = fmaxf(m0, wmax(fmaxf(sa, sb)));
        float e0 = expf(m0 - mn0);
        float p00 = v0 ? expf(sa - mn0) : 0.f;
        float p01 = v1 ? expf(sb - mn0) : 0.f;
        SP[g0*64+l] = p00; SP[g0*64+l+32] = p01;
        Z0 = Z0*e0 + wsum(p00 + p01);
        a0.x *= e0; a0.y *= e0;
        float mn1 = fmaxf(m1, wmax(fmaxf(sc_, sd)));
        float e1 = expf(m1 - mn1);
        float p10 = v0 ? expf(sc_ - mn1) : 0.f;
        float p11 = v1 ? expf(sd - mn1) : 0.f;
        SP[g1*64+l] = p10; SP[g1*64+l+32] = p11;
        Z1 = Z1*e1 + wsum(p10 + p11);
        a1.x *= e1; a1.y *= e1;
        m0 = mn0; m1 = mn1;
        __syncwarp();
        int dl = 2*l;
        #pragma unroll
        for (int c4 = 0; c4 < 64; c4 += 4){
            float4 pg0 = *(const float4*)&SP[g0*64+c4];
            float4 pg1 = *(const float4*)&SP[g1*64+c4];
            float2 vv0 = *(const float2*)&Vd[(c4+0)*64+dl];
            float2 vv1 = *(const float2*)&Vd[(c4+1)*64+dl];
            float2 vv2 = *(const float2*)&Vd[(c4+2)*64+dl];
            float2 vv3 = *(const float2*)&Vd[(c4+3)*64+dl];
            a0.x += pg0.x*vv0.x + pg0.y*vv1.x + pg0.z*vv2.x + pg0.w*vv3.x;
            a0.y += pg0.x*vv0.y + pg0.y*vv1.y + pg0.z*vv2.y + pg0.w*vv3.y;
            a1.x += pg1.x*vv0.x + pg1.y*vv1.x + pg1.z*vv2.x + pg1.w*vv3.x;
            a1.y += pg1.x*vv0.y + pg1.y*vv1.y + pg1.z*vv2.y + pg1.w*vv3.y;
        }
        __syncthreads();
    }
    size_t ob = (size_t)i*DIMM + h*512;
    *(float2*)&g_fout[ob + g0*64 + 2*l] = make_float2(a0.x/Z0, a0.y/Z0);
    *(float2*)&g_fout[ob + g1*64 + 2*l] = make_float2(a1.x/Z1, a1.y/Z1);
}

// ---------------- sliding window: 256 thr, 8 warps x 4 q = 32 queries/block ----------------
__global__ void slide_kernel(){
    extern __shared__ float ssm[];
    float* Kb = ssm;
    float* Vb = ssm + 8704;
    float* SQ = ssm + 16896;
    float* SP = ssm + 18944;
    int tid = threadIdx.x;
    int w = tid>>5, l = tid&31;
    int hq = blockIdx.y, hk = hq>>3;
    int i0 = blockIdx.x*32;
    for (int o = tid; o < 2048; o += 256){
        int qq = o>>6, d = o&63;
        SQ[o] = g_rq[(size_t)(i0+qq)*DIMM + hq*64 + d];
    }
    int cbtop = i0>>6;
    int cb0 = cbtop - 8; if (cb0 < 0) cb0 = 0;
    int nb = cbtop - cb0 + 1;

    auto issue = [&](int t, int stg){
        int cb = cb0 + t;
        float* Kd = Kb + stg*4352;
        float* Vd = Vb + stg*4096;
        #pragma unroll
        for (int o = tid; o < 1024; o += 256){
            int c = o>>4, d4 = (o&15)*4;
            cp16((unsigned)__cvta_generic_to_shared(&Kd[c*68+d4]),
                 g_rk + (size_t)(cb*64+c)*128 + hk*64 + d4);
            cp16((unsigned)__cvta_generic_to_shared(&Vd[c*64+d4]),
                 g_qkv + (size_t)(cb*64+c)*QKVW + 1152 + hk*64 + d4);
        }
        cp_commit();
    };

    float m[4], Z[4]; float2 a[4];
    #pragma unroll
    for (int q = 0; q < 4; q++){ m[q]=NEGF; Z[q]=0.f; a[q]=make_float2(0.f,0.f); }
    int q0 = w*4;

    issue(0, 0);
    for (int t = 0; t < nb; t++){
        if (t + 1 < nb) issue(t+1, (t+1)&1);
        if (t + 1 < nb) cp_wait<1>(); else cp_wait<0>();
        __syncthreads();
        int cb = cb0 + t;
        float* Kd = Kb + (t&1)*4352;
        float* Vd = Vb + (t&1)*4096;

        float2 s[4];
        #pragma unroll
        for (int q = 0; q < 4; q++) s[q] = make_float2(0.f,0.f);
        #pragma unroll
        for (int d4 = 0; d4 < 64; d4 += 4){
            float4 k0 = *(const float4*)&Kd[l*68+d4];
            float4 k1 = *(const float4*)&Kd[(l+32)*68+d4];
            #pragma unroll
            for (int q = 0; q < 4; q++){
                float4 qv = *(const float4*)&SQ[(q0+q)*64+d4];
                s[q].x += qv.x*k0.x + qv.y*k0.y + qv.z*k0.z + qv.w*k0.w;
                s[q].y += qv.x*k1.x + qv.y*k1.y + qv.z*k1.z + qv.w*k1.w;
            }
        }
        int k0p = cb*64 + l, k1p = k0p + 32;
        #pragma unroll
        for (int q = 0; q < 4; q++){
            int i = i0 + q0 + q;
            bool v0 = (k0p <= i) && (i - k0p <= 512);
            bool v1 = (k1p <= i) && (i - k1p <= 512);
            float sx = v0 ? s[q].x*0.125f : NEGF;
            float sy = v1 ? s[q].y*0.125f : NEGF;
            float mn = fmaxf(m[q], wmax(fmaxf(sx, sy)));
            float e = expf(m[q] - mn);
            float p0 = v0 ? expf(sx - mn) : 0.f;
            float p1 = v1 ? expf(sy - mn) : 0.f;
            SP[(q0+q)*64+l] = p0; SP[(q0+q)*64+l+32] = p1;
            Z[q] = Z[q]*e + wsum(p0 + p1);
            a[q].x *= e; a[q].y *= e;
            m[q] = mn;
        }
        __syncwarp();
        int dl = 2*l;
        #pragma unroll
        for (int c4 = 0; c4 < 64; c4 += 4){
            float2 vv0 = *(const float2*)&Vd[(c4+0)*64+dl];
            float2 vv1 = *(const float2*)&Vd[(c4+1)*64+dl];
            float2 vv2 = *(const float2*)&Vd[(c4+2)*64+dl];
            float2 vv3 = *(const float2*)&Vd[(c4+3)*64+dl];
            #pragma unroll
            for (int q = 0; q < 4; q++){
                float4 pg = *(const float4*)&SP[(q0+q)*64+c4];
                a[q].x += pg.x*vv0.x + pg.y*vv1.x + pg.z*vv2.x + pg.w*vv3.x;
                a[q].y += pg.x*vv0.y + pg.y*vv1.y + pg.z*vv2.y + pg.w*vv3.y;
            }
        }
        __syncthreads();
    }
    #pragma unroll
    for (int q = 0; q < 4; q++){
        int i = i0 + q0 + q;
        *(float2*)&g_sout[(size_t)i*DIMM + hq*64 + 2*l] = make_float2(a[q].x/Z[q], a[q].y/Z[q]);
    }
}

// ---------------- gated combination ----------------
__global__ void combine_kernel(){
    int idx = blockIdx.x*256 + threadIdx.x;
    int i = idx>>10, e = idx & 1023;
    int hh = e>>6;
    const float* gt = g_gate + i*48 + hh*3;
    g_comb[idx] = gt[0]*g_cout[idx] + gt[1]*g_fout[idx] + gt[2]*g_sout[idx];
}

extern "C" void kernel_launch(void* const* d_in, const int* in_sizes, int n_in,
                              void* d_out, int out_size){
    const float* x      = (const float*)d_in[0];
    const float* rms_g  = (const float*)d_in[1];
    const float* W_qkv  = (const float*)d_in[2];
    const float* k_pos  = (const float*)d_in[3];
    const float* v_pos  = (const float*)d_in[4];
    const float* mem_kv = (const float*)d_in[5];
    const float* kW1    = (const float*)d_in[6];
    const float* kb1    = (const float*)d_in[7];
    const float* kW2    = (const float*)d_in[8];
    const float* kb2    = (const float*)d_in[9];
    const float* vW1    = (const float*)d_in[10];
    const float* vb1    = (const float*)d_in[11];
    const float* vW2    = (const float*)d_in[12];
    const float* vb2    = (const float*)d_in[13];
    const float* W_comb = (const float*)d_in[14];
    const float* b_comb = (const float*)d_in[15];
    const float* W_out  = (const float*)d_in[16];
    float* out = (float*)d_out;

    float *p_xn, *p_qkv, *p_gate, *p_comb, *p_gp;
    cudaGetSymbolAddress((void**)&p_xn,   g_xn);
    cudaGetSymbolAddress((void**)&p_qkv,  g_qkv);
    cudaGetSymbolAddress((void**)&p_gate, g_gate);
    cudaGetSymbolAddress((void**)&p_comb, g_comb);
    cudaGetSymbolAddress((void**)&p_gp,   g_gp);

    const int GEMM_SMEM  = 2*GSTG*4;
    const int MLP1_SMEM  = 2*MSTG*4;
    const int FINE_SMEM  = 17920*4;
    const int SLIDE_SMEM = 20992*4;
    cudaFuncSetAttribute(tf32gemm_kernel,  cudaFuncAttributeMaxDynamicSharedMemorySize, GEMM_SMEM);
    cudaFuncSetAttribute(mlp1_tf32_kernel, cudaFuncAttributeMaxDynamicSharedMemorySize, MLP1_SMEM);
    cudaFuncSetAttribute(fine_attn_kernel, cudaFuncAttributeMaxDynamicSharedMemorySize, FINE_SMEM);
    cudaFuncSetAttribute(slide_kernel,     cudaFuncAttributeMaxDynamicSharedMemorySize, SLIDE_SMEM);

    rmsnorm_kernel<<<SEQ, 256>>>(x, rms_g);
    tf32gemm_kernel<<<dim3(10, 16, 2), 256, GEMM_SMEM>>>(p_xn, W_qkv, p_gp, SEQ, QKVW, DIMM, 512, 1);
    add2_kernel<<<(SEQ*QKVW + 255)/256, 256>>>(p_gp, p_qkv, SEQ*QKVW);
    build_comp_kernel<<<2048, 256>>>(k_pos, v_pos);
    mlp1_tf32_kernel<<<dim3(32, 2, 4), 256, MLP1_SMEM>>>(kW1, vW1);
    mlp1red_kernel<<<2048, 256>>>(kb1, vb1);
    init_ck_kernel<<<1, 256>>>(mem_kv);
    mlp2_kernel<<<dim3(64, 2), 256>>>(kW2, kb2, vW2, vb2);
    comp_attn_kernel<<<dim3(SEQ, 2), 256>>>();
    rope_kernel<<<(SEQ*576 + 255)/256, 256>>>();
    fine_attn_kernel<<<dim3(SEQ, 2), 128, FINE_SMEM>>>();
    slide_kernel<<<dim3(64, 16), 256, SLIDE_SMEM>>>();
    sgemm_kernel<<<dim3(1, 32), 256>>>(p_xn, W_comb, b_comb, p_gate, SEQ, 48, DIMM, 3);
    combine_kernel<<<8192, 256>>>();
    tf32gemm_kernel<<<dim3(8, 16, 2), 256, GEMM_SMEM>>>(p_comb, W_out, p_gp, SEQ, DIMM, DIMM, 512, 0);
    add2_kernel<<<(SEQ*DIMM + 255)/256, 256>>>(p_gp, out, SEQ*DIMM);
}

// round 17
// speedup vs baseline: 1.4787x; 1.0122x over previous
#include <cuda_runtime.h>
#include <math.h>

#define SEQ   2048
#define DIMM  1024
#define QKVW  1280
#define NEGF  (-3.402823466e38f)

// ---------------- scratch (static device globals) ----------------
__device__ __align__(16) float g_xn  [SEQ*DIMM];
__device__ __align__(16) float g_qkv [SEQ*QKVW];
__device__ __align__(16) float g_rq  [SEQ*DIMM];
__device__ __align__(16) float g_rk  [SEQ*128];
__device__ __align__(16) float g_cin [2*64*4096];
__device__ __align__(16) float g_hidp[4*2*64*4096];
__device__ __align__(16) float g_hid [2*64*4096];
__device__ __align__(16) float g_gp  [2*SEQ*QKVW];
__device__ __align__(16) float g_ck  [2*33*64];
__device__ __align__(16) float g_cv  [2*33*64];
__device__ __align__(16) float g_cout[SEQ*DIMM];
__device__ __align__(16) float g_fout[SEQ*DIMM];
__device__ __align__(16) float g_sout[SEQ*DIMM];
__device__ __align__(16) float g_gate[SEQ*48];
__device__ __align__(16) float g_comb[SEQ*DIMM];
__device__            int   g_sel [2*SEQ*9];

__device__ __forceinline__ float wmax(float v){
    #pragma unroll
    for (int o=16;o;o>>=1) v = fmaxf(v, __shfl_xor_sync(0xffffffffu, v, o));
    return v;
}
__device__ __forceinline__ float wsum(float v){
    #pragma unroll
    for (int o=16;o;o>>=1) v += __shfl_xor_sync(0xffffffffu, v, o);
    return v;
}

// ---------------- cp.async helpers ----------------
__device__ __forceinline__ void cp16(unsigned dst, const void* src){
    asm volatile("cp.async.cg.shared.global [%0], [%1], 16;" :: "r"(dst), "l"(src));
}
__device__ __forceinline__ void cp_commit(){ asm volatile("cp.async.commit_group;"); }
template<int N> __device__ __forceinline__ void cp_wait(){
    asm volatile("cp.async.wait_group %0;" :: "n"(N));
}

// ---------------- tf32 helpers ----------------
__device__ __forceinline__ void tf32_split(float f, unsigned& hi, unsigned& lo){
    asm("cvt.rna.tf32.f32 %0, %1;" : "=r"(hi) : "f"(f));
    float rem = f - __uint_as_float(hi);
    asm("cvt.rna.tf32.f32 %0, %1;" : "=r"(lo) : "f"(rem));
}
__device__ __forceinline__ void mma_tf32(float* c, const unsigned* a, const unsigned* b){
    asm volatile(
        "mma.sync.aligned.m16n8k8.row.col.f32.tf32.tf32.f32 "
        "{%0,%1,%2,%3},{%4,%5,%6,%7},{%8,%9},{%0,%1,%2,%3};"
        : "+f"(c[0]), "+f"(c[1]), "+f"(c[2]), "+f"(c[3])
        : "r"(a[0]), "r"(a[1]), "r"(a[2]), "r"(a[3]), "r"(b[0]), "r"(b[1]));
}
__device__ __forceinline__ void ldsm4(unsigned* r, unsigned addr){
    asm volatile("ldmatrix.sync.aligned.m8n8.x4.shared.b16 {%0,%1,%2,%3}, [%4];"
        : "=r"(r[0]), "=r"(r[1]), "=r"(r[2]), "=r"(r[3]) : "r"(addr));
}

// ---------------- RMSNorm ----------------
__global__ void rmsnorm_kernel(const float* __restrict__ x, const float* __restrict__ g){
    int s = blockIdx.x, tid = threadIdx.x;
    const float* xr = x + (size_t)s*DIMM;
    __shared__ float red[256];
    float ss = 0.f;
    for (int i = tid; i < DIMM; i += 256){ float v = xr[i]; ss += v*v; }
    red[tid] = ss; __syncthreads();
    for (int st = 128; st > 0; st >>= 1){ if (tid < st) red[tid] += red[tid+st]; __syncthreads(); }
    float sc = rsqrtf(red[0]*(1.f/DIMM) + 1.1920929e-7f);
    for (int i = tid; i < DIMM; i += 256) g_xn[(size_t)s*DIMM+i] = xr[i]*sc*g[i];
}

// ---------------- tf32 GEMM, double-buffered + split-K: BM=128,BN=128,BK=16 ----------------
// interleaved Bhl layout (stride 264, hi/lo pairs). x3!=0: 3 MMAs (fp32-equiv);
// x3==0: 2 MMAs (drop ah*bl term).
#define GSTG 9344
__global__ __launch_bounds__(256,2) void tf32gemm_kernel(
        const float* __restrict__ A, const float* __restrict__ B,
        float* __restrict__ Cp, int M, int N, int K, int Kc, int x3){
    extern __shared__ unsigned dsm[];
    int tid = threadIdx.x, lane = tid&31, wid = tid>>5;
    int m0b = blockIdx.y*128, n0b = blockIdx.x*128;
    int kbase = blockIdx.z*Kc;
    int mw = (wid>>2)*64, nw = (wid&3)*32;
    int r = lane>>2, c = lane&3;
    float acc[4][4][4] = {};
    int la_m = tid>>2, la_k = (tid&3)*4;
    int lb_r = tid>>5, lb_n = (tid&31)*4;
    int sub = lane>>3, e = lane&7;
    int a_row = mw + ((sub&1)<<3) + e;
    int a_col = (sub>>1)<<2;
    unsigned sm_base = (unsigned)__cvta_generic_to_shared(dsm);

    float4 pa0 = *(const float4*)(A + (size_t)(m0b+la_m)*K + kbase + la_k);
    float4 pa1 = *(const float4*)(A + (size_t)(m0b+la_m+64)*K + kbase + la_k);
    float4 pb0 = *(const float4*)(B + (size_t)(kbase+lb_r)*N + n0b + lb_n);
    float4 pb1 = *(const float4*)(B + (size_t)(kbase+lb_r+8)*N + n0b + lb_n);

    {
        unsigned* Ah = dsm; unsigned* Al = dsm + 2560; unsigned* Bhl = dsm + 5120;
        float fa0[4]={pa0.x,pa0.y,pa0.z,pa0.w}, fa1[4]={pa1.x,pa1.y,pa1.z,pa1.w};
        #pragma unroll
        for (int u = 0; u < 4; u++){
            unsigned hi, lo;
            tf32_split(fa0[u], hi, lo); Ah[la_m*20 + la_k+u] = hi;      Al[la_m*20 + la_k+u] = lo;
            tf32_split(fa1[u], hi, lo); Ah[(la_m+64)*20 + la_k+u] = hi; Al[(la_m+64)*20 + la_k+u] = lo;
        }
        unsigned h0,l0,h1,l1,h2,l2,h3,l3;
        tf32_split(pb0.x,h0,l0); tf32_split(pb0.y,h1,l1);
        tf32_split(pb0.z,h2,l2); tf32_split(pb0.w,h3,l3);
        *(uint4*)&Bhl[lb_r*264 + lb_n*2]     = make_uint4(h0,l0,h1,l1);
        *(uint4*)&Bhl[lb_r*264 + lb_n*2 + 4] = make_uint4(h2,l2,h3,l3);
        tf32_split(pb1.x,h0,l0); tf32_split(pb1.y,h1,l1);
        tf32_split(pb1.z,h2,l2); tf32_split(pb1.w,h3,l3);
        *(uint4*)&Bhl[(lb_r+8)*264 + lb_n*2]     = make_uint4(h0,l0,h1,l1);
        *(uint4*)&Bhl[(lb_r+8)*264 + lb_n*2 + 4] = make_uint4(h2,l2,h3,l3);
    }
    if (16 < Kc){
        pa0 = *(const float4*)(A + (size_t)(m0b+la_m)*K + kbase + 16 + la_k);
        pa1 = *(const float4*)(A + (size_t)(m0b+la_m+64)*K + kbase + 16 + la_k);
        pb0 = *(const float4*)(B + (size_t)(kbase+16+lb_r)*N + n0b + lb_n);
        pb1 = *(const float4*)(B + (size_t)(kbase+16+lb_r+8)*N + n0b + lb_n);
    }
    __syncthreads();

    int cur = 0;
    for (int k0 = 0; k0 < Kc; k0 += 16){
        {
            unsigned stg = cur*GSTG;
            unsigned* Bhl = dsm + stg + 5120;
            #pragma unroll
            for (int ks = 0; ks < 2; ks++){
                int kk = ks*8;
                unsigned ah[4][4], al[4][4];
                #pragma unroll
                for (int t = 0; t < 4; t++){
                    unsigned offh = sm_base + (stg + (a_row + t*16)*20 + kk + a_col)*4u;
                    ldsm4(ah[t], offh);
                    ldsm4(al[t], offh + 2560*4u);
                }
                #pragma unroll
                for (int j = 0; j < 4; j++){
                    int nc = nw + j*8 + r;
                    uint2 b0 = *(const uint2*)&Bhl[(kk+c)*264 + nc*2];
                    uint2 b1 = *(const uint2*)&Bhl[(kk+c+4)*264 + nc*2];
                    unsigned bh[2] = { b0.x, b1.x };
                    unsigned bl[2] = { b0.y, b1.y };
                    #pragma unroll
                    for (int t = 0; t < 4; t++){
                        mma_tf32(acc[t][j], ah[t], bh);
                        mma_tf32(acc[t][j], al[t], bh);
                        if (x3) mma_tf32(acc[t][j], ah[t], bl);
                    }
                }
            }
        }
        if (k0 + 16 < Kc){
            unsigned nstg = (cur^1)*GSTG;
            unsigned* Ah = dsm + nstg; unsigned* Al = dsm + nstg + 2560; unsigned* Bhl = dsm + nstg + 5120;
            float fa0[4]={pa0.x,pa0.y,pa0.z,pa0.w}, fa1[4]={pa1.x,pa1.y,pa1.z,pa1.w};
            #pragma unroll
            for (int u = 0; u < 4; u++){
                unsigned hi, lo;
                tf32_split(fa0[u], hi, lo); Ah[la_m*20 + la_k+u] = hi;      Al[la_m*20 + la_k+u] = lo;
                tf32_split(fa1[u], hi, lo); Ah[(la_m+64)*20 + la_k+u] = hi; Al[(la_m+64)*20 + la_k+u] = lo;
            }
            unsigned h0,l0,h1,l1,h2,l2,h3,l3;
            tf32_split(pb0.x,h0,l0); tf32_split(pb0.y,h1,l1);
            tf32_split(pb0.z,h2,l2); tf32_split(pb0.w,h3,l3);
            *(uint4*)&Bhl[lb_r*264 + lb_n*2]     = make_uint4(h0,l0,h1,l1);
            *(uint4*)&Bhl[lb_r*264 + lb_n*2 + 4] = make_uint4(h2,l2,h3,l3);
            tf32_split(pb1.x,h0,l0); tf32_split(pb1.y,h1,l1);
            tf32_split(pb1.z,h2,l2); tf32_split(pb1.w,h3,l3);
            *(uint4*)&Bhl[(lb_r+8)*264 + lb_n*2]     = make_uint4(h0,l0,h1,l1);
            *(uint4*)&Bhl[(lb_r+8)*264 + lb_n*2 + 4] = make_uint4(h2,l2,h3,l3);
        }
        if (k0 + 32 < Kc){
            pa0 = *(const float4*)(A + (size_t)(m0b+la_m)*K + kbase + k0+32 + la_k);
            pa1 = *(const float4*)(A + (size_t)(m0b+la_m+64)*K + kbase + k0+32 + la_k);
            pb0 = *(const float4*)(B + (size_t)(kbase+k0+32+lb_r)*N + n0b + lb_n);
            pb1 = *(const float4*)(B + (size_t)(kbase+k0+32+lb_r+8)*N + n0b + lb_n);
        }
        __syncthreads();
        cur ^= 1;
    }
    float* O = Cp + (size_t)blockIdx.z*M*N;
    #pragma unroll
    for (int t = 0; t < 4; t++)
        #pragma unroll
        for (int j = 0; j < 4; j++){
            int row = m0b + mw + t*16 + r;
            int col = n0b + nw + j*8 + c*2;
            O[(size_t)row*N + col]       = acc[t][j][0];
            O[(size_t)row*N + col+1]     = acc[t][j][1];
            O[(size_t)(row+8)*N + col]   = acc[t][j][2];
            O[(size_t)(row+8)*N + col+1] = acc[t][j][3];
        }
}

// partial sum: out[i] = p[i] + p[i+n]
__global__ void add2_kernel(const float* __restrict__ p, float* __restrict__ out, int n){
    int idx = blockIdx.x*256 + threadIdx.x;
    if (idx < n) out[idx] = p[idx] + p[idx + n];
}

// ---------------- MLP1 tf32x2 split-K, double-buffered: BM=64,BN=128 ----------------
#define MSTG 6784
__global__ __launch_bounds__(256,2) void mlp1_tf32_kernel(
        const float* __restrict__ kW1, const float* __restrict__ vW1){
    extern __shared__ unsigned dsm[];
    int tid = threadIdx.x, lane = tid&31, wid = tid>>5;
    int mat = blockIdx.y, kc = blockIdx.z;
    const float* A = g_cin + (size_t)mat*262144;
    const float* B = (mat ? vW1 : kW1);
    int n0b = blockIdx.x*128, kbase = kc*1024;
    int mw = (wid>>2)*32, nw = (wid&3)*32;
    int r = lane>>2, c = lane&3;
    float acc[2][4][4] = {};
    int fa_k = tid&15, fa_m = tid>>4;
    int fb_n = tid&127, fb_r = tid>>7;
    int sub = lane>>3, e = lane&7;
    int a_row = mw + ((sub&1)<<3) + e;
    int a_col = (sub>>1)<<2;
    unsigned sm_base = (unsigned)__cvta_generic_to_shared(dsm);

    float pa[4], pb[8];
    #pragma unroll
    for (int p = 0; p < 4; p++)
        pa[p] = A[(size_t)(fa_m + 16*p)*4096 + kbase + fa_k];
    #pragma unroll
    for (int p = 0; p < 8; p++)
        pb[p] = B[(size_t)(kbase + fb_r + 2*p)*4096 + n0b + fb_n];

    {
        unsigned* Ah = dsm; unsigned* Al = dsm + 1280; unsigned* Bhl = dsm + 2560;
        #pragma unroll
        for (int p = 0; p < 4; p++){
            unsigned hi, lo;
            tf32_split(pa[p], hi, lo);
            Ah[(fa_m + 16*p)*20 + fa_k] = hi;
            Al[(fa_m + 16*p)*20 + fa_k] = lo;
        }
        #pragma unroll
        for (int p = 0; p < 8; p++){
            unsigned hi, lo;
            tf32_split(pb[p], hi, lo);
            *(uint2*)&Bhl[(fb_r + 2*p)*264 + fb_n*2] = make_uint2(hi, lo);
        }
    }
    {
        #pragma unroll
        for (int p = 0; p < 4; p++)
            pa[p] = A[(size_t)(fa_m + 16*p)*4096 + kbase + 16 + fa_k];
        #pragma unroll
        for (int p = 0; p < 8; p++)
            pb[p] = B[(size_t)(kbase + 16 + fb_r + 2*p)*4096 + n0b + fb_n];
    }
    __syncthreads();

    int cur = 0;
    for (int k0 = 0; k0 < 1024; k0 += 16){
        {
            unsigned stg = cur*MSTG;
            unsigned* Bhl = dsm + stg + 2560;
            #pragma unroll
            for (int ks = 0; ks < 2; ks++){
                int kk = ks*8;
                unsigned ah[2][4], al[2][4];
                #pragma unroll
                for (int t = 0; t < 2; t++){
                    unsigned offh = sm_base + (stg + (a_row + t*16)*20 + kk + a_col)*4u;
                    ldsm4(ah[t], offh);
                    ldsm4(al[t], offh + 1280*4u);
                }
                #pragma unroll
                for (int j = 0; j < 4; j++){
                    int nc = nw + j*8 + r;
                    uint2 b0 = *(const uint2*)&Bhl[(kk+c)*264 + nc*2];
                    uint2 b1 = *(const uint2*)&Bhl[(kk+c+4)*264 + nc*2];
                    unsigned bh[2] = { b0.x, b1.x };
                    #pragma unroll
                    for (int t = 0; t < 2; t++){
                        mma_tf32(acc[t][j], ah[t], bh);
                        mma_tf32(acc[t][j], al[t], bh);
                    }
                }
            }
        }
        if (k0 + 16 < 1024){
            unsigned nstg = (cur^1)*MSTG;
            unsigned* Ah = dsm + nstg; unsigned* Al = dsm + nstg + 1280; unsigned* Bhl = dsm + nstg + 2560;
            #pragma unroll
            for (int p = 0; p < 4; p++){
                unsigned hi, lo;
                tf32_split(pa[p], hi, lo);
                Ah[(fa_m + 16*p)*20 + fa_k] = hi;
                Al[(fa_m + 16*p)*20 + fa_k] = lo;
            }
            #pragma unroll
            for (int p = 0; p < 8; p++){
                unsigned hi, lo;
                tf32_split(pb[p], hi, lo);
                *(uint2*)&Bhl[(fb_r + 2*p)*264 + fb_n*2] = make_uint2(hi, lo);
            }
        }
        if (k0 + 32 < 1024){
            #pragma unroll
            for (int p = 0; p < 4; p++)
                pa[p] = A[(size_t)(fa_m + 16*p)*4096 + kbase + k0 + 32 + fa_k];
            #pragma unroll
            for (int p = 0; p < 8; p++)
                pb[p] = B[(size_t)(kbase + k0 + 32 + fb_r + 2*p)*4096 + n0b + fb_n];
        }
        __syncthreads();
        cur ^= 1;
    }
    float* O = g_hidp + (size_t)(kc*2+mat)*64*4096;
    #pragma unroll
    for (int t = 0; t < 2; t++)
        #pragma unroll
        for (int j = 0; j < 4; j++){
            int row = mw + t*16 + r;
            int col = n0b + nw + j*8 + c*2;
            O[(size_t)row*4096 + col]       = acc[t][j][0];
            O[(size_t)row*4096 + col+1]     = acc[t][j][1];
            O[(size_t)(row+8)*4096 + col]   = acc[t][j][2];
            O[(size_t)(row+8)*4096 + col+1] = acc[t][j][3];
        }
}

// ---------------- small SGEMM (gates) ----------------
__global__ void sgemm_kernel(const float* __restrict__ A, const float* __restrict__ B,
                             const float* __restrict__ bias, float* __restrict__ C,
                             int M, int N, int K, int epi){
    __shared__ __align__(16) float As[16][72];
    __shared__ __align__(16) float Bs[16][72];
    int tid = threadIdx.x;
    int tr = tid>>4, tc = tid&15;
    int m0 = blockIdx.y*64, n0 = blockIdx.x*64;
    int lm = tid>>2, lk4 = (tid&3)*4;
    int lkb = tid>>4, ln4 = (tid&15)*4;
    float acc[4][4] = {};
    for (int k0 = 0; k0 < K; k0 += 16){
        float4 a4 = *(const float4*)(A + (size_t)(m0+lm)*K + k0 + lk4);
        As[lk4+0][lm]=a4.x; As[lk4+1][lm]=a4.y; As[lk4+2][lm]=a4.z; As[lk4+3][lm]=a4.w;
        if (n0+ln4+3 < N){
            *(float4*)&Bs[lkb][ln4] = *(const float4*)(B + (size_t)(k0+lkb)*N + n0 + ln4);
        } else {
            #pragma unroll
            for (int u=0;u<4;u++)
                Bs[lkb][ln4+u] = (n0+ln4+u < N) ? B[(size_t)(k0+lkb)*N + n0+ln4+u] : 0.f;
        }
        __syncthreads();
        #pragma unroll
        for (int kk=0; kk<16; kk++){
            float4 a = *(const float4*)&As[kk][tr*4];
            float4 b = *(const float4*)&Bs[kk][tc*4];
            float av[4]={a.x,a.y,a.z,a.w}, bv[4]={b.x,b.y,b.z,b.w};
            #pragma unroll
            for (int i=0;i<4;i++)
                #pragma unroll
                for (int j=0;j<4;j++) acc[i][j] += av[i]*bv[j];
        }
        __syncthreads();
    }
    #pragma unroll
    for (int i=0;i<4;i++){
        int row = m0 + tr*4 + i;
        #pragma unroll
        for (int j=0;j<4;j++){
            int col = n0 + tc*4 + j;
            if (col < N){
                float v = acc[i][j];
                if (epi >= 1) v += bias[col];
                if (epi == 3) v = 1.f/(1.f + expf(-v));
                C[(size_t)row*N + col] = v;
            }
        }
    }
}

// ---------------- build compression MLP input [2][64][4096] ----------------
__global__ void build_comp_kernel(const float* __restrict__ k_pos, const float* __restrict__ v_pos){
    int idx = blockIdx.x*256 + threadIdx.x;
    int mat = idx>>18, rem = idx & 262143;
    int r = rem>>12, i = rem & 4095;
    int h = r>>5, w = r&31;
    int c = i>>6, d = i&63;
    int s = w*64 + c;
    const float* pos = mat ? v_pos : k_pos;
    int off = mat ? (DIMM + 128) : DIMM;
    g_cin[idx] = g_qkv[(size_t)s*QKVW + off + h*64 + d] + pos[(h*64+c)*64 + d];
}

__global__ void mlp1red_kernel(const float* __restrict__ kb1, const float* __restrict__ vb1){
    int idx = blockIdx.x*256 + threadIdx.x;
    int mat = idx>>18, n = idx & 4095;
    float s = g_hidp[idx] + g_hidp[idx+524288] + g_hidp[idx+1048576] + g_hidp[idx+1572864];
    s += (mat ? vb1 : kb1)[n];
    g_hid[idx] = fmaxf(s, 0.f);
}

// ---------------- mem token init ----------------
__global__ void init_ck_kernel(const float* __restrict__ mem_kv){
    int t = threadIdx.x;
    int mat = t>>7, h = (t>>6)&1, d = t&63;
    float* out = mat ? g_cv : g_ck;
    out[h*33*64 + d] = mem_kv[(mat*2+h)*64 + d];
}

// ---------------- MLP layer2 ----------------
__global__ void mlp2_kernel(const float* __restrict__ kW2, const float* __restrict__ kb2,
                            const float* __restrict__ vW2, const float* __restrict__ vb2){
    int r = blockIdx.x, mat = blockIdx.y, tid = threadIdx.x;
    int d = tid&63, kq = tid>>6;
    const float* H = g_hid + (size_t)(mat*64+r)*4096;
    const float* W = mat ? vW2 : kW2;
    const float* b = mat ? vb2 : kb2;
    float acc = 0.f;
    int kend = kq*1024 + 1024;
    for (int k = kq*1024; k < kend; k++) acc += H[k]*W[(size_t)k*64 + d];
    __shared__ float red[4][64];
    red[kq][d] = acc; __syncthreads();
    if (kq == 0){
        float s = red[0][d]+red[1][d]+red[2][d]+red[3][d] + b[d];
        int h = r>>5, w = r&31;
        float* out = mat ? g_cv : g_ck;
        out[(h*33 + 1 + w)*64 + d] = s;
    }
}

// ---------------- compressed attention + selection ----------------
__global__ void comp_attn_kernel(){
    int i = blockIdx.x, h = blockIdx.y, tid = threadIdx.x;
    __shared__ float sq[512];
    __shared__ float sk[33*65];
    __shared__ float sv[33*65];
    __shared__ float L[264], P[264], Zr[8];
    for (int o = tid; o < 512; o += 256) sq[o] = g_qkv[(size_t)i*QKVW + h*512 + o];
    for (int o = tid; o < 33*64; o += 256){
        int j = o>>6, d = o&63;
        sk[j*65+d] = g_ck[h*2112 + o];
        sv[j*65+d] = g_cv[h*2112 + o];
    }
    __syncthreads();
    for (int o = tid; o < 264; o += 256){
        int g = o/33, j = o - g*33;
        bool vis = (j == 0) || (j*64 - 1 < i);
        float a = NEGF;
        if (vis){
            float s = 0.f;
            #pragma unroll 8
            for (int d = 0; d < 64; d++) s += sq[g*64+d]*sk[j*65+d];
            a = s*0.125f;
        }
        L[o] = a;
    }
    __syncthreads();
    if (tid < 8){
        int g = tid;
        float m = NEGF;
        for (int j = 0; j < 33; j++) m = fmaxf(m, L[g*33+j]);
        float z = 0.f;
        for (int j = 0; j < 33; j++){
            float l = L[g*33+j];
            float p = (l < -1e30f) ? 0.f : expf(l - m);
            P[g*33+j] = p; z += p;
        }
        Zr[g] = z;
    }
    if (tid == 32){
        float pr[32], im[32]; float M = -1000.f;
        for (int j = 0; j < 32; j++){
            float s = 0.f;
            for (int g = 0; g < 8; g++) s += L[g*33 + j + 1];
            im[j] = s*0.125f;
            M = fmaxf(M, im[j]);
        }
        float Zs = expf(-1000.f - M);
        for (int j = 0; j < 32; j++){
            float p = (im[j] < -1e30f) ? 0.f : expf(im[j] - M);
            pr[j] = p; Zs += p;
        }
        bool taken[32];
        for (int j = 0; j < 32; j++) taken[j] = false;
        int base = (h*SEQ + i)*9;
        for (int t = 0; t < 8; t++){
            int best = -1; float bv = -1.f;
            for (int j = 0; j < 32; j++)
                if (!taken[j] && pr[j] > bv){ bv = pr[j]; best = j; }
            if (best >= 0 && bv/Zs > 1e-10f){ taken[best] = true; g_sel[base+t] = best; }
            else g_sel[base+t] = -1;
        }
        g_sel[base+8] = i>>6;
    }
    __syncthreads();
    for (int o = tid; o < 512; o += 256){
        int g = o>>6, d = o&63;
        float a = 0.f;
        for (int j = 0; j < 33; j++) a += P[g*33+j]*sv[j*65+d];
        g_cout[(size_t)i*DIMM + h*512 + o] = a/Zr[g];
    }
}

// ---------------- RoPE on q and k ----------------
__global__ void rope_kernel(){
    int idx = blockIdx.x*256 + threadIdx.x;
    if (idx >= SEQ*576) return;
    int s = idx/576, e = idx - s*576;
    float pos = (float)s;
    if (e < 512){
        int p = e & 31;
        float ang = pos*exp2f(-(float)p*0.41524101186092033f);
        float c = cosf(ang), si = sinf(ang);
        const float* b = g_qkv + (size_t)s*QKVW + e*2;
        float u0 = b[0], u1 = b[1];
        g_rq[(size_t)s*DIMM + e*2]   = u0*c - u1*si;
        g_rq[(size_t)s*DIMM + e*2+1] = u1*c + u0*si;
    } else {
        int e2 = e - 512, p = e2 & 31;
        float ang = pos*exp2f(-(float)p*0.41524101186092033f);
        float c = cosf(ang), si = sinf(ang);
        const float* b = g_qkv + (size_t)s*QKVW + DIMM + e2*2;
        float u0 = b[0], u1 = b[1];
        g_rk[(size_t)s*128 + e2*2]   = u0*c - u1*si;
        g_rk[(size_t)s*128 + e2*2+1] = u1*c + u0*si;
    }
}

// ---------------- fine attention: cp.async double-buffered tiles ----------------
__global__ void fine_attn_kernel(){
    extern __shared__ float fsm[];
    float* Kb = fsm;
    float* Vb = fsm + 8704;
    float* SQ = fsm + 16896;
    float* SP = fsm + 17408;
    int i = blockIdx.x, h = blockIdx.y, tid = threadIdx.x;
    int w = tid>>5, l = tid&31;
    int base = (h*SEQ + i)*9;
    int blks[9]; bool dg[9]; int nb = 0;
    #pragma unroll
    for (int slot = 0; slot < 9; slot++){
        int blk = (slot < 8) ? g_sel[base+slot] : (i>>6);
        if (blk >= 0){ blks[nb] = blk; dg[nb] = (slot == 8); nb++; }
    }
    for (int o = tid; o < 512; o += 128) SQ[o] = g_rq[(size_t)i*DIMM + h*512 + o];

    auto issue = [&](int t, int stg){
        int blk = blks[t];
        float* Kd = Kb + stg*4352;
        float* Vd = Vb + stg*4096;
        #pragma unroll
        for (int o = tid; o < 1024; o += 128){
            int c = o>>4, d4 = (o&15)*4;
            cp16((unsigned)__cvta_generic_to_shared(&Kd[c*68+d4]),
                 g_rk + (size_t)(blk*64+c)*128 + h*64 + d4);
            cp16((unsigned)__cvta_generic_to_shared(&Vd[c*64+d4]),
                 g_qkv + (size_t)(blk*64+c)*QKVW + 1152 + h*64 + d4);
        }
        cp_commit();
    };

    int g0 = w*2, g1 = w*2+1;
    float m0=NEGF, m1=NEGF, Z0=0.f, Z1=0.f;
    float2 a0 = make_float2(0.f,0.f), a1 = make_float2(0.f,0.f);
    int lim = i & 63;

    issue(0, 0);
    for (int t = 0; t < nb; t++){
        if (t + 1 < nb) issue(t+1, (t+1)&1);
        if (t + 1 < nb) cp_wait<1>(); else cp_wait<0>();
        __syncthreads();
        float* Kd = Kb + (t&1)*4352;
        float* Vd = Vb + (t&1)*4096;
        bool isdg = dg[t];

        float2 s0 = make_float2(0.f,0.f), s1 = make_float2(0.f,0.f);
        #pragma unroll
        for (int d4 = 0; d4 < 64; d4 += 4){
            float4 k0 = *(const float4*)&Kd[l*68+d4];
            float4 k1 = *(const float4*)&Kd[(l+32)*68+d4];
            float4 q0 = *(const float4*)&SQ[g0*64+d4];
            float4 q1 = *(const float4*)&SQ[g1*64+d4];
            s0.x += q0.x*k0.x + q0.y*k0.y + q0.z*k0.z + q0.w*k0.w;
            s0.y += q0.x*k1.x + q0.y*k1.y + q0.z*k1.z + q0.w*k1.w;
            s1.x += q1.x*k0.x + q1.y*k0.y + q1.z*k0.z + q1.w*k0.w;
            s1.y += q1.x*k1.x + q1.y*k1.y + q1.z*k1.z + q1.w*k1.w;
        }
        bool v0 = (!isdg) || (l <= lim);
        bool v1 = (!isdg) || (l+32 <= lim);
        float sa = v0 ? s0.x*0.125f : NEGF;
        float sb = v1 ? s0.y*0.125f : NEGF;
        float sc_ = v0 ? s1.x*0.125f : NEGF;
        float sd = v1 ? s1.y*0.125f : NEGF;
        float mn0 = fmaxf(m0, wmax(fmaxf(sa, sb)));
        float e0 = expf(m0 - mn0);
        float p00 = v0 ? expf(sa - mn0) : 0.f;
        float p01 = v1 ? expf(sb - mn0) : 0.f;
        SP[g0*64+l] = p00; SP[g0*64+l+32] = p01;
        Z0 = Z0*e0 + wsum(p00 + p01);
        a0.x *= e0; a0.y *= e0;
        float mn1 = fmaxf(m1, wmax(fmaxf(sc_, sd)));
        float e1 = expf(m1 - mn1);
        float p10 = v0 ? expf(sc_ - mn1) : 0.f;
        float p11 = v1 ? expf(sd - mn1) : 0.f;
        SP[g1*64+l] = p10; SP[g1*64+l+32] = p11;
        Z1 = Z1*e1 + wsum(p10 + p11);
        a1.x *= e1; a1.y *= e1;
        m0 = mn0; m1 = mn1;
        __syncwarp();
        int dl = 2*l;
        #pragma unroll
        for (int c4 = 0; c4 < 64; c4 += 4){
            float4 pg0 = *(const float4*)&SP[g0*64+c4];
            float4 pg1 = *(const float4*)&SP[g1*64+c4];
            float2 vv0 = *(const float2*)&Vd[(c4+0)*64+dl];
            float2 vv1 = *(const float2*)&Vd[(c4+1)*64+dl];
            float2 vv2 = *(const float2*)&Vd[(c4+2)*64+dl];
            float2 vv3 = *(const float2*)&Vd[(c4+3)*64+dl];
            a0.x += pg0.x*vv0.x + pg0.y*vv1.x + pg0.z*vv2.x + pg0.w*vv3.x;
            a0.y += pg0.x*vv0.y + pg0.y*vv1.y + pg0.z*vv2.y + pg0.w*vv3.y;
            a1.x += pg1.x*vv0.x + pg1.y*vv1.x + pg1.z*vv2.x + pg1.w*vv3.x;
            a1.y += pg1.x*vv0.y + pg1.y*vv1.y + pg1.z*vv2.y + pg1.w*vv3.y;
        }
        __syncthreads();
    }
    size_t ob = (size_t)i*DIMM + h*512;
    *(float2*)&g_fout[ob + g0*64 + 2*l] = make_float2(a0.x/Z0, a0.y/Z0);
    *(float2*)&g_fout[ob + g1*64 + 2*l] = make_float2(a1.x/Z1, a1.y/Z1);
}

// ---------------- sliding window: 256 thr, 8 warps x 4 q = 32 queries/block ----------------
__global__ void slide_kernel(){
    extern __shared__ float ssm[];
    float* Kb = ssm;
    float* Vb = ssm + 8704;
    float* SQ = ssm + 16896;
    float* SP = ssm + 18944;
    int tid = threadIdx.x;
    int w = tid>>5, l = tid&31;
    int hq = blockIdx.y, hk = hq>>3;
    int i0 = blockIdx.x*32;
    for (int o = tid; o < 2048; o += 256){
        int qq = o>>6, d = o&63;
        SQ[o] = g_rq[(size_t)(i0+qq)*DIMM + hq*64 + d];
    }
    int cbtop = i0>>6;
    int cb0 = cbtop - 8; if (cb0 < 0) cb0 = 0;
    int nb = cbtop - cb0 + 1;

    auto issue = [&](int t, int stg){
        int cb = cb0 + t;
        float* Kd = Kb + stg*4352;
        float* Vd = Vb + stg*4096;
        #pragma unroll
        for (int o = tid; o < 1024; o += 256){
            int c = o>>4, d4 = (o&15)*4;
            cp16((unsigned)__cvta_generic_to_shared(&Kd[c*68+d4]),
                 g_rk + (size_t)(cb*64+c)*128 + hk*64 + d4);
            cp16((unsigned)__cvta_generic_to_shared(&Vd[c*64+d4]),
                 g_qkv + (size_t)(cb*64+c)*QKVW + 1152 + hk*64 + d4);
        }
        cp_commit();
    };

    float m[4], Z[4]; float2 a[4];
    #pragma unroll
    for (int q = 0; q < 4; q++){ m[q]=NEGF; Z[q]=0.f; a[q]=make_float2(0.f,0.f); }
    int q0 = w*4;

    issue(0, 0);
    for (int t = 0; t < nb; t++){
        if (t + 1 < nb) issue(t+1, (t+1)&1);
        if (t + 1 < nb) cp_wait<1>(); else cp_wait<0>();
        __syncthreads();
        int cb = cb0 + t;
        float* Kd = Kb + (t&1)*4352;
        float* Vd = Vb + (t&1)*4096;

        float2 s[4];
        #pragma unroll
        for (int q = 0; q < 4; q++) s[q] = make_float2(0.f,0.f);
        #pragma unroll
        for (int d4 = 0; d4 < 64; d4 += 4){
            float4 k0 = *(const float4*)&Kd[l*68+d4];
            float4 k1 = *(const float4*)&Kd[(l+32)*68+d4];
            #pragma unroll
            for (int q = 0; q < 4; q++){
                float4 qv = *(const float4*)&SQ[(q0+q)*64+d4];
                s[q].x += qv.x*k0.x + qv.y*k0.y + qv.z*k0.z + qv.w*k0.w;
                s[q].y += qv.x*k1.x + qv.y*k1.y + qv.z*k1.z + qv.w*k1.w;
            }
        }
        int k0p = cb*64 + l, k1p = k0p + 32;
        #pragma unroll
        for (int q = 0; q < 4; q++){
            int i = i0 + q0 + q;
            bool v0 = (k0p <= i) && (i - k0p <= 512);
            bool v1 = (k1p <= i) && (i - k1p <= 512);
            float sx = v0 ? s[q].x*0.125f : NEGF;
            float sy = v1 ? s[q].y*0.125f : NEGF;
            float mn = fmaxf(m[q], wmax(fmaxf(sx, sy)));
            float e = expf(m[q] - mn);
            float p0 = v0 ? expf(sx - mn) : 0.f;
            float p1 = v1 ? expf(sy - mn) : 0.f;
            SP[(q0+q)*64+l] = p0; SP[(q0+q)*64+l+32] = p1;
            Z[q] = Z[q]*e + wsum(p0 + p1);
            a[q].x *= e; a[q].y *= e;
            m[q] = mn;
        }
        __syncwarp();
        int dl = 2*l;
        #pragma unroll
        for (int c4 = 0; c4 < 64; c4 += 4){
            float2 vv0 = *(const float2*)&Vd[(c4+0)*64+dl];
            float2 vv1 = *(const float2*)&Vd[(c4+1)*64+dl];
            float2 vv2 = *(const float2*)&Vd[(c4+2)*64+dl];
            float2 vv3 = *(const float2*)&Vd[(c4+3)*64+dl];
            #pragma unroll
            for (int q = 0; q < 4; q++){
                float4 pg = *(const float4*)&SP[(q0+q)*64+c4];
                a[q].x += pg.x*vv0.x + pg.y*vv1.x + pg.z*vv2.x + pg.w*vv3.x;
                a[q].y += pg.x*vv0.y + pg.y*vv1.y + pg.z*vv2.y + pg.w*vv3.y;
            }
        }
        __syncthreads();
    }
    #pragma unroll
    for (int q = 0; q < 4; q++){
        int i = i0 + q0 + q;
        *(float2*)&g_sout[(size_t)i*DIMM + hq*64 + 2*l] = make_float2(a[q].x/Z[q], a[q].y/Z[q]);
    }
}

// ---------------- gated combination ----------------
__global__ void combine_kernel(){
    int idx = blockIdx.x*256 + threadIdx.x;
    int i = idx>>10, e = idx & 1023;
    int hh = e>>6;
    const float* gt = g_gate + i*48 + hh*3;
    g_comb[idx] = gt[0]*g_cout[idx] + gt[1]*g_fout[idx] + gt[2]*g_sout[idx];
}

extern "C" void kernel_launch(void* const* d_in, const int* in_sizes, int n_in,
                              void* d_out, int out_size){
    const float* x      = (const float*)d_in[0];
    const float* rms_g  = (const float*)d_in[1];
    const float* W_qkv  = (const float*)d_in[2];
    const float* k_pos  = (const float*)d_in[3];
    const float* v_pos  = (const float*)d_in[4];
    const float* mem_kv = (const float*)d_in[5];
    const float* kW1    = (const float*)d_in[6];
    const float* kb1    = (const float*)d_in[7];
    const float* kW2    = (const float*)d_in[8];
    const float* kb2    = (const float*)d_in[9];
    const float* vW1    = (const float*)d_in[10];
    const float* vb1    = (const float*)d_in[11];
    const float* vW2    = (const float*)d_in[12];
    const float* vb2    = (const float*)d_in[13];
    const float* W_comb = (const float*)d_in[14];
    const float* b_comb = (const float*)d_in[15];
    const float* W_out  = (const float*)d_in[16];
    float* out = (float*)d_out;

    float *p_xn, *p_qkv, *p_gate, *p_comb, *p_gp;
    cudaGetSymbolAddress((void**)&p_xn,   g_xn);
    cudaGetSymbolAddress((void**)&p_qkv,  g_qkv);
    cudaGetSymbolAddress((void**)&p_gate, g_gate);
    cudaGetSymbolAddress((void**)&p_comb, g_comb);
    cudaGetSymbolAddress((void**)&p_gp,   g_gp);

    const int GEMM_SMEM  = 2*GSTG*4;
    const int MLP1_SMEM  = 2*MSTG*4;
    const int FINE_SMEM  = 17920*4;
    const int SLIDE_SMEM = 20992*4;
    cudaFuncSetAttribute(tf32gemm_kernel,  cudaFuncAttributeMaxDynamicSharedMemorySize, GEMM_SMEM);
    cudaFuncSetAttribute(mlp1_tf32_kernel, cudaFuncAttributeMaxDynamicSharedMemorySize, MLP1_SMEM);
    cudaFuncSetAttribute(fine_attn_kernel, cudaFuncAttributeMaxDynamicSharedMemorySize, FINE_SMEM);
    cudaFuncSetAttribute(slide_kernel,     cudaFuncAttributeMaxDynamicSharedMemorySize, SLIDE_SMEM);

    rmsnorm_kernel<<<SEQ, 256>>>(x, rms_g);
    tf32gemm_kernel<<<dim3(10, 16, 2), 256, GEMM_SMEM>>>(p_xn, W_qkv, p_gp, SEQ, QKVW, DIMM, 512, 1);
    add2_kernel<<<(SEQ*QKVW + 255)/256, 256>>>(p_gp, p_qkv, SEQ*QKVW);
    build_comp_kernel<<<2048, 256>>>(k_pos, v_pos);
    mlp1_tf32_kernel<<<dim3(32, 2, 4), 256, MLP1_SMEM>>>(kW1, vW1);
    mlp1red_kernel<<<2048, 256>>>(kb1, vb1);
    init_ck_kernel<<<1, 256>>>(mem_kv);
    mlp2_kernel<<<dim3(64, 2), 256>>>(kW2, kb2, vW2, vb2);
    comp_attn_kernel<<<dim3(SEQ, 2), 256>>>();
    rope_kernel<<<(SEQ*576 + 255)/256, 256>>>();
    fine_attn_kernel<<<dim3(SEQ, 2), 128, FINE_SMEM>>>();
    slide_kernel<<<dim3(64, 16), 256, SLIDE_SMEM>>>();
    sgemm_kernel<<<dim3(1, 32), 256>>>(p_xn, W_comb, b_comb, p_gate, SEQ, 48, DIMM, 3);
    combine_kernel<<<8192, 256>>>();
    tf32gemm_kernel<<<dim3(8, 16, 2), 256, GEMM_SMEM>>>(p_comb, W_out, p_gp, SEQ, DIMM, DIMM, 512, 0);
    add2_kernel<<<(SEQ*DIMM + 255)/256, 256>>>(p_gp, out, SEQ*DIMM);
}